// round 3
// baseline (speedup 1.0000x reference)
#include <cuda_runtime.h>
#include <cuda_bf16.h>
#include <math.h>

// ---------------------------------------------------------------------------
// Problem constants (fixed shapes per reference)
// ---------------------------------------------------------------------------
#define HID   1024
#define NHEAD 16
#define HD    64
#define INTER 4096
#define BATCH 4
#define SEQ   2048
#define NTOK  (BATCH * SEQ)          // 8192
#define LN_EPS 1e-5f

// ---------------------------------------------------------------------------
// Scratch: __device__ globals (no runtime allocation anywhere).
// Aliased arena — liveness:
//   LN1:  x   -> h      (arena0)
//   QKV:  h   -> qkv    (arena1)   h dead after
//   ATTN: qkv -> attn   (arena0)   qkv dead after
//   PROJ: attn + x -> x1 (g_x1)    attn dead after
//   LN2:  x1  -> h2     (arena0)
//   MLP1: h2  -> mid    (arena1)   h2 dead after
//   MLP2: mid + x1 -> out
// arena0 holds h/attn/h2 (32 MB), arena1 holds qkv(96 MB)/mid(128 MB).
// Total static: 128 + 32 + 32 = 192 MB.
// ---------------------------------------------------------------------------
__device__ float g_arena0[NTOK * HID];       // h / attn / h2
__device__ float g_arena1[NTOK * INTER];     // qkv (uses 3/4) / mid (full)
__device__ float g_x1    [NTOK * HID];       // residual-1 output

// ---------------------------------------------------------------------------
// LayerNorm: one block per row of 1024, 256 threads, float4 per thread.
// SRC selects input: 0 = external x (param), 1 = g_x1. DST: 0 = g_arena0.
// ---------------------------------------------------------------------------
template <int SRC>
__global__ __launch_bounds__(256) void ln_kernel(
    const float* __restrict__ Xext, const float* __restrict__ g,
    const float* __restrict__ b)
{
    __shared__ float red[16];
    const long row = blockIdx.x;
    const int  t   = threadIdx.x;

    const float* X = (SRC == 0) ? Xext : g_x1;
    float4 v = ((const float4*)(X + row * HID))[t];
    float s  = v.x + v.y + v.z + v.w;
    float sq = v.x*v.x + v.y*v.y + v.z*v.z + v.w*v.w;

    #pragma unroll
    for (int o = 16; o > 0; o >>= 1) {
        s  += __shfl_xor_sync(0xffffffffu, s,  o);
        sq += __shfl_xor_sync(0xffffffffu, sq, o);
    }
    const int warp = t >> 5, lane = t & 31;
    if (lane == 0) { red[warp] = s; red[warp + 8] = sq; }
    __syncthreads();
    if (t < 32) {
        float ss = (lane < 8) ? red[lane]     : 0.f;
        float qq = (lane < 8) ? red[lane + 8] : 0.f;
        #pragma unroll
        for (int o = 4; o > 0; o >>= 1) {
            ss += __shfl_xor_sync(0xffffffffu, ss, o);
            qq += __shfl_xor_sync(0xffffffffu, qq, o);
        }
        if (lane == 0) { red[0] = ss; red[1] = qq; }
    }
    __syncthreads();

    const float mu   = red[0] * (1.f / HID);
    const float var  = red[1] * (1.f / HID) - mu * mu;
    const float rstd = rsqrtf(var + LN_EPS);

    const float4 gv = ((const float4*)g)[t];
    const float4 bv = ((const float4*)b)[t];
    float4 y;
    y.x = (v.x - mu) * rstd * gv.x + bv.x;
    y.y = (v.y - mu) * rstd * gv.y + bv.y;
    y.z = (v.z - mu) * rstd * gv.z + bv.z;
    y.w = (v.w - mu) * rstd * gv.w + bv.w;
    ((float4*)(g_arena0 + row * HID))[t] = y;
}

// ---------------------------------------------------------------------------
// SGEMM: C[M,N] = A[M,K] @ B[K,N] + bias (+epilogue)
// 128x128 block, K-tile 16, 256 threads, 8x8 per-thread microtile.
// All M,N,K are multiples of the tile sizes -> no bounds checks.
// EPI: 0 = +bias; 1 = +bias +residual; 2 = +bias then tanh-GELU
// ---------------------------------------------------------------------------
#define GBM 128
#define GBN 128
#define GBK 16

template <int EPI>
__global__ __launch_bounds__(256) void gemm_kernel(
    const float* __restrict__ A, const float* __restrict__ B,
    const float* __restrict__ bias, const float* __restrict__ res,
    float* __restrict__ C, int M, int N, int K)
{
    __shared__ float As[GBK][GBM];
    __shared__ float Bs[GBK][GBN];

    const int tid = threadIdx.x;
    const int m0  = blockIdx.y * GBM;
    const int n0  = blockIdx.x * GBN;
    const int tx  = tid & 15;       // 0..15 -> N
    const int ty  = tid >> 4;       // 0..15 -> M

    // A loader: 128 rows x 16 cols, float4 along K
    const int a_row = tid >> 2;         // 0..63 (+64)
    const int a_k4  = (tid & 3) * 4;    // 0,4,8,12
    // B loader: 16 rows x 128 cols, float4 along N
    const int b_row = tid >> 5;         // 0..7 (+8)
    const int b_n4  = (tid & 31) * 4;   // 0..124

    float acc[8][8] = {};

    for (int k0 = 0; k0 < K; k0 += GBK) {
        #pragma unroll
        for (int r = 0; r < 2; r++) {
            const int row = a_row + r * 64;
            float4 v = *(const float4*)(A + (long)(m0 + row) * K + k0 + a_k4);
            As[a_k4 + 0][row] = v.x;
            As[a_k4 + 1][row] = v.y;
            As[a_k4 + 2][row] = v.z;
            As[a_k4 + 3][row] = v.w;
        }
        #pragma unroll
        for (int r = 0; r < 2; r++) {
            const int row = b_row + r * 8;
            *(float4*)&Bs[row][b_n4] =
                *(const float4*)(B + (long)(k0 + row) * N + n0 + b_n4);
        }
        __syncthreads();

        #pragma unroll
        for (int kk = 0; kk < GBK; kk++) {
            float af[8], bf[8];
            *(float4*)&af[0] = *(const float4*)&As[kk][ty * 8];
            *(float4*)&af[4] = *(const float4*)&As[kk][ty * 8 + 4];
            *(float4*)&bf[0] = *(const float4*)&Bs[kk][tx * 8];
            *(float4*)&bf[4] = *(const float4*)&Bs[kk][tx * 8 + 4];
            #pragma unroll
            for (int i = 0; i < 8; i++)
                #pragma unroll
                for (int j = 0; j < 8; j++)
                    acc[i][j] = fmaf(af[i], bf[j], acc[i][j]);
        }
        __syncthreads();
    }

    #pragma unroll
    for (int i = 0; i < 8; i++) {
        const int m = m0 + ty * 8 + i;
        #pragma unroll
        for (int j = 0; j < 8; j++) {
            const int n = n0 + tx * 8 + j;
            float v = acc[i][j] + bias[n];
            if (EPI == 2) {
                const float u = v;
                const float t = tanhf(0.7978845608028654f * (u + 0.044715f * u * u * u));
                v = 0.5f * u * (1.0f + t);
            }
            const long idx = (long)m * N + n;
            if (EPI == 1) v += res[idx];
            C[idx] = v;
        }
    }
}

// ---------------------------------------------------------------------------
// Flash attention (fp32, online softmax).
// Grid: (SEQ/128, NHEAD, BATCH), 128 threads; 1 thread = 1 query row.
// qkv read from g_arena1, output written to g_arena0 (qkv chunk already
// consumed for those tokens only at the very end -> no hazard: we read ALL
// of qkv before writing attn? No — we write attn only for our own token,
// but other blocks still read K/V of all tokens. So attn CANNOT overwrite
// qkv storage. It writes to g_arena0 (h is dead), which is disjoint. OK.
// ---------------------------------------------------------------------------
#define AQ 128   // queries per block
#define AK 64    // kv rows per chunk

__global__ __launch_bounds__(128) void attn_kernel()
{
    __shared__ float Ks[AK][HD];   // 16 KB
    __shared__ float Vs[AK][HD];   // 16 KB

    const float* qkv = g_arena1;
    float*       out = g_arena0;

    const int h   = blockIdx.y;
    const int bb  = blockIdx.z;
    const int qi  = blockIdx.x * AQ + threadIdx.x;   // query position in sequence
    const long tok = (long)bb * SEQ + qi;

    // load q row into registers
    const float* qptr = qkv + tok * (3 * HID) + h * HD;
    float q[HD], o[HD];
    #pragma unroll
    for (int i = 0; i < HD / 4; i++) {
        float4 v = ((const float4*)qptr)[i];
        q[4*i+0] = v.x; q[4*i+1] = v.y; q[4*i+2] = v.z; q[4*i+3] = v.w;
    }
    #pragma unroll
    for (int d = 0; d < HD; d++) o[d] = 0.f;

    float m_run = -1e30f, l_run = 0.f;

    // K/V loader mapping: 2 threads per row, each loads 32 floats
    const int lr   = threadIdx.x >> 1;
    const int lcol = (threadIdx.x & 1) * 32;

    for (int kv0 = 0; kv0 < SEQ; kv0 += AK) {
        const long ktok = (long)bb * SEQ + kv0 + lr;
        const float* kp = qkv + ktok * (3 * HID) + HID     + h * HD + lcol;
        const float* vp = qkv + ktok * (3 * HID) + 2 * HID + h * HD + lcol;
        #pragma unroll
        for (int c = 0; c < 8; c++) {
            ((float4*)&Ks[lr][lcol])[c] = ((const float4*)kp)[c];
            ((float4*)&Vs[lr][lcol])[c] = ((const float4*)vp)[c];
        }
        __syncthreads();

        #pragma unroll 1
        for (int sc = 0; sc < AK; sc += 16) {
            float s[16];
            #pragma unroll
            for (int j = 0; j < 16; j++) {
                const float* kr = &Ks[sc + j][0];
                float d = 0.f;
                #pragma unroll
                for (int dd = 0; dd < HD; dd++) d = fmaf(q[dd], kr[dd], d);
                s[j] = d * 0.125f;   // 1/sqrt(64)
            }
            float mloc = s[0];
            #pragma unroll
            for (int j = 1; j < 16; j++) mloc = fmaxf(mloc, s[j]);
            const float m_new = fmaxf(m_run, mloc);
            const float corr  = __expf(m_run - m_new);
            l_run *= corr;
            #pragma unroll
            for (int dd = 0; dd < HD; dd++) o[dd] *= corr;
            #pragma unroll
            for (int j = 0; j < 16; j++) {
                const float p = __expf(s[j] - m_new);
                l_run += p;
                const float* vr = &Vs[sc + j][0];
                #pragma unroll
                for (int dd = 0; dd < HD; dd++) o[dd] = fmaf(p, vr[dd], o[dd]);
            }
            m_run = m_new;
        }
        __syncthreads();
    }

    const float inv = 1.f / l_run;
    float* op = out + tok * HID + h * HD;
    #pragma unroll
    for (int i = 0; i < HD / 4; i++) {
        float4 y;
        y.x = o[4*i+0] * inv; y.y = o[4*i+1] * inv;
        y.z = o[4*i+2] * inv; y.w = o[4*i+3] * inv;
        ((float4*)op)[i] = y;
    }
}

// ---------------------------------------------------------------------------
// Tiny helper kernels to obtain device pointers to the arenas without any
// host runtime API: instead we launch GEMMs with pointers taken from device
// symbols via kernels that reference them directly. Simplest: wrapper
// kernels are overkill — gemm/ln/attn already reference globals where the
// operand is a scratch buffer. For GEMMs, A/C vary per call, so we pass a
// selector instead of a raw pointer.
// ---------------------------------------------------------------------------
// Selector-based GEMM wrapper: SEL_A / SEL_C choose among {arena0, arena1,
// x1, external}. This keeps kernel_launch free of ANY runtime API calls
// (pure kernel launches only -> trivially graph-capturable).
enum { P_ARENA0 = 0, P_ARENA1 = 1, P_X1 = 2, P_EXT = 3 };

__device__ __forceinline__ const float* sel_ptr(int sel, const float* ext) {
    switch (sel) {
        case P_ARENA0: return g_arena0;
        case P_ARENA1: return g_arena1;
        case P_X1:     return g_x1;
        default:       return ext;
    }
}

template <int EPI, int SA, int SC, int SR>
__global__ __launch_bounds__(256) void gemm_sel_kernel(
    const float* __restrict__ Aext, const float* __restrict__ B,
    const float* __restrict__ bias, const float* __restrict__ Rext,
    float* __restrict__ Cext, int M, int N, int K)
{
    const float* A   = sel_ptr(SA, Aext);
    const float* res = sel_ptr(SR, Rext);
    float*       C   = const_cast<float*>(sel_ptr(SC, Cext));

    // --- body identical to gemm_kernel ---
    __shared__ float As[GBK][GBM];
    __shared__ float Bs[GBK][GBN];

    const int tid = threadIdx.x;
    const int m0  = blockIdx.y * GBM;
    const int n0  = blockIdx.x * GBN;
    const int tx  = tid & 15;
    const int ty  = tid >> 4;

    const int a_row = tid >> 2;
    const int a_k4  = (tid & 3) * 4;
    const int b_row = tid >> 5;
    const int b_n4  = (tid & 31) * 4;

    float acc[8][8] = {};

    for (int k0 = 0; k0 < K; k0 += GBK) {
        #pragma unroll
        for (int r = 0; r < 2; r++) {
            const int row = a_row + r * 64;
            float4 v = *(const float4*)(A + (long)(m0 + row) * K + k0 + a_k4);
            As[a_k4 + 0][row] = v.x;
            As[a_k4 + 1][row] = v.y;
            As[a_k4 + 2][row] = v.z;
            As[a_k4 + 3][row] = v.w;
        }
        #pragma unroll
        for (int r = 0; r < 2; r++) {
            const int row = b_row + r * 8;
            *(float4*)&Bs[row][b_n4] =
                *(const float4*)(B + (long)(k0 + row) * N + n0 + b_n4);
        }
        __syncthreads();

        #pragma unroll
        for (int kk = 0; kk < GBK; kk++) {
            float af[8], bf[8];
            *(float4*)&af[0] = *(const float4*)&As[kk][ty * 8];
            *(float4*)&af[4] = *(const float4*)&As[kk][ty * 8 + 4];
            *(float4*)&bf[0] = *(const float4*)&Bs[kk][tx * 8];
            *(float4*)&bf[4] = *(const float4*)&Bs[kk][tx * 8 + 4];
            #pragma unroll
            for (int i = 0; i < 8; i++)
                #pragma unroll
                for (int j = 0; j < 8; j++)
                    acc[i][j] = fmaf(af[i], bf[j], acc[i][j]);
        }
        __syncthreads();
    }

    #pragma unroll
    for (int i = 0; i < 8; i++) {
        const int m = m0 + ty * 8 + i;
        #pragma unroll
        for (int j = 0; j < 8; j++) {
            const int n = n0 + tx * 8 + j;
            float v = acc[i][j] + bias[n];
            if (EPI == 2) {
                const float u = v;
                const float t = tanhf(0.7978845608028654f * (u + 0.044715f * u * u * u));
                v = 0.5f * u * (1.0f + t);
            }
            const long idx = (long)m * N + n;
            if (EPI == 1) v += res[idx];
            C[idx] = v;
        }
    }
}

// ---------------------------------------------------------------------------
// Launch: pure kernel launches, zero runtime API calls.
// ---------------------------------------------------------------------------
extern "C" void kernel_launch(void* const* d_in, const int* in_sizes, int n_in,
                              void* d_out, int out_size)
{
    const float* x     = (const float*)d_in[0];
    const float* ln1_g = (const float*)d_in[1];
    const float* ln1_b = (const float*)d_in[2];
    const float* qkv_w = (const float*)d_in[3];
    const float* qkv_b = (const float*)d_in[4];
    const float* out_w = (const float*)d_in[5];
    const float* out_b = (const float*)d_in[6];
    const float* ln2_g = (const float*)d_in[7];
    const float* ln2_b = (const float*)d_in[8];
    const float* w1    = (const float*)d_in[9];
    const float* b1    = (const float*)d_in[10];
    const float* w2    = (const float*)d_in[11];
    const float* b2    = (const float*)d_in[12];
    float* out = (float*)d_out;

    // 1) LN1: x -> arena0 (h)
    ln_kernel<0><<<NTOK, 256>>>(x, ln1_g, ln1_b);

    // 2) QKV: arena0 @ qkv_w + qkv_b -> arena1   [8192 x 3072]
    gemm_sel_kernel<0, P_ARENA0, P_ARENA1, P_EXT>
        <<<dim3((3 * HID) / GBN, NTOK / GBM), 256>>>(
        nullptr, qkv_w, qkv_b, nullptr, nullptr, NTOK, 3 * HID, HID);

    // 3) attention: arena1 (qkv) -> arena0 (attn)
    attn_kernel<<<dim3(SEQ / AQ, NHEAD, BATCH), AQ>>>();

    // 4) x1 = x + arena0 @ out_w + out_b -> g_x1   [8192 x 1024]
    gemm_sel_kernel<1, P_ARENA0, P_X1, P_EXT>
        <<<dim3(HID / GBN, NTOK / GBM), 256>>>(
        nullptr, out_w, out_b, x, nullptr, NTOK, HID, HID);

    // 5) LN2: g_x1 -> arena0 (h2)
    ln_kernel<1><<<NTOK, 256>>>(nullptr, ln2_g, ln2_b);

    // 6) mid = gelu(arena0 @ w1 + b1) -> arena1   [8192 x 4096]
    gemm_sel_kernel<2, P_ARENA0, P_ARENA1, P_EXT>
        <<<dim3(INTER / GBN, NTOK / GBM), 256>>>(
        nullptr, w1, b1, nullptr, nullptr, NTOK, INTER, HID);

    // 7) out = g_x1 + arena1 @ w2 + b2 -> d_out   [8192 x 1024]
    gemm_sel_kernel<1, P_ARENA1, P_EXT, P_X1>
        <<<dim3(HID / GBN, NTOK / GBM), 256>>>(
        nullptr, w2, b2, nullptr, out, NTOK, HID, INTER);
}

// round 5
// speedup vs baseline: 2.2447x; 2.2447x over previous
#include <cuda_runtime.h>
#include <cuda_bf16.h>
#include <math.h>
#include <stdint.h>

// ---------------------------------------------------------------------------
// Problem constants
// ---------------------------------------------------------------------------
#define HID   1024
#define NHEAD 16
#define HD    64
#define INTER 4096
#define BATCH 4
#define SEQ   2048
#define NTOK  (BATCH * SEQ)          // 8192
#define LN_EPS 1e-5f

// ---------------------------------------------------------------------------
// Scratch arenas (static device globals; no runtime allocation)
// ---------------------------------------------------------------------------
__device__ float g_arena0[NTOK * HID];       // h / attn / h2
__device__ float g_arena1[NTOK * INTER];     // qkv (3/4 used) / mid
__device__ float g_x1    [NTOK * HID];       // residual-1 output

enum { P_ARENA0 = 0, P_ARENA1 = 1, P_X1 = 2, P_EXT = 3 };

__device__ __forceinline__ const float* sel_ptr(int sel, const float* ext) {
    switch (sel) {
        case P_ARENA0: return g_arena0;
        case P_ARENA1: return g_arena1;
        case P_X1:     return g_x1;
        default:       return ext;
    }
}

// ---------------------------------------------------------------------------
// Baseline-PTX tensor-core helpers (sm_80+ features; compile for compute_103)
// ---------------------------------------------------------------------------
__device__ __forceinline__ uint32_t smem_u32(const void* p) {
    uint32_t a;
    asm("{ .reg .u64 t; cvta.to.shared.u64 t, %1; cvt.u32.u64 %0, t; }"
        : "=r"(a) : "l"(p));
    return a;
}
__device__ __forceinline__ void ldsm4(uint32_t* r, uint32_t addr) {
    asm volatile("ldmatrix.sync.aligned.m8n8.x4.shared.b16 {%0,%1,%2,%3}, [%4];"
                 : "=r"(r[0]), "=r"(r[1]), "=r"(r[2]), "=r"(r[3]) : "r"(addr));
}
__device__ __forceinline__ void ldsm4t(uint32_t* r, uint32_t addr) {
    asm volatile("ldmatrix.sync.aligned.m8n8.x4.trans.shared.b16 {%0,%1,%2,%3}, [%4];"
                 : "=r"(r[0]), "=r"(r[1]), "=r"(r[2]), "=r"(r[3]) : "r"(addr));
}
__device__ __forceinline__ void mma16816(float* c, const uint32_t* a,
                                         uint32_t b0, uint32_t b1) {
    asm volatile(
        "mma.sync.aligned.m16n8k16.row.col.f32.bf16.bf16.f32 "
        "{%0,%1,%2,%3}, {%4,%5,%6,%7}, {%8,%9}, {%0,%1,%2,%3};"
        : "+f"(c[0]), "+f"(c[1]), "+f"(c[2]), "+f"(c[3])
        : "r"(a[0]), "r"(a[1]), "r"(a[2]), "r"(a[3]), "r"(b0), "r"(b1));
}

// ---------------------------------------------------------------------------
// HMMA GEMM: C[M,N] = A[M,K] @ B[K,N] + bias (+epilogue), 3xbf16 split.
// Tile 128x128, BK=32, 8 warps (warp tile 32x64), double-buffered smem.
//   stage layout (32KB each, 2 stages = 64KB dynamic smem):
//     Ahi [128][32] bf16 (8KB, swizzle sw2) | Alo (8KB)
//     Bhi [32][128] bf16 (8KB, swizzle sw4) | Blo (8KB)
// EPI: 0 = +bias; 1 = +bias +residual; 2 = +bias then tanh-GELU
// ---------------------------------------------------------------------------
#define BM 128
#define BN 128
#define BK 32
#define STAGE 32768
#define HG_SMEM (2 * STAGE)

// A: row m stride 64B; swizzle bits[5:4] ^= bits[7:6]
__device__ __forceinline__ uint32_t swA(uint32_t off) { return off ^ ((off >> 2) & 0x30); }
// B: row k stride 256B; swizzle bits[6:4] ^= bits[10:8]
__device__ __forceinline__ uint32_t swB(uint32_t off) { return off ^ ((off >> 4) & 0x70); }

template <int EPI, int SA, int SC, int SR>
__global__ __launch_bounds__(256) void hgemm(
    const float* __restrict__ Aext, const float* __restrict__ B,
    const float* __restrict__ bias, const float* __restrict__ Rext,
    float* __restrict__ Cext, int M, int N, int K)
{
    extern __shared__ char smem[];
    const float* A   = sel_ptr(SA, Aext);
    const float* res = sel_ptr(SR, Rext);
    float*       C   = const_cast<float*>(sel_ptr(SC, (const float*)Cext));

    const uint32_t sb = smem_u32(smem);
    const int tid  = threadIdx.x;
    const int lane = tid & 31;
    const int wid  = tid >> 5;
    const int m0   = blockIdx.y * BM;
    const int n0   = blockIdx.x * BN;

    // ---- loaders ----
    const int ar = tid >> 1;             // 0..127 (m row)
    const int ac = (tid & 1) * 16;       // k half
    const int br = tid >> 3;             // 0..31 (k row)
    const int bc = (tid & 7) * 16;       // n offset
    const size_t arow = (size_t)(m0 + ar) * K;

    float4 av[4], bv[4];
    auto LOAD = [&](int k0) {
        #pragma unroll
        for (int i = 0; i < 4; i++)
            av[i] = *(const float4*)(A + arow + k0 + ac + i * 4);
        #pragma unroll
        for (int i = 0; i < 4; i++)
            bv[i] = *(const float4*)(B + (size_t)(k0 + br) * N + n0 + bc + i * 4);
    };
    auto STORE = [&](int s) {
        char* Ahi = smem + s * STAGE;
        char* Alo = Ahi + 8192;
        char* Bhi = Ahi + 16384;
        char* Blo = Ahi + 24576;
        #pragma unroll
        for (int i = 0; i < 4; i++) {
            const float4 v = av[i];
            __nv_bfloat162 h01 = __floats2bfloat162_rn(v.x, v.y);
            __nv_bfloat162 h23 = __floats2bfloat162_rn(v.z, v.w);
            __nv_bfloat162 l01 = __floats2bfloat162_rn(v.x - __bfloat162float(h01.x),
                                                       v.y - __bfloat162float(h01.y));
            __nv_bfloat162 l23 = __floats2bfloat162_rn(v.z - __bfloat162float(h23.x),
                                                       v.w - __bfloat162float(h23.y));
            const uint32_t so = swA(ar * 64 + (ac + i * 4) * 2);
            uint2 hv, lv;
            hv.x = *(uint32_t*)&h01; hv.y = *(uint32_t*)&h23;
            lv.x = *(uint32_t*)&l01; lv.y = *(uint32_t*)&l23;
            *(uint2*)(Ahi + so) = hv;
            *(uint2*)(Alo + so) = lv;
        }
        #pragma unroll
        for (int i = 0; i < 4; i++) {
            const float4 v = bv[i];
            __nv_bfloat162 h01 = __floats2bfloat162_rn(v.x, v.y);
            __nv_bfloat162 h23 = __floats2bfloat162_rn(v.z, v.w);
            __nv_bfloat162 l01 = __floats2bfloat162_rn(v.x - __bfloat162float(h01.x),
                                                       v.y - __bfloat162float(h01.y));
            __nv_bfloat162 l23 = __floats2bfloat162_rn(v.z - __bfloat162float(h23.x),
                                                       v.w - __bfloat162float(h23.y));
            const uint32_t so = swB(br * 256 + (bc + i * 4) * 2);
            uint2 hv, lv;
            hv.x = *(uint32_t*)&h01; hv.y = *(uint32_t*)&h23;
            lv.x = *(uint32_t*)&l01; lv.y = *(uint32_t*)&l23;
            *(uint2*)(Bhi + so) = hv;
            *(uint2*)(Blo + so) = lv;
        }
    };

    // ---- per-warp compute mapping ----
    const int wm = (wid & 3) * 32;       // warp M origin (4 warps along M)
    const int wn = (wid >> 2) * 64;      // warp N origin (2 warps along N)
    const int a_r = lane & 15;           // ldmatrix A row
    const int a_k = (lane >> 4) * 8;     // ldmatrix A k-offset
    const int b_k = lane & 15;           // ldmatrix B k row
    const int b_n = (lane >> 4) * 8;     // ldmatrix B n-offset

    float acc[2][8][4];
    #pragma unroll
    for (int i = 0; i < 2; i++)
        #pragma unroll
        for (int j = 0; j < 8; j++)
            #pragma unroll
            for (int q = 0; q < 4; q++) acc[i][j][q] = 0.f;

    auto COMPUTE = [&](int s) {
        const uint32_t Ahi = sb + s * STAGE;
        const uint32_t Alo = Ahi + 8192;
        const uint32_t Bhi = Ahi + 16384;
        const uint32_t Blo = Ahi + 24576;
        #pragma unroll
        for (int ks = 0; ks < 2; ks++) {
            uint32_t ah[2][4], al[2][4];
            #pragma unroll
            for (int mt = 0; mt < 2; mt++) {
                const uint32_t off = swA((wm + mt * 16 + a_r) * 64 + (ks * 16 + a_k) * 2);
                ldsm4(ah[mt], Ahi + off);
                ldsm4(al[mt], Alo + off);
            }
            #pragma unroll
            for (int ng = 0; ng < 4; ng++) {
                uint32_t bh[4], bl[4];
                const uint32_t off = swB((ks * 16 + b_k) * 256 + (wn + ng * 16 + b_n) * 2);
                ldsm4t(bh, Bhi + off);
                ldsm4t(bl, Blo + off);
                #pragma unroll
                for (int mt = 0; mt < 2; mt++) {
                    #pragma unroll
                    for (int hf = 0; hf < 2; hf++) {
                        float* cc = acc[mt][ng * 2 + hf];
                        mma16816(cc, ah[mt], bh[hf * 2], bh[hf * 2 + 1]);
                        mma16816(cc, ah[mt], bl[hf * 2], bl[hf * 2 + 1]);
                        mma16816(cc, al[mt], bh[hf * 2], bh[hf * 2 + 1]);
                    }
                }
            }
        }
    };

    // ---- pipeline ----
    LOAD(0); STORE(0); __syncthreads();
    const int NC = K / BK;
    #pragma unroll 1
    for (int c = 0; c < NC; c++) {
        const int s = c & 1;
        if (c + 1 < NC) LOAD((c + 1) * BK);
        COMPUTE(s);
        if (c + 1 < NC) STORE(s ^ 1);
        __syncthreads();
    }

    // ---- epilogue: fused bias / GELU / residual, float2 stores ----
    #pragma unroll
    for (int mt = 0; mt < 2; mt++) {
        #pragma unroll
        for (int nt = 0; nt < 8; nt++) {
            const int r0 = m0 + wm + mt * 16 + (lane >> 2);
            const int cc = n0 + wn + nt * 8 + (lane & 3) * 2;
            const float bx = bias[cc], by = bias[cc + 1];
            #pragma unroll
            for (int half = 0; half < 2; half++) {
                const int r = r0 + half * 8;
                float vx = acc[mt][nt][half * 2 + 0] + bx;
                float vy = acc[mt][nt][half * 2 + 1] + by;
                if (EPI == 2) {
                    float t = tanhf(0.7978845608028654f * (vx + 0.044715f * vx * vx * vx));
                    vx = 0.5f * vx * (1.0f + t);
                    t = tanhf(0.7978845608028654f * (vy + 0.044715f * vy * vy * vy));
                    vy = 0.5f * vy * (1.0f + t);
                }
                if (EPI == 1) {
                    const float2 rv = *(const float2*)(res + (size_t)r * N + cc);
                    vx += rv.x; vy += rv.y;
                }
                float2 w; w.x = vx; w.y = vy;
                *(float2*)(C + (size_t)r * N + cc) = w;
            }
        }
    }
}

// ---------------------------------------------------------------------------
// LayerNorm (unchanged): block/row, 256 threads, float4/thread
// ---------------------------------------------------------------------------
template <int SRC>
__global__ __launch_bounds__(256) void ln_kernel(
    const float* __restrict__ Xext, const float* __restrict__ g,
    const float* __restrict__ b)
{
    __shared__ float red[16];
    const long row = blockIdx.x;
    const int  t   = threadIdx.x;

    const float* X = (SRC == 0) ? Xext : g_x1;
    float4 v = ((const float4*)(X + row * HID))[t];
    float s  = v.x + v.y + v.z + v.w;
    float sq = v.x*v.x + v.y*v.y + v.z*v.z + v.w*v.w;

    #pragma unroll
    for (int o = 16; o > 0; o >>= 1) {
        s  += __shfl_xor_sync(0xffffffffu, s,  o);
        sq += __shfl_xor_sync(0xffffffffu, sq, o);
    }
    const int warp = t >> 5, lane = t & 31;
    if (lane == 0) { red[warp] = s; red[warp + 8] = sq; }
    __syncthreads();
    if (t < 32) {
        float ss = (lane < 8) ? red[lane]     : 0.f;
        float qq = (lane < 8) ? red[lane + 8] : 0.f;
        #pragma unroll
        for (int o = 4; o > 0; o >>= 1) {
            ss += __shfl_xor_sync(0xffffffffu, ss, o);
            qq += __shfl_xor_sync(0xffffffffu, qq, o);
        }
        if (lane == 0) { red[0] = ss; red[1] = qq; }
    }
    __syncthreads();

    const float mu   = red[0] * (1.f / HID);
    const float var  = red[1] * (1.f / HID) - mu * mu;
    const float rstd = rsqrtf(var + LN_EPS);

    const float4 gv = ((const float4*)g)[t];
    const float4 bv = ((const float4*)b)[t];
    float4 y;
    y.x = (v.x - mu) * rstd * gv.x + bv.x;
    y.y = (v.y - mu) * rstd * gv.y + bv.y;
    y.z = (v.z - mu) * rstd * gv.z + bv.z;
    y.w = (v.w - mu) * rstd * gv.w + bv.w;
    ((float4*)(g_arena0 + row * HID))[t] = y;
}

// ---------------------------------------------------------------------------
// Flash attention (unchanged): fp32 online softmax, thread/query
// ---------------------------------------------------------------------------
#define AQ 128
#define AK 64

__global__ __launch_bounds__(128) void attn_kernel()
{
    __shared__ float Ks[AK][HD];
    __shared__ float Vs[AK][HD];

    const float* qkv = g_arena1;
    float*       out = g_arena0;

    const int h   = blockIdx.y;
    const int bb  = blockIdx.z;
    const int qi  = blockIdx.x * AQ + threadIdx.x;
    const long tok = (long)bb * SEQ + qi;

    const float* qptr = qkv + tok * (3 * HID) + h * HD;
    float q[HD], o[HD];
    #pragma unroll
    for (int i = 0; i < HD / 4; i++) {
        float4 v = ((const float4*)qptr)[i];
        q[4*i+0] = v.x; q[4*i+1] = v.y; q[4*i+2] = v.z; q[4*i+3] = v.w;
    }
    #pragma unroll
    for (int d = 0; d < HD; d++) o[d] = 0.f;

    float m_run = -1e30f, l_run = 0.f;

    const int lr   = threadIdx.x >> 1;
    const int lcol = (threadIdx.x & 1) * 32;

    for (int kv0 = 0; kv0 < SEQ; kv0 += AK) {
        const long ktok = (long)bb * SEQ + kv0 + lr;
        const float* kp = qkv + ktok * (3 * HID) + HID     + h * HD + lcol;
        const float* vp = qkv + ktok * (3 * HID) + 2 * HID + h * HD + lcol;
        #pragma unroll
        for (int c = 0; c < 8; c++) {
            ((float4*)&Ks[lr][lcol])[c] = ((const float4*)kp)[c];
            ((float4*)&Vs[lr][lcol])[c] = ((const float4*)vp)[c];
        }
        __syncthreads();

        #pragma unroll 1
        for (int sc = 0; sc < AK; sc += 16) {
            float s[16];
            #pragma unroll
            for (int j = 0; j < 16; j++) {
                const float* kr = &Ks[sc + j][0];
                float d = 0.f;
                #pragma unroll
                for (int dd = 0; dd < HD; dd++) d = fmaf(q[dd], kr[dd], d);
                s[j] = d * 0.125f;
            }
            float mloc = s[0];
            #pragma unroll
            for (int j = 1; j < 16; j++) mloc = fmaxf(mloc, s[j]);
            const float m_new = fmaxf(m_run, mloc);
            const float corr  = __expf(m_run - m_new);
            l_run *= corr;
            #pragma unroll
            for (int dd = 0; dd < HD; dd++) o[dd] *= corr;
            #pragma unroll
            for (int j = 0; j < 16; j++) {
                const float p = __expf(s[j] - m_new);
                l_run += p;
                const float* vr = &Vs[sc + j][0];
                #pragma unroll
                for (int dd = 0; dd < HD; dd++) o[dd] = fmaf(p, vr[dd], o[dd]);
            }
            m_run = m_new;
        }
        __syncthreads();
    }

    const float inv = 1.f / l_run;
    float* op = out + tok * HID + h * HD;
    #pragma unroll
    for (int i = 0; i < HD / 4; i++) {
        float4 y;
        y.x = o[4*i+0] * inv; y.y = o[4*i+1] * inv;
        y.z = o[4*i+2] * inv; y.w = o[4*i+3] * inv;
        ((float4*)op)[i] = y;
    }
}

// ---------------------------------------------------------------------------
// Launch
// ---------------------------------------------------------------------------
extern "C" void kernel_launch(void* const* d_in, const int* in_sizes, int n_in,
                              void* d_out, int out_size)
{
    const float* x     = (const float*)d_in[0];
    const float* ln1_g = (const float*)d_in[1];
    const float* ln1_b = (const float*)d_in[2];
    const float* qkv_w = (const float*)d_in[3];
    const float* qkv_b = (const float*)d_in[4];
    const float* out_w = (const float*)d_in[5];
    const float* out_b = (const float*)d_in[6];
    const float* ln2_g = (const float*)d_in[7];
    const float* ln2_b = (const float*)d_in[8];
    const float* w1    = (const float*)d_in[9];
    const float* b1    = (const float*)d_in[10];
    const float* w2    = (const float*)d_in[11];
    const float* b2    = (const float*)d_in[12];
    float* out = (float*)d_out;

    // 64KB dynamic smem opt-in (host attribute set; not a stream op)
    cudaFuncSetAttribute((const void*)hgemm<0, P_ARENA0, P_ARENA1, P_EXT>,
                         cudaFuncAttributeMaxDynamicSharedMemorySize, HG_SMEM);
    cudaFuncSetAttribute((const void*)hgemm<1, P_ARENA0, P_X1, P_EXT>,
                         cudaFuncAttributeMaxDynamicSharedMemorySize, HG_SMEM);
    cudaFuncSetAttribute((const void*)hgemm<2, P_ARENA0, P_ARENA1, P_EXT>,
                         cudaFuncAttributeMaxDynamicSharedMemorySize, HG_SMEM);
    cudaFuncSetAttribute((const void*)hgemm<1, P_ARENA1, P_EXT, P_X1>,
                         cudaFuncAttributeMaxDynamicSharedMemorySize, HG_SMEM);

    // 1) LN1: x -> arena0
    ln_kernel<0><<<NTOK, 256>>>(x, ln1_g, ln1_b);

    // 2) QKV: arena0 @ qkv_w + qkv_b -> arena1   [8192 x 3072, K=1024]
    hgemm<0, P_ARENA0, P_ARENA1, P_EXT>
        <<<dim3((3 * HID) / BN, NTOK / BM), 256, HG_SMEM>>>(
        nullptr, qkv_w, qkv_b, nullptr, nullptr, NTOK, 3 * HID, HID);

    // 3) attention: arena1 -> arena0
    attn_kernel<<<dim3(SEQ / AQ, NHEAD, BATCH), AQ>>>();

    // 4) x1 = x + arena0 @ out_w + out_b -> g_x1   [8192 x 1024, K=1024]
    hgemm<1, P_ARENA0, P_X1, P_EXT>
        <<<dim3(HID / BN, NTOK / BM), 256, HG_SMEM>>>(
        nullptr, out_w, out_b, x, nullptr, NTOK, HID, HID);

    // 5) LN2: g_x1 -> arena0
    ln_kernel<1><<<NTOK, 256>>>(nullptr, ln2_g, ln2_b);

    // 6) mid = gelu(arena0 @ w1 + b1) -> arena1   [8192 x 4096, K=1024]
    hgemm<2, P_ARENA0, P_ARENA1, P_EXT>
        <<<dim3(INTER / BN, NTOK / BM), 256, HG_SMEM>>>(
        nullptr, w1, b1, nullptr, nullptr, NTOK, INTER, HID);

    // 7) out = g_x1 + arena1 @ w2 + b2 -> d_out   [8192 x 1024, K=4096]
    hgemm<1, P_ARENA1, P_EXT, P_X1>
        <<<dim3(HID / BN, NTOK / BM), 256, HG_SMEM>>>(
        nullptr, w2, b2, nullptr, out, NTOK, HID, INTER);
}

// round 6
// speedup vs baseline: 2.5671x; 1.1436x over previous
#include <cuda_runtime.h>
#include <cuda_bf16.h>
#include <math.h>
#include <stdint.h>

// ---------------------------------------------------------------------------
// Problem constants
// ---------------------------------------------------------------------------
#define HID   1024
#define NHEAD 16
#define HD    64
#define INTER 4096
#define BATCH 4
#define SEQ   2048
#define NTOK  (BATCH * SEQ)          // 8192
#define LN_EPS 1e-5f

// ---------------------------------------------------------------------------
// Scratch arenas (static device globals; no runtime allocation)
// ---------------------------------------------------------------------------
__device__ float g_arena0[NTOK * HID];       // h / attn / h2
__device__ float g_arena1[NTOK * INTER];     // qkv (3/4 used) / mid
__device__ float g_x1    [NTOK * HID];       // residual-1 output

enum { P_ARENA0 = 0, P_ARENA1 = 1, P_X1 = 2, P_EXT = 3 };

__device__ __forceinline__ const float* sel_ptr(int sel, const float* ext) {
    switch (sel) {
        case P_ARENA0: return g_arena0;
        case P_ARENA1: return g_arena1;
        case P_X1:     return g_x1;
        default:       return ext;
    }
}

// ---------------------------------------------------------------------------
// Baseline-PTX tensor-core helpers (sm_80+ features; compile for compute_103)
// ---------------------------------------------------------------------------
__device__ __forceinline__ uint32_t smem_u32(const void* p) {
    uint32_t a;
    asm("{ .reg .u64 t; cvta.to.shared.u64 t, %1; cvt.u32.u64 %0, t; }"
        : "=r"(a) : "l"(p));
    return a;
}
__device__ __forceinline__ void ldsm4(uint32_t* r, uint32_t addr) {
    asm volatile("ldmatrix.sync.aligned.m8n8.x4.shared.b16 {%0,%1,%2,%3}, [%4];"
                 : "=r"(r[0]), "=r"(r[1]), "=r"(r[2]), "=r"(r[3]) : "r"(addr));
}
__device__ __forceinline__ void ldsm4t(uint32_t* r, uint32_t addr) {
    asm volatile("ldmatrix.sync.aligned.m8n8.x4.trans.shared.b16 {%0,%1,%2,%3}, [%4];"
                 : "=r"(r[0]), "=r"(r[1]), "=r"(r[2]), "=r"(r[3]) : "r"(addr));
}
__device__ __forceinline__ void mma16816(float* c, const uint32_t* a,
                                         uint32_t b0, uint32_t b1) {
    asm volatile(
        "mma.sync.aligned.m16n8k16.row.col.f32.bf16.bf16.f32 "
        "{%0,%1,%2,%3}, {%4,%5,%6,%7}, {%8,%9}, {%0,%1,%2,%3};"
        : "+f"(c[0]), "+f"(c[1]), "+f"(c[2]), "+f"(c[3])
        : "r"(a[0]), "r"(a[1]), "r"(a[2]), "r"(a[3]), "r"(b0), "r"(b1));
}

// 128B-row swizzle (rows of 64 bf16)
__device__ __forceinline__ uint32_t sw128(uint32_t off) {
    return off ^ ((off >> 3) & 0x70);
}

// ---------------------------------------------------------------------------
// HMMA GEMM (unchanged from R5): C = A@B + bias (+epilogue), 3xbf16 split
// ---------------------------------------------------------------------------
#define BM 128
#define BN 128
#define BK 32
#define STAGE 32768
#define HG_SMEM (2 * STAGE)

__device__ __forceinline__ uint32_t swA(uint32_t off) { return off ^ ((off >> 2) & 0x30); }
__device__ __forceinline__ uint32_t swB(uint32_t off) { return off ^ ((off >> 4) & 0x70); }

template <int EPI, int SA, int SC, int SR>
__global__ __launch_bounds__(256) void hgemm(
    const float* __restrict__ Aext, const float* __restrict__ B,
    const float* __restrict__ bias, const float* __restrict__ Rext,
    float* __restrict__ Cext, int M, int N, int K)
{
    extern __shared__ char smem[];
    const float* A   = sel_ptr(SA, Aext);
    const float* res = sel_ptr(SR, Rext);
    float*       C   = const_cast<float*>(sel_ptr(SC, (const float*)Cext));

    const uint32_t sb = smem_u32(smem);
    const int tid  = threadIdx.x;
    const int lane = tid & 31;
    const int wid  = tid >> 5;
    const int m0   = blockIdx.y * BM;
    const int n0   = blockIdx.x * BN;

    const int ar = tid >> 1;
    const int ac = (tid & 1) * 16;
    const int br = tid >> 3;
    const int bc = (tid & 7) * 16;
    const size_t arow = (size_t)(m0 + ar) * K;

    float4 av[4], bv[4];
    auto LOAD = [&](int k0) {
        #pragma unroll
        for (int i = 0; i < 4; i++)
            av[i] = *(const float4*)(A + arow + k0 + ac + i * 4);
        #pragma unroll
        for (int i = 0; i < 4; i++)
            bv[i] = *(const float4*)(B + (size_t)(k0 + br) * N + n0 + bc + i * 4);
    };
    auto STORE = [&](int s) {
        char* Ahi = smem + s * STAGE;
        char* Alo = Ahi + 8192;
        char* Bhi = Ahi + 16384;
        char* Blo = Ahi + 24576;
        #pragma unroll
        for (int i = 0; i < 4; i++) {
            const float4 v = av[i];
            __nv_bfloat162 h01 = __floats2bfloat162_rn(v.x, v.y);
            __nv_bfloat162 h23 = __floats2bfloat162_rn(v.z, v.w);
            __nv_bfloat162 l01 = __floats2bfloat162_rn(v.x - __bfloat162float(h01.x),
                                                       v.y - __bfloat162float(h01.y));
            __nv_bfloat162 l23 = __floats2bfloat162_rn(v.z - __bfloat162float(h23.x),
                                                       v.w - __bfloat162float(h23.y));
            const uint32_t so = swA(ar * 64 + (ac + i * 4) * 2);
            uint2 hv, lv;
            hv.x = *(uint32_t*)&h01; hv.y = *(uint32_t*)&h23;
            lv.x = *(uint32_t*)&l01; lv.y = *(uint32_t*)&l23;
            *(uint2*)(Ahi + so) = hv;
            *(uint2*)(Alo + so) = lv;
        }
        #pragma unroll
        for (int i = 0; i < 4; i++) {
            const float4 v = bv[i];
            __nv_bfloat162 h01 = __floats2bfloat162_rn(v.x, v.y);
            __nv_bfloat162 h23 = __floats2bfloat162_rn(v.z, v.w);
            __nv_bfloat162 l01 = __floats2bfloat162_rn(v.x - __bfloat162float(h01.x),
                                                       v.y - __bfloat162float(h01.y));
            __nv_bfloat162 l23 = __floats2bfloat162_rn(v.z - __bfloat162float(h23.x),
                                                       v.w - __bfloat162float(h23.y));
            const uint32_t so = swB(br * 256 + (bc + i * 4) * 2);
            uint2 hv, lv;
            hv.x = *(uint32_t*)&h01; hv.y = *(uint32_t*)&h23;
            lv.x = *(uint32_t*)&l01; lv.y = *(uint32_t*)&l23;
            *(uint2*)(Bhi + so) = hv;
            *(uint2*)(Blo + so) = lv;
        }
    };

    const int wm = (wid & 3) * 32;
    const int wn = (wid >> 2) * 64;
    const int a_r = lane & 15;
    const int a_k = (lane >> 4) * 8;
    const int b_k = lane & 15;
    const int b_n = (lane >> 4) * 8;

    float acc[2][8][4];
    #pragma unroll
    for (int i = 0; i < 2; i++)
        #pragma unroll
        for (int j = 0; j < 8; j++)
            #pragma unroll
            for (int q = 0; q < 4; q++) acc[i][j][q] = 0.f;

    auto COMPUTE = [&](int s) {
        const uint32_t Ahi = sb + s * STAGE;
        const uint32_t Alo = Ahi + 8192;
        const uint32_t Bhi = Ahi + 16384;
        const uint32_t Blo = Ahi + 24576;
        #pragma unroll
        for (int ks = 0; ks < 2; ks++) {
            uint32_t ah[2][4], al[2][4];
            #pragma unroll
            for (int mt = 0; mt < 2; mt++) {
                const uint32_t off = swA((wm + mt * 16 + a_r) * 64 + (ks * 16 + a_k) * 2);
                ldsm4(ah[mt], Ahi + off);
                ldsm4(al[mt], Alo + off);
            }
            #pragma unroll
            for (int ng = 0; ng < 4; ng++) {
                uint32_t bh[4], bl[4];
                const uint32_t off = swB((ks * 16 + b_k) * 256 + (wn + ng * 16 + b_n) * 2);
                ldsm4t(bh, Bhi + off);
                ldsm4t(bl, Blo + off);
                #pragma unroll
                for (int mt = 0; mt < 2; mt++) {
                    #pragma unroll
                    for (int hf = 0; hf < 2; hf++) {
                        float* cc = acc[mt][ng * 2 + hf];
                        mma16816(cc, ah[mt], bh[hf * 2], bh[hf * 2 + 1]);
                        mma16816(cc, ah[mt], bl[hf * 2], bl[hf * 2 + 1]);
                        mma16816(cc, al[mt], bh[hf * 2], bh[hf * 2 + 1]);
                    }
                }
            }
        }
    };

    LOAD(0); STORE(0); __syncthreads();
    const int NC = K / BK;
    #pragma unroll 1
    for (int c = 0; c < NC; c++) {
        const int s = c & 1;
        if (c + 1 < NC) LOAD((c + 1) * BK);
        COMPUTE(s);
        if (c + 1 < NC) STORE(s ^ 1);
        __syncthreads();
    }

    #pragma unroll
    for (int mt = 0; mt < 2; mt++) {
        #pragma unroll
        for (int nt = 0; nt < 8; nt++) {
            const int r0 = m0 + wm + mt * 16 + (lane >> 2);
            const int cc = n0 + wn + nt * 8 + (lane & 3) * 2;
            const float bx = bias[cc], by = bias[cc + 1];
            #pragma unroll
            for (int half = 0; half < 2; half++) {
                const int r = r0 + half * 8;
                float vx = acc[mt][nt][half * 2 + 0] + bx;
                float vy = acc[mt][nt][half * 2 + 1] + by;
                if (EPI == 2) {
                    float t = tanhf(0.7978845608028654f * (vx + 0.044715f * vx * vx * vx));
                    vx = 0.5f * vx * (1.0f + t);
                    t = tanhf(0.7978845608028654f * (vy + 0.044715f * vy * vy * vy));
                    vy = 0.5f * vy * (1.0f + t);
                }
                if (EPI == 1) {
                    const float2 rv = *(const float2*)(res + (size_t)r * N + cc);
                    vx += rv.x; vy += rv.y;
                }
                float2 w; w.x = vx; w.y = vy;
                *(float2*)(C + (size_t)r * N + cc) = w;
            }
        }
    }
}

// ---------------------------------------------------------------------------
// Tensor-core flash attention, 3xbf16 split throughout.
// One CTA: 128 query rows x one (head, batch). 8 warps, warp = m16 slab.
// KV chunks of 64, double-buffered smem, fp32 online softmax in C-layout.
// Smem: Qh 16K | Ql 16K | stage{0,1}: Kh 8K, Kl 8K, Vh 8K, Vl 8K  => 96KB
// ---------------------------------------------------------------------------
#define QT 128
#define KT 64
#define ATT_SMEM (32768 + 2 * 32768)

__global__ __launch_bounds__(256) void attn_mma()
{
    extern __shared__ char smem[];
    const uint32_t sb = smem_u32(smem);
    const int tid  = threadIdx.x;
    const int lane = tid & 31;
    const int wid  = tid >> 5;
    const int h    = blockIdx.y;
    const int bb   = blockIdx.z;
    const int q0   = blockIdx.x * QT;
    const float* qkv = g_arena1;

    // ---- Q load + split into smem ----
    {
        const int row = tid >> 1;
        const int ch  = (tid & 1) * 32;
        const float* qp = qkv + (size_t)(bb * SEQ + q0 + row) * 3072 + h * 64 + ch;
        char* Qh = smem;
        char* Ql = smem + 16384;
        #pragma unroll
        for (int i = 0; i < 8; i++) {
            const float4 v = *(const float4*)(qp + i * 4);
            __nv_bfloat162 h01 = __floats2bfloat162_rn(v.x, v.y);
            __nv_bfloat162 h23 = __floats2bfloat162_rn(v.z, v.w);
            __nv_bfloat162 l01 = __floats2bfloat162_rn(v.x - __bfloat162float(h01.x),
                                                       v.y - __bfloat162float(h01.y));
            __nv_bfloat162 l23 = __floats2bfloat162_rn(v.z - __bfloat162float(h23.x),
                                                       v.w - __bfloat162float(h23.y));
            const uint32_t so = sw128(row * 128 + (ch + i * 4) * 2);
            uint2 hv, lv;
            hv.x = *(uint32_t*)&h01; hv.y = *(uint32_t*)&h23;
            lv.x = *(uint32_t*)&l01; lv.y = *(uint32_t*)&l23;
            *(uint2*)(Qh + so) = hv;
            *(uint2*)(Ql + so) = lv;
        }
    }

    // ---- KV chunk loader (regs) + split store ----
    const int kr = tid >> 2;
    const int kc = (tid & 3) * 16;
    float4 kv4[8];
    auto LOADKV = [&](int c) {
        const size_t base = (size_t)(bb * SEQ + c * KT + kr) * 3072 + h * 64 + kc;
        #pragma unroll
        for (int i = 0; i < 4; i++)
            kv4[i] = *(const float4*)(qkv + base + 1024 + i * 4);
        #pragma unroll
        for (int i = 0; i < 4; i++)
            kv4[4 + i] = *(const float4*)(qkv + base + 2048 + i * 4);
    };
    auto STOREKV = [&](int s) {
        char* st = smem + 32768 + s * 32768;
        #pragma unroll
        for (int i = 0; i < 8; i++) {
            const float4 v = kv4[i];
            __nv_bfloat162 h01 = __floats2bfloat162_rn(v.x, v.y);
            __nv_bfloat162 h23 = __floats2bfloat162_rn(v.z, v.w);
            __nv_bfloat162 l01 = __floats2bfloat162_rn(v.x - __bfloat162float(h01.x),
                                                       v.y - __bfloat162float(h01.y));
            __nv_bfloat162 l23 = __floats2bfloat162_rn(v.z - __bfloat162float(h23.x),
                                                       v.w - __bfloat162float(h23.y));
            const uint32_t so = sw128(kr * 128 + (kc + (i & 3) * 4) * 2);
            char* hb = st + ((i < 4) ? 0 : 16384);   // K then V
            uint2 hv, lv;
            hv.x = *(uint32_t*)&h01; hv.y = *(uint32_t*)&h23;
            lv.x = *(uint32_t*)&l01; lv.y = *(uint32_t*)&l23;
            *(uint2*)(hb + so)        = hv;
            *(uint2*)(hb + 8192 + so) = lv;
        }
    };

    LOADKV(0); STOREKV(0);
    __syncthreads();

    // ---- Q fragments pinned in registers (m16 x k64, hi+lo) ----
    const int wm = wid * 16;
    uint32_t qh[4][4], ql[4][4];
    {
        const uint32_t Qhb = sb, Qlb = sb + 16384;
        #pragma unroll
        for (int ks = 0; ks < 4; ks++) {
            const uint32_t off =
                sw128((wm + (lane & 15)) * 128 + (ks * 16 + (lane >> 4) * 8) * 2);
            ldsm4(qh[ks], Qhb + off);
            ldsm4(ql[ks], Qlb + off);
        }
    }

    float oacc[8][4];
    #pragma unroll
    for (int j = 0; j < 8; j++)
        #pragma unroll
        for (int q = 0; q < 4; q++) oacc[j][q] = 0.f;
    float m0 = -1e30f, m1 = -1e30f, l0 = 0.f, l1 = 0.f;

    // K-operand ldmatrix (non-trans, K-major B): per-lane addressing
    const int k_rowadd = ((lane >> 4) & 1) * 8;   // matrices 2,3 -> +8 n-rows
    const int k_koff   = ((lane >> 3) & 1) * 8;   // matrices 1,3 -> +8 k
    const int k_r8     = lane & 7;

    const int NCH = SEQ / KT;
    #pragma unroll 1
    for (int c = 0; c < NCH; c++) {
        const int s = c & 1;
        if (c + 1 < NCH) LOADKV(c + 1);

        const uint32_t st  = sb + 32768 + s * 32768;
        const uint32_t Khb = st, Klb = st + 8192, Vhb = st + 16384, Vlb = st + 24576;

        // ---- S = Q @ K^T (3-term split), raw scores in fp32 frags ----
        float sacc[8][4];
        #pragma unroll
        for (int j = 0; j < 8; j++)
            #pragma unroll
            for (int q = 0; q < 4; q++) sacc[j][q] = 0.f;

        #pragma unroll
        for (int ks = 0; ks < 4; ks++) {
            #pragma unroll
            for (int j = 0; j < 4; j++) {
                const uint32_t off = sw128((j * 16 + k_r8 + k_rowadd) * 128 +
                                           (ks * 16 + k_koff) * 2);
                uint32_t kb[4], kl[4];
                ldsm4(kb, Khb + off);
                ldsm4(kl, Klb + off);
                #pragma unroll
                for (int t2 = 0; t2 < 2; t2++) {
                    float* cc = sacc[j * 2 + t2];
                    mma16816(cc, qh[ks], kb[t2 * 2], kb[t2 * 2 + 1]);
                    mma16816(cc, qh[ks], kl[t2 * 2], kl[t2 * 2 + 1]);
                    mma16816(cc, ql[ks], kb[t2 * 2], kb[t2 * 2 + 1]);
                }
            }
        }

        // ---- online softmax (rows r = wm + lane>>2, and r+8) ----
        float vm0 = -1e30f, vm1 = -1e30f;
        #pragma unroll
        for (int j = 0; j < 8; j++) {
            vm0 = fmaxf(vm0, fmaxf(sacc[j][0], sacc[j][1]));
            vm1 = fmaxf(vm1, fmaxf(sacc[j][2], sacc[j][3]));
        }
        vm0 = fmaxf(vm0, __shfl_xor_sync(0xffffffffu, vm0, 1));
        vm0 = fmaxf(vm0, __shfl_xor_sync(0xffffffffu, vm0, 2));
        vm1 = fmaxf(vm1, __shfl_xor_sync(0xffffffffu, vm1, 1));
        vm1 = fmaxf(vm1, __shfl_xor_sync(0xffffffffu, vm1, 2));
        vm0 *= 0.125f; vm1 *= 0.125f;

        const float mn0 = fmaxf(m0, vm0), mn1 = fmaxf(m1, vm1);
        const float c0 = __expf(m0 - mn0), c1 = __expf(m1 - mn1);
        m0 = mn0; m1 = mn1;
        l0 *= c0;  l1 *= c1;
        #pragma unroll
        for (int j = 0; j < 8; j++) {
            oacc[j][0] *= c0; oacc[j][1] *= c0;
            oacc[j][2] *= c1; oacc[j][3] *= c1;
        }
        #pragma unroll
        for (int j = 0; j < 8; j++) {
            sacc[j][0] = __expf(fmaf(sacc[j][0], 0.125f, -mn0));
            sacc[j][1] = __expf(fmaf(sacc[j][1], 0.125f, -mn0));
            sacc[j][2] = __expf(fmaf(sacc[j][2], 0.125f, -mn1));
            sacc[j][3] = __expf(fmaf(sacc[j][3], 0.125f, -mn1));
            l0 += sacc[j][0] + sacc[j][1];
            l1 += sacc[j][2] + sacc[j][3];
        }

        // ---- O += P @ V (3-term split); P repacked C-frag -> A-frag ----
        #pragma unroll
        for (int kk = 0; kk < 4; kk++) {
            const float* p0 = sacc[kk * 2];
            const float* p1 = sacc[kk * 2 + 1];
            uint32_t pa[4], pl[4];
            {
                __nv_bfloat162 h0 = __floats2bfloat162_rn(p0[0], p0[1]);
                __nv_bfloat162 h1 = __floats2bfloat162_rn(p0[2], p0[3]);
                __nv_bfloat162 h2 = __floats2bfloat162_rn(p1[0], p1[1]);
                __nv_bfloat162 h3 = __floats2bfloat162_rn(p1[2], p1[3]);
                __nv_bfloat162 e0 = __floats2bfloat162_rn(p0[0] - __bfloat162float(h0.x),
                                                          p0[1] - __bfloat162float(h0.y));
                __nv_bfloat162 e1 = __floats2bfloat162_rn(p0[2] - __bfloat162float(h1.x),
                                                          p0[3] - __bfloat162float(h1.y));
                __nv_bfloat162 e2 = __floats2bfloat162_rn(p1[0] - __bfloat162float(h2.x),
                                                          p1[1] - __bfloat162float(h2.y));
                __nv_bfloat162 e3 = __floats2bfloat162_rn(p1[2] - __bfloat162float(h3.x),
                                                          p1[3] - __bfloat162float(h3.y));
                pa[0] = *(uint32_t*)&h0; pa[1] = *(uint32_t*)&h1;
                pa[2] = *(uint32_t*)&h2; pa[3] = *(uint32_t*)&h3;
                pl[0] = *(uint32_t*)&e0; pl[1] = *(uint32_t*)&e1;
                pl[2] = *(uint32_t*)&e2; pl[3] = *(uint32_t*)&e3;
            }
            #pragma unroll
            for (int j = 0; j < 4; j++) {
                const uint32_t off = sw128((kk * 16 + (lane & 15)) * 128 +
                                           (j * 16 + (lane >> 4) * 8) * 2);
                uint32_t vb[4], vl[4];
                ldsm4t(vb, Vhb + off);
                ldsm4t(vl, Vlb + off);
                #pragma unroll
                for (int t2 = 0; t2 < 2; t2++) {
                    float* cc = oacc[j * 2 + t2];
                    mma16816(cc, pa, vb[t2 * 2], vb[t2 * 2 + 1]);
                    mma16816(cc, pa, vl[t2 * 2], vl[t2 * 2 + 1]);
                    mma16816(cc, pl, vb[t2 * 2], vb[t2 * 2 + 1]);
                }
            }
        }

        if (c + 1 < NCH) STOREKV(s ^ 1);
        __syncthreads();
    }

    // ---- finalize: divide by l, write out ----
    l0 += __shfl_xor_sync(0xffffffffu, l0, 1);
    l0 += __shfl_xor_sync(0xffffffffu, l0, 2);
    l1 += __shfl_xor_sync(0xffffffffu, l1, 1);
    l1 += __shfl_xor_sync(0xffffffffu, l1, 2);
    const float i0 = 1.f / l0, i1 = 1.f / l1;

    const int r0g = bb * SEQ + q0 + wm + (lane >> 2);
    const int cb  = h * 64 + (lane & 3) * 2;
    #pragma unroll
    for (int j = 0; j < 8; j++) {
        float2 w0, w1;
        w0.x = oacc[j][0] * i0; w0.y = oacc[j][1] * i0;
        w1.x = oacc[j][2] * i1; w1.y = oacc[j][3] * i1;
        *(float2*)(g_arena0 + (size_t)r0g * HID + cb + j * 8)       = w0;
        *(float2*)(g_arena0 + (size_t)(r0g + 8) * HID + cb + j * 8) = w1;
    }
}

// ---------------------------------------------------------------------------
// LayerNorm (unchanged)
// ---------------------------------------------------------------------------
template <int SRC>
__global__ __launch_bounds__(256) void ln_kernel(
    const float* __restrict__ Xext, const float* __restrict__ g,
    const float* __restrict__ b)
{
    __shared__ float red[16];
    const long row = blockIdx.x;
    const int  t   = threadIdx.x;

    const float* X = (SRC == 0) ? Xext : g_x1;
    float4 v = ((const float4*)(X + row * HID))[t];
    float s  = v.x + v.y + v.z + v.w;
    float sq = v.x*v.x + v.y*v.y + v.z*v.z + v.w*v.w;

    #pragma unroll
    for (int o = 16; o > 0; o >>= 1) {
        s  += __shfl_xor_sync(0xffffffffu, s,  o);
        sq += __shfl_xor_sync(0xffffffffu, sq, o);
    }
    const int warp = t >> 5, lane = t & 31;
    if (lane == 0) { red[warp] = s; red[warp + 8] = sq; }
    __syncthreads();
    if (t < 32) {
        float ss = (lane < 8) ? red[lane]     : 0.f;
        float qq = (lane < 8) ? red[lane + 8] : 0.f;
        #pragma unroll
        for (int o = 4; o > 0; o >>= 1) {
            ss += __shfl_xor_sync(0xffffffffu, ss, o);
            qq += __shfl_xor_sync(0xffffffffu, qq, o);
        }
        if (lane == 0) { red[0] = ss; red[1] = qq; }
    }
    __syncthreads();

    const float mu   = red[0] * (1.f / HID);
    const float var  = red[1] * (1.f / HID) - mu * mu;
    const float rstd = rsqrtf(var + LN_EPS);

    const float4 gv = ((const float4*)g)[t];
    const float4 bv = ((const float4*)b)[t];
    float4 y;
    y.x = (v.x - mu) * rstd * gv.x + bv.x;
    y.y = (v.y - mu) * rstd * gv.y + bv.y;
    y.z = (v.z - mu) * rstd * gv.z + bv.z;
    y.w = (v.w - mu) * rstd * gv.w + bv.w;
    ((float4*)(g_arena0 + row * HID))[t] = y;
}

// ---------------------------------------------------------------------------
// Launch
// ---------------------------------------------------------------------------
extern "C" void kernel_launch(void* const* d_in, const int* in_sizes, int n_in,
                              void* d_out, int out_size)
{
    const float* x     = (const float*)d_in[0];
    const float* ln1_g = (const float*)d_in[1];
    const float* ln1_b = (const float*)d_in[2];
    const float* qkv_w = (const float*)d_in[3];
    const float* qkv_b = (const float*)d_in[4];
    const float* out_w = (const float*)d_in[5];
    const float* out_b = (const float*)d_in[6];
    const float* ln2_g = (const float*)d_in[7];
    const float* ln2_b = (const float*)d_in[8];
    const float* w1    = (const float*)d_in[9];
    const float* b1    = (const float*)d_in[10];
    const float* w2    = (const float*)d_in[11];
    const float* b2    = (const float*)d_in[12];
    float* out = (float*)d_out;

    cudaFuncSetAttribute((const void*)hgemm<0, P_ARENA0, P_ARENA1, P_EXT>,
                         cudaFuncAttributeMaxDynamicSharedMemorySize, HG_SMEM);
    cudaFuncSetAttribute((const void*)hgemm<1, P_ARENA0, P_X1, P_EXT>,
                         cudaFuncAttributeMaxDynamicSharedMemorySize, HG_SMEM);
    cudaFuncSetAttribute((const void*)hgemm<2, P_ARENA0, P_ARENA1, P_EXT>,
                         cudaFuncAttributeMaxDynamicSharedMemorySize, HG_SMEM);
    cudaFuncSetAttribute((const void*)hgemm<1, P_ARENA1, P_EXT, P_X1>,
                         cudaFuncAttributeMaxDynamicSharedMemorySize, HG_SMEM);
    cudaFuncSetAttribute((const void*)attn_mma,
                         cudaFuncAttributeMaxDynamicSharedMemorySize, ATT_SMEM);

    // 1) LN1: x -> arena0
    ln_kernel<0><<<NTOK, 256>>>(x, ln1_g, ln1_b);

    // 2) QKV: arena0 @ qkv_w + qkv_b -> arena1
    hgemm<0, P_ARENA0, P_ARENA1, P_EXT>
        <<<dim3((3 * HID) / BN, NTOK / BM), 256, HG_SMEM>>>(
        nullptr, qkv_w, qkv_b, nullptr, nullptr, NTOK, 3 * HID, HID);

    // 3) attention (tensor cores): arena1 -> arena0
    attn_mma<<<dim3(SEQ / QT, NHEAD, BATCH), 256, ATT_SMEM>>>();

    // 4) x1 = x + arena0 @ out_w + out_b -> g_x1
    hgemm<1, P_ARENA0, P_X1, P_EXT>
        <<<dim3(HID / BN, NTOK / BM), 256, HG_SMEM>>>(
        nullptr, out_w, out_b, x, nullptr, NTOK, HID, HID);

    // 5) LN2: g_x1 -> arena0
    ln_kernel<1><<<NTOK, 256>>>(nullptr, ln2_g, ln2_b);

    // 6) mid = gelu(arena0 @ w1 + b1) -> arena1
    hgemm<2, P_ARENA0, P_ARENA1, P_EXT>
        <<<dim3(INTER / BN, NTOK / BM), 256, HG_SMEM>>>(
        nullptr, w1, b1, nullptr, nullptr, NTOK, INTER, HID);

    // 7) out = g_x1 + arena1 @ w2 + b2 -> d_out
    hgemm<1, P_ARENA1, P_EXT, P_X1>
        <<<dim3(HID / BN, NTOK / BM), 256, HG_SMEM>>>(
        nullptr, w2, b2, nullptr, out, NTOK, HID, INTER);
}

// round 7
// speedup vs baseline: 5.3838x; 2.0973x over previous
#include <cuda_runtime.h>
#include <cuda_bf16.h>
#include <math.h>
#include <stdint.h>

// ---------------------------------------------------------------------------
// Problem constants
// ---------------------------------------------------------------------------
#define HID   1024
#define NHEAD 16
#define HD    64
#define INTER 4096
#define BATCH 4
#define SEQ   2048
#define NTOK  (BATCH * SEQ)          // 8192
#define LN_EPS 1e-5f

// ---------------------------------------------------------------------------
// Scratch (static device globals; no runtime allocation)
// ---------------------------------------------------------------------------
__device__ float g_qkv[NTOK * 3 * HID];                 // fp32 QKV (attn input)
__device__ float g_x1 [NTOK * HID];                     // residual-1 (fp32)
__device__ __nv_bfloat16 g_h_hi  [NTOK * HID];          // LN out hi/lo
__device__ __nv_bfloat16 g_h_lo  [NTOK * HID];
__device__ __nv_bfloat16 g_attn_hi[NTOK * HID];         // attention out hi/lo
__device__ __nv_bfloat16 g_attn_lo[NTOK * HID];
__device__ __nv_bfloat16 g_mid_hi[NTOK * INTER];        // GELU(MLP1) hi/lo
__device__ __nv_bfloat16 g_mid_lo[NTOK * INTER];
__device__ __nv_bfloat16 g_wqkv_hi[HID * 3 * HID];      // split weights
__device__ __nv_bfloat16 g_wqkv_lo[HID * 3 * HID];
__device__ __nv_bfloat16 g_wout_hi[HID * HID];
__device__ __nv_bfloat16 g_wout_lo[HID * HID];
__device__ __nv_bfloat16 g_w1_hi  [HID * INTER];
__device__ __nv_bfloat16 g_w1_lo  [HID * INTER];
__device__ __nv_bfloat16 g_w2_hi  [INTER * HID];
__device__ __nv_bfloat16 g_w2_lo  [INTER * HID];

// ---------------------------------------------------------------------------
// PTX helpers (sm_80-baseline features only; compile for compute_103)
// ---------------------------------------------------------------------------
__device__ __forceinline__ uint32_t smem_u32(const void* p) {
    uint32_t a;
    asm("{ .reg .u64 t; cvta.to.shared.u64 t, %1; cvt.u32.u64 %0, t; }"
        : "=r"(a) : "l"(p));
    return a;
}
__device__ __forceinline__ void ldsm4(uint32_t* r, uint32_t addr) {
    asm volatile("ldmatrix.sync.aligned.m8n8.x4.shared.b16 {%0,%1,%2,%3}, [%4];"
                 : "=r"(r[0]), "=r"(r[1]), "=r"(r[2]), "=r"(r[3]) : "r"(addr));
}
__device__ __forceinline__ void ldsm4t(uint32_t* r, uint32_t addr) {
    asm volatile("ldmatrix.sync.aligned.m8n8.x4.trans.shared.b16 {%0,%1,%2,%3}, [%4];"
                 : "=r"(r[0]), "=r"(r[1]), "=r"(r[2]), "=r"(r[3]) : "r"(addr));
}
__device__ __forceinline__ void mma16816(float* c, const uint32_t* a,
                                         uint32_t b0, uint32_t b1) {
    asm volatile(
        "mma.sync.aligned.m16n8k16.row.col.f32.bf16.bf16.f32 "
        "{%0,%1,%2,%3}, {%4,%5,%6,%7}, {%8,%9}, {%0,%1,%2,%3};"
        : "+f"(c[0]), "+f"(c[1]), "+f"(c[2]), "+f"(c[3])
        : "r"(a[0]), "r"(a[1]), "r"(a[2]), "r"(a[3]), "r"(b0), "r"(b1));
}
__device__ __forceinline__ void cpasync16(uint32_t s, const void* g) {
    asm volatile("cp.async.cg.shared.global [%0], [%1], 16;" :: "r"(s), "l"(g));
}
#define CP_COMMIT() asm volatile("cp.async.commit_group;" ::: "memory")
#define CP_WAIT1()  asm volatile("cp.async.wait_group 1;"  ::: "memory")

__device__ __forceinline__ uint32_t swA(uint32_t off) { return off ^ ((off >> 2) & 0x30); }
__device__ __forceinline__ uint32_t swB(uint32_t off) { return off ^ ((off >> 4) & 0x70); }
__device__ __forceinline__ uint32_t sw128(uint32_t off) { return off ^ ((off >> 3) & 0x70); }

// ---------------------------------------------------------------------------
// Weight fp32 -> bf16 hi/lo split (grid-stride over float4)
// ---------------------------------------------------------------------------
__global__ __launch_bounds__(256) void convw(
    const float* __restrict__ w, __nv_bfloat16* __restrict__ hi,
    __nv_bfloat16* __restrict__ lo, int n)
{
    const int i = (blockIdx.x * 256 + threadIdx.x) * 4;
    if (i >= n) return;
    const float4 v = *(const float4*)(w + i);
    __nv_bfloat162 h01 = __floats2bfloat162_rn(v.x, v.y);
    __nv_bfloat162 h23 = __floats2bfloat162_rn(v.z, v.w);
    __nv_bfloat162 l01 = __floats2bfloat162_rn(v.x - __bfloat162float(h01.x),
                                               v.y - __bfloat162float(h01.y));
    __nv_bfloat162 l23 = __floats2bfloat162_rn(v.z - __bfloat162float(h23.x),
                                               v.w - __bfloat162float(h23.y));
    uint2 hv, lv;
    hv.x = *(uint32_t*)&h01; hv.y = *(uint32_t*)&h23;
    lv.x = *(uint32_t*)&l01; lv.y = *(uint32_t*)&l23;
    *(uint2*)(hi + i) = hv;
    *(uint2*)(lo + i) = lv;
}

// ---------------------------------------------------------------------------
// Pure-bf16 HMMA GEMM with cp.async 3-stage pipeline.
// C[M,N] = (Ahi+Alo)@(Bhi+Blo) + bias (+epilogue), 3-term split.
// Tile 128x128, BK=32, 8 warps (warp tile 32x64), 2 CTAs/SM target.
// Stage (32KB): Ahi[128][32] | Alo | Bhi[32][128] | Blo. 3 stages = 96KB.
// EPI: 0 = +bias -> fp32 C; 1 = +bias+res -> fp32 C; 2 = +bias+GELU -> bf16 hi/lo
// ---------------------------------------------------------------------------
#define BM 128
#define BN 128
#define BK 32
#define ST_BYTES 32768
#define HG2_SMEM (3 * ST_BYTES)

template <int EPI>
__global__ __launch_bounds__(256, 2) void hgemm2(
    const __nv_bfloat16* __restrict__ Ahi, const __nv_bfloat16* __restrict__ Alo,
    const __nv_bfloat16* __restrict__ Bhi, const __nv_bfloat16* __restrict__ Blo,
    const float* __restrict__ bias, const float* __restrict__ res,
    float* __restrict__ Cf, __nv_bfloat16* __restrict__ Chi,
    __nv_bfloat16* __restrict__ Clo, int M, int N, int K)
{
    extern __shared__ char smem[];
    const uint32_t sb = smem_u32(smem);
    const int tid  = threadIdx.x;
    const int lane = tid & 31;
    const int wid  = tid >> 5;
    const int m0   = blockIdx.y * BM;
    const int n0   = blockIdx.x * BN;

    // prefetch mapping: A 128 rows x 64B, 2x16B per thread; B 32 rows x 256B
    const int ar  = tid >> 1;
    const int ae  = (tid & 1) * 16;                 // elem offset in row
    const int bkr = tid >> 3;
    const int bne = (tid & 7) * 16;
    const uint32_t sA0 = swA(ar * 64 + ae * 2);
    const uint32_t sA1 = swA(ar * 64 + ae * 2 + 16);
    const uint32_t sB0 = swB(bkr * 256 + bne * 2);
    const uint32_t sB1 = swB(bkr * 256 + bne * 2 + 16);
    const size_t aoff = (size_t)(m0 + ar) * K + ae;

    auto PRE = [&](int c, int s) {
        const uint32_t st = sb + s * ST_BYTES;
        const __nv_bfloat16* ah = Ahi + aoff + c * BK;
        const __nv_bfloat16* al = Alo + aoff + c * BK;
        const size_t boff = (size_t)(c * BK + bkr) * N + n0 + bne;
        const __nv_bfloat16* bh = Bhi + boff;
        const __nv_bfloat16* bl = Blo + boff;
        cpasync16(st + sA0, ah);
        cpasync16(st + sA1, ah + 8);
        cpasync16(st + 8192 + sA0, al);
        cpasync16(st + 8192 + sA1, al + 8);
        cpasync16(st + 16384 + sB0, bh);
        cpasync16(st + 16384 + sB1, bh + 8);
        cpasync16(st + 24576 + sB0, bl);
        cpasync16(st + 24576 + sB1, bl + 8);
    };

    // per-warp compute mapping
    const int wm  = (wid & 3) * 32;
    const int wn  = (wid >> 2) * 64;
    const int a_r = lane & 15;
    const int a_k = (lane >> 4) * 8;
    const int b_k = lane & 15;
    const int b_n = (lane >> 4) * 8;

    float acc[2][8][4];
    #pragma unroll
    for (int i = 0; i < 2; i++)
        #pragma unroll
        for (int j = 0; j < 8; j++)
            #pragma unroll
            for (int q = 0; q < 4; q++) acc[i][j][q] = 0.f;

    auto COMPUTE = [&](int s) {
        const uint32_t AhiS = sb + s * ST_BYTES;
        const uint32_t AloS = AhiS + 8192;
        const uint32_t BhiS = AhiS + 16384;
        const uint32_t BloS = AhiS + 24576;
        #pragma unroll
        for (int ks = 0; ks < 2; ks++) {
            uint32_t ah[2][4], al[2][4];
            #pragma unroll
            for (int mt = 0; mt < 2; mt++) {
                const uint32_t off = swA((wm + mt * 16 + a_r) * 64 + (ks * 16 + a_k) * 2);
                ldsm4(ah[mt], AhiS + off);
                ldsm4(al[mt], AloS + off);
            }
            #pragma unroll
            for (int ng = 0; ng < 4; ng++) {
                uint32_t bh[4], bl[4];
                const uint32_t off = swB((ks * 16 + b_k) * 256 + (wn + ng * 16 + b_n) * 2);
                ldsm4t(bh, BhiS + off);
                ldsm4t(bl, BloS + off);
                #pragma unroll
                for (int mt = 0; mt < 2; mt++) {
                    #pragma unroll
                    for (int hf = 0; hf < 2; hf++) {
                        float* cc = acc[mt][ng * 2 + hf];
                        mma16816(cc, ah[mt], bh[hf * 2], bh[hf * 2 + 1]);
                        mma16816(cc, ah[mt], bl[hf * 2], bl[hf * 2 + 1]);
                        mma16816(cc, al[mt], bh[hf * 2], bh[hf * 2 + 1]);
                    }
                }
            }
        }
    };

    PRE(0, 0); CP_COMMIT();
    PRE(1, 1); CP_COMMIT();
    const int NC = K / BK;
    #pragma unroll 1
    for (int c = 0; c < NC; c++) {
        const int s = c - (c / 3) * 3;
        CP_WAIT1();
        __syncthreads();
        COMPUTE(s);
        if (c + 2 < NC) {
            const int s2 = (c + 2) - ((c + 2) / 3) * 3;
            PRE(c + 2, s2);
        }
        CP_COMMIT();
    }

    // ---- epilogue ----
    #pragma unroll
    for (int mt = 0; mt < 2; mt++) {
        #pragma unroll
        for (int nt = 0; nt < 8; nt++) {
            const int r0 = m0 + wm + mt * 16 + (lane >> 2);
            const int cc = n0 + wn + nt * 8 + (lane & 3) * 2;
            const float bx = bias[cc], by = bias[cc + 1];
            #pragma unroll
            for (int half = 0; half < 2; half++) {
                const int r = r0 + half * 8;
                float vx = acc[mt][nt][half * 2 + 0] + bx;
                float vy = acc[mt][nt][half * 2 + 1] + by;
                if (EPI == 2) {
                    float t = tanhf(0.7978845608028654f * (vx + 0.044715f * vx * vx * vx));
                    vx = 0.5f * vx * (1.0f + t);
                    t = tanhf(0.7978845608028654f * (vy + 0.044715f * vy * vy * vy));
                    vy = 0.5f * vy * (1.0f + t);
                    __nv_bfloat162 hh = __floats2bfloat162_rn(vx, vy);
                    __nv_bfloat162 ll = __floats2bfloat162_rn(
                        vx - __bfloat162float(hh.x), vy - __bfloat162float(hh.y));
                    *(__nv_bfloat162*)(Chi + (size_t)r * N + cc) = hh;
                    *(__nv_bfloat162*)(Clo + (size_t)r * N + cc) = ll;
                } else {
                    if (EPI == 1) {
                        const float2 rv = *(const float2*)(res + (size_t)r * N + cc);
                        vx += rv.x; vy += rv.y;
                    }
                    float2 w; w.x = vx; w.y = vy;
                    *(float2*)(Cf + (size_t)r * N + cc) = w;
                }
            }
        }
    }
}

// ---------------------------------------------------------------------------
// Tensor-core flash attention (R6 design); epilogue now emits bf16 hi/lo.
// ---------------------------------------------------------------------------
#define QT 128
#define KT 64
#define ATT_SMEM (32768 + 2 * 32768)

__global__ __launch_bounds__(256) void attn_mma()
{
    extern __shared__ char smem[];
    const uint32_t sb = smem_u32(smem);
    const int tid  = threadIdx.x;
    const int lane = tid & 31;
    const int wid  = tid >> 5;
    const int h    = blockIdx.y;
    const int bb   = blockIdx.z;
    const int q0   = blockIdx.x * QT;
    const float* qkv = g_qkv;

    {
        const int row = tid >> 1;
        const int ch  = (tid & 1) * 32;
        const float* qp = qkv + (size_t)(bb * SEQ + q0 + row) * 3072 + h * 64 + ch;
        char* Qh = smem;
        char* Ql = smem + 16384;
        #pragma unroll
        for (int i = 0; i < 8; i++) {
            const float4 v = *(const float4*)(qp + i * 4);
            __nv_bfloat162 h01 = __floats2bfloat162_rn(v.x, v.y);
            __nv_bfloat162 h23 = __floats2bfloat162_rn(v.z, v.w);
            __nv_bfloat162 l01 = __floats2bfloat162_rn(v.x - __bfloat162float(h01.x),
                                                       v.y - __bfloat162float(h01.y));
            __nv_bfloat162 l23 = __floats2bfloat162_rn(v.z - __bfloat162float(h23.x),
                                                       v.w - __bfloat162float(h23.y));
            const uint32_t so = sw128(row * 128 + (ch + i * 4) * 2);
            uint2 hv, lv;
            hv.x = *(uint32_t*)&h01; hv.y = *(uint32_t*)&h23;
            lv.x = *(uint32_t*)&l01; lv.y = *(uint32_t*)&l23;
            *(uint2*)(Qh + so) = hv;
            *(uint2*)(Ql + so) = lv;
        }
    }

    const int kr = tid >> 2;
    const int kc = (tid & 3) * 16;
    float4 kv4[8];
    auto LOADKV = [&](int c) {
        const size_t base = (size_t)(bb * SEQ + c * KT + kr) * 3072 + h * 64 + kc;
        #pragma unroll
        for (int i = 0; i < 4; i++)
            kv4[i] = *(const float4*)(qkv + base + 1024 + i * 4);
        #pragma unroll
        for (int i = 0; i < 4; i++)
            kv4[4 + i] = *(const float4*)(qkv + base + 2048 + i * 4);
    };
    auto STOREKV = [&](int s) {
        char* st = smem + 32768 + s * 32768;
        #pragma unroll
        for (int i = 0; i < 8; i++) {
            const float4 v = kv4[i];
            __nv_bfloat162 h01 = __floats2bfloat162_rn(v.x, v.y);
            __nv_bfloat162 h23 = __floats2bfloat162_rn(v.z, v.w);
            __nv_bfloat162 l01 = __floats2bfloat162_rn(v.x - __bfloat162float(h01.x),
                                                       v.y - __bfloat162float(h01.y));
            __nv_bfloat162 l23 = __floats2bfloat162_rn(v.z - __bfloat162float(h23.x),
                                                       v.w - __bfloat162float(h23.y));
            const uint32_t so = sw128(kr * 128 + (kc + (i & 3) * 4) * 2);
            char* hb = st + ((i < 4) ? 0 : 16384);
            uint2 hv, lv;
            hv.x = *(uint32_t*)&h01; hv.y = *(uint32_t*)&h23;
            lv.x = *(uint32_t*)&l01; lv.y = *(uint32_t*)&l23;
            *(uint2*)(hb + so)        = hv;
            *(uint2*)(hb + 8192 + so) = lv;
        }
    };

    LOADKV(0); STOREKV(0);
    __syncthreads();

    const int wm = wid * 16;
    uint32_t qh[4][4], ql[4][4];
    {
        const uint32_t Qhb = sb, Qlb = sb + 16384;
        #pragma unroll
        for (int ks = 0; ks < 4; ks++) {
            const uint32_t off =
                sw128((wm + (lane & 15)) * 128 + (ks * 16 + (lane >> 4) * 8) * 2);
            ldsm4(qh[ks], Qhb + off);
            ldsm4(ql[ks], Qlb + off);
        }
    }

    float oacc[8][4];
    #pragma unroll
    for (int j = 0; j < 8; j++)
        #pragma unroll
        for (int q = 0; q < 4; q++) oacc[j][q] = 0.f;
    float m0 = -1e30f, m1 = -1e30f, l0 = 0.f, l1 = 0.f;

    const int k_rowadd = ((lane >> 4) & 1) * 8;
    const int k_koff   = ((lane >> 3) & 1) * 8;
    const int k_r8     = lane & 7;

    const int NCH = SEQ / KT;
    #pragma unroll 1
    for (int c = 0; c < NCH; c++) {
        const int s = c & 1;
        if (c + 1 < NCH) LOADKV(c + 1);

        const uint32_t st  = sb + 32768 + s * 32768;
        const uint32_t Khb = st, Klb = st + 8192, Vhb = st + 16384, Vlb = st + 24576;

        float sacc[8][4];
        #pragma unroll
        for (int j = 0; j < 8; j++)
            #pragma unroll
            for (int q = 0; q < 4; q++) sacc[j][q] = 0.f;

        #pragma unroll
        for (int ks = 0; ks < 4; ks++) {
            #pragma unroll
            for (int j = 0; j < 4; j++) {
                const uint32_t off = sw128((j * 16 + k_r8 + k_rowadd) * 128 +
                                           (ks * 16 + k_koff) * 2);
                uint32_t kb[4], kl[4];
                ldsm4(kb, Khb + off);
                ldsm4(kl, Klb + off);
                #pragma unroll
                for (int t2 = 0; t2 < 2; t2++) {
                    float* cc = sacc[j * 2 + t2];
                    mma16816(cc, qh[ks], kb[t2 * 2], kb[t2 * 2 + 1]);
                    mma16816(cc, qh[ks], kl[t2 * 2], kl[t2 * 2 + 1]);
                    mma16816(cc, ql[ks], kb[t2 * 2], kb[t2 * 2 + 1]);
                }
            }
        }

        float vm0 = -1e30f, vm1 = -1e30f;
        #pragma unroll
        for (int j = 0; j < 8; j++) {
            vm0 = fmaxf(vm0, fmaxf(sacc[j][0], sacc[j][1]));
            vm1 = fmaxf(vm1, fmaxf(sacc[j][2], sacc[j][3]));
        }
        vm0 = fmaxf(vm0, __shfl_xor_sync(0xffffffffu, vm0, 1));
        vm0 = fmaxf(vm0, __shfl_xor_sync(0xffffffffu, vm0, 2));
        vm1 = fmaxf(vm1, __shfl_xor_sync(0xffffffffu, vm1, 1));
        vm1 = fmaxf(vm1, __shfl_xor_sync(0xffffffffu, vm1, 2));
        vm0 *= 0.125f; vm1 *= 0.125f;

        const float mn0 = fmaxf(m0, vm0), mn1 = fmaxf(m1, vm1);
        const float c0 = __expf(m0 - mn0), c1 = __expf(m1 - mn1);
        m0 = mn0; m1 = mn1;
        l0 *= c0;  l1 *= c1;
        #pragma unroll
        for (int j = 0; j < 8; j++) {
            oacc[j][0] *= c0; oacc[j][1] *= c0;
            oacc[j][2] *= c1; oacc[j][3] *= c1;
        }
        #pragma unroll
        for (int j = 0; j < 8; j++) {
            sacc[j][0] = __expf(fmaf(sacc[j][0], 0.125f, -mn0));
            sacc[j][1] = __expf(fmaf(sacc[j][1], 0.125f, -mn0));
            sacc[j][2] = __expf(fmaf(sacc[j][2], 0.125f, -mn1));
            sacc[j][3] = __expf(fmaf(sacc[j][3], 0.125f, -mn1));
            l0 += sacc[j][0] + sacc[j][1];
            l1 += sacc[j][2] + sacc[j][3];
        }

        #pragma unroll
        for (int kk = 0; kk < 4; kk++) {
            const float* p0 = sacc[kk * 2];
            const float* p1 = sacc[kk * 2 + 1];
            uint32_t pa[4], pl[4];
            {
                __nv_bfloat162 h0 = __floats2bfloat162_rn(p0[0], p0[1]);
                __nv_bfloat162 h1 = __floats2bfloat162_rn(p0[2], p0[3]);
                __nv_bfloat162 h2 = __floats2bfloat162_rn(p1[0], p1[1]);
                __nv_bfloat162 h3 = __floats2bfloat162_rn(p1[2], p1[3]);
                __nv_bfloat162 e0 = __floats2bfloat162_rn(p0[0] - __bfloat162float(h0.x),
                                                          p0[1] - __bfloat162float(h0.y));
                __nv_bfloat162 e1 = __floats2bfloat162_rn(p0[2] - __bfloat162float(h1.x),
                                                          p0[3] - __bfloat162float(h1.y));
                __nv_bfloat162 e2 = __floats2bfloat162_rn(p1[0] - __bfloat162float(h2.x),
                                                          p1[1] - __bfloat162float(h2.y));
                __nv_bfloat162 e3 = __floats2bfloat162_rn(p1[2] - __bfloat162float(h3.x),
                                                          p1[3] - __bfloat162float(h3.y));
                pa[0] = *(uint32_t*)&h0; pa[1] = *(uint32_t*)&h1;
                pa[2] = *(uint32_t*)&h2; pa[3] = *(uint32_t*)&h3;
                pl[0] = *(uint32_t*)&e0; pl[1] = *(uint32_t*)&e1;
                pl[2] = *(uint32_t*)&e2; pl[3] = *(uint32_t*)&e3;
            }
            #pragma unroll
            for (int j = 0; j < 4; j++) {
                const uint32_t off = sw128((kk * 16 + (lane & 15)) * 128 +
                                           (j * 16 + (lane >> 4) * 8) * 2);
                uint32_t vb[4], vl[4];
                ldsm4t(vb, Vhb + off);
                ldsm4t(vl, Vlb + off);
                #pragma unroll
                for (int t2 = 0; t2 < 2; t2++) {
                    float* cc = oacc[j * 2 + t2];
                    mma16816(cc, pa, vb[t2 * 2], vb[t2 * 2 + 1]);
                    mma16816(cc, pa, vl[t2 * 2], vl[t2 * 2 + 1]);
                    mma16816(cc, pl, vb[t2 * 2], vb[t2 * 2 + 1]);
                }
            }
        }

        if (c + 1 < NCH) STOREKV(s ^ 1);
        __syncthreads();
    }

    l0 += __shfl_xor_sync(0xffffffffu, l0, 1);
    l0 += __shfl_xor_sync(0xffffffffu, l0, 2);
    l1 += __shfl_xor_sync(0xffffffffu, l1, 1);
    l1 += __shfl_xor_sync(0xffffffffu, l1, 2);
    const float i0 = 1.f / l0, i1 = 1.f / l1;

    const int r0g = bb * SEQ + q0 + wm + (lane >> 2);
    const int cb  = h * 64 + (lane & 3) * 2;
    #pragma unroll
    for (int j = 0; j < 8; j++) {
        const float v0x = oacc[j][0] * i0, v0y = oacc[j][1] * i0;
        const float v1x = oacc[j][2] * i1, v1y = oacc[j][3] * i1;
        __nv_bfloat162 h0 = __floats2bfloat162_rn(v0x, v0y);
        __nv_bfloat162 e0 = __floats2bfloat162_rn(v0x - __bfloat162float(h0.x),
                                                  v0y - __bfloat162float(h0.y));
        __nv_bfloat162 h1 = __floats2bfloat162_rn(v1x, v1y);
        __nv_bfloat162 e1 = __floats2bfloat162_rn(v1x - __bfloat162float(h1.x),
                                                  v1y - __bfloat162float(h1.y));
        *(__nv_bfloat162*)(g_attn_hi + (size_t)r0g * HID + cb + j * 8)       = h0;
        *(__nv_bfloat162*)(g_attn_lo + (size_t)r0g * HID + cb + j * 8)       = e0;
        *(__nv_bfloat162*)(g_attn_hi + (size_t)(r0g + 8) * HID + cb + j * 8) = h1;
        *(__nv_bfloat162*)(g_attn_lo + (size_t)(r0g + 8) * HID + cb + j * 8) = e1;
    }
}

// ---------------------------------------------------------------------------
// LayerNorm: fp32 in -> bf16 hi/lo out
// ---------------------------------------------------------------------------
__global__ __launch_bounds__(256) void ln_kernel(
    const float* __restrict__ X, const float* __restrict__ g,
    const float* __restrict__ b, __nv_bfloat16* __restrict__ Yhi,
    __nv_bfloat16* __restrict__ Ylo)
{
    __shared__ float red[16];
    const long row = blockIdx.x;
    const int  t   = threadIdx.x;

    float4 v = ((const float4*)(X + row * HID))[t];
    float s  = v.x + v.y + v.z + v.w;
    float sq = v.x*v.x + v.y*v.y + v.z*v.z + v.w*v.w;

    #pragma unroll
    for (int o = 16; o > 0; o >>= 1) {
        s  += __shfl_xor_sync(0xffffffffu, s,  o);
        sq += __shfl_xor_sync(0xffffffffu, sq, o);
    }
    const int warp = t >> 5, lane = t & 31;
    if (lane == 0) { red[warp] = s; red[warp + 8] = sq; }
    __syncthreads();
    if (t < 32) {
        float ss = (lane < 8) ? red[lane]     : 0.f;
        float qq = (lane < 8) ? red[lane + 8] : 0.f;
        #pragma unroll
        for (int o = 4; o > 0; o >>= 1) {
            ss += __shfl_xor_sync(0xffffffffu, ss, o);
            qq += __shfl_xor_sync(0xffffffffu, qq, o);
        }
        if (lane == 0) { red[0] = ss; red[1] = qq; }
    }
    __syncthreads();

    const float mu   = red[0] * (1.f / HID);
    const float var  = red[1] * (1.f / HID) - mu * mu;
    const float rstd = rsqrtf(var + LN_EPS);

    const float4 gv = ((const float4*)g)[t];
    const float4 bv = ((const float4*)b)[t];
    float4 y;
    y.x = (v.x - mu) * rstd * gv.x + bv.x;
    y.y = (v.y - mu) * rstd * gv.y + bv.y;
    y.z = (v.z - mu) * rstd * gv.z + bv.z;
    y.w = (v.w - mu) * rstd * gv.w + bv.w;

    __nv_bfloat162 h01 = __floats2bfloat162_rn(y.x, y.y);
    __nv_bfloat162 h23 = __floats2bfloat162_rn(y.z, y.w);
    __nv_bfloat162 l01 = __floats2bfloat162_rn(y.x - __bfloat162float(h01.x),
                                               y.y - __bfloat162float(h01.y));
    __nv_bfloat162 l23 = __floats2bfloat162_rn(y.z - __bfloat162float(h23.x),
                                               y.w - __bfloat162float(h23.y));
    uint2 hv, lv;
    hv.x = *(uint32_t*)&h01; hv.y = *(uint32_t*)&h23;
    lv.x = *(uint32_t*)&l01; lv.y = *(uint32_t*)&l23;
    *(uint2*)(Yhi + row * HID + t * 4) = hv;
    *(uint2*)(Ylo + row * HID + t * 4) = lv;
}

// ---------------------------------------------------------------------------
// Launch
// ---------------------------------------------------------------------------
extern "C" void kernel_launch(void* const* d_in, const int* in_sizes, int n_in,
                              void* d_out, int out_size)
{
    const float* x     = (const float*)d_in[0];
    const float* ln1_g = (const float*)d_in[1];
    const float* ln1_b = (const float*)d_in[2];
    const float* qkv_w = (const float*)d_in[3];
    const float* qkv_b = (const float*)d_in[4];
    const float* out_w = (const float*)d_in[5];
    const float* out_b = (const float*)d_in[6];
    const float* ln2_g = (const float*)d_in[7];
    const float* ln2_b = (const float*)d_in[8];
    const float* w1    = (const float*)d_in[9];
    const float* b1    = (const float*)d_in[10];
    const float* w2    = (const float*)d_in[11];
    const float* b2    = (const float*)d_in[12];
    float* out = (float*)d_out;

    // device symbol addresses (host-side lookups; not stream ops)
    float *p_qkv, *p_x1;
    __nv_bfloat16 *p_h_hi, *p_h_lo, *p_attn_hi, *p_attn_lo, *p_mid_hi, *p_mid_lo;
    __nv_bfloat16 *p_wqkv_hi, *p_wqkv_lo, *p_wout_hi, *p_wout_lo;
    __nv_bfloat16 *p_w1_hi, *p_w1_lo, *p_w2_hi, *p_w2_lo;
    cudaGetSymbolAddress((void**)&p_qkv,     g_qkv);
    cudaGetSymbolAddress((void**)&p_x1,      g_x1);
    cudaGetSymbolAddress((void**)&p_h_hi,    g_h_hi);
    cudaGetSymbolAddress((void**)&p_h_lo,    g_h_lo);
    cudaGetSymbolAddress((void**)&p_attn_hi, g_attn_hi);
    cudaGetSymbolAddress((void**)&p_attn_lo, g_attn_lo);
    cudaGetSymbolAddress((void**)&p_mid_hi,  g_mid_hi);
    cudaGetSymbolAddress((void**)&p_mid_lo,  g_mid_lo);
    cudaGetSymbolAddress((void**)&p_wqkv_hi, g_wqkv_hi);
    cudaGetSymbolAddress((void**)&p_wqkv_lo, g_wqkv_lo);
    cudaGetSymbolAddress((void**)&p_wout_hi, g_wout_hi);
    cudaGetSymbolAddress((void**)&p_wout_lo, g_wout_lo);
    cudaGetSymbolAddress((void**)&p_w1_hi,   g_w1_hi);
    cudaGetSymbolAddress((void**)&p_w1_lo,   g_w1_lo);
    cudaGetSymbolAddress((void**)&p_w2_hi,   g_w2_hi);
    cudaGetSymbolAddress((void**)&p_w2_lo,   g_w2_lo);

    cudaFuncSetAttribute((const void*)hgemm2<0>,
                         cudaFuncAttributeMaxDynamicSharedMemorySize, HG2_SMEM);
    cudaFuncSetAttribute((const void*)hgemm2<1>,
                         cudaFuncAttributeMaxDynamicSharedMemorySize, HG2_SMEM);
    cudaFuncSetAttribute((const void*)hgemm2<2>,
                         cudaFuncAttributeMaxDynamicSharedMemorySize, HG2_SMEM);
    cudaFuncSetAttribute((const void*)attn_mma,
                         cudaFuncAttributeMaxDynamicSharedMemorySize, ATT_SMEM);

    // 0) weight splits (cheap; every launch for determinism)
    convw<<<(HID * 3 * HID / 4 + 255) / 256, 256>>>(qkv_w, p_wqkv_hi, p_wqkv_lo, HID * 3 * HID);
    convw<<<(HID * HID / 4 + 255) / 256, 256>>>(out_w, p_wout_hi, p_wout_lo, HID * HID);
    convw<<<(HID * INTER / 4 + 255) / 256, 256>>>(w1, p_w1_hi, p_w1_lo, HID * INTER);
    convw<<<(INTER * HID / 4 + 255) / 256, 256>>>(w2, p_w2_hi, p_w2_lo, INTER * HID);

    // 1) LN1: x -> h hi/lo
    ln_kernel<<<NTOK, 256>>>(x, ln1_g, ln1_b, p_h_hi, p_h_lo);

    // 2) QKV: h @ wqkv + qkv_b -> fp32 qkv
    hgemm2<0><<<dim3((3 * HID) / BN, NTOK / BM), 256, HG2_SMEM>>>(
        p_h_hi, p_h_lo, p_wqkv_hi, p_wqkv_lo, qkv_b, nullptr,
        p_qkv, nullptr, nullptr, NTOK, 3 * HID, HID);

    // 3) attention: qkv -> attn hi/lo
    attn_mma<<<dim3(SEQ / QT, NHEAD, BATCH), 256, ATT_SMEM>>>();

    // 4) x1 = x + attn @ wout + out_b
    hgemm2<1><<<dim3(HID / BN, NTOK / BM), 256, HG2_SMEM>>>(
        p_attn_hi, p_attn_lo, p_wout_hi, p_wout_lo, out_b, x,
        p_x1, nullptr, nullptr, NTOK, HID, HID);

    // 5) LN2: x1 -> h hi/lo
    ln_kernel<<<NTOK, 256>>>(p_x1, ln2_g, ln2_b, p_h_hi, p_h_lo);

    // 6) mid = gelu(h @ w1 + b1) -> mid hi/lo
    hgemm2<2><<<dim3(INTER / BN, NTOK / BM), 256, HG2_SMEM>>>(
        p_h_hi, p_h_lo, p_w1_hi, p_w1_lo, b1, nullptr,
        nullptr, p_mid_hi, p_mid_lo, NTOK, INTER, HID);

    // 7) out = x1 + mid @ w2 + b2
    hgemm2<1><<<dim3(HID / BN, NTOK / BM), 256, HG2_SMEM>>>(
        p_mid_hi, p_mid_lo, p_w2_hi, p_w2_lo, b2, p_x1,
        out, nullptr, nullptr, NTOK, HID, INTER);
}

// round 8
// speedup vs baseline: 5.8387x; 1.0845x over previous
#include <cuda_runtime.h>
#include <cuda_bf16.h>
#include <math.h>
#include <stdint.h>

// ---------------------------------------------------------------------------
// Problem constants
// ---------------------------------------------------------------------------
#define HID   1024
#define NHEAD 16
#define HD    64
#define INTER 4096
#define BATCH 4
#define SEQ   2048
#define NTOK  (BATCH * SEQ)          // 8192
#define LN_EPS 1e-5f

// ---------------------------------------------------------------------------
// Scratch (static device globals; no runtime allocation)
// ---------------------------------------------------------------------------
__device__ float g_x1 [NTOK * HID];                     // residual-1 (fp32)
__device__ __nv_bfloat16 g_qkv_hi[NTOK * 3 * HID];      // QKV hi/lo (bf16)
__device__ __nv_bfloat16 g_qkv_lo[NTOK * 3 * HID];
__device__ __nv_bfloat16 g_h_hi  [NTOK * HID];          // LN out hi/lo
__device__ __nv_bfloat16 g_h_lo  [NTOK * HID];
__device__ __nv_bfloat16 g_attn_hi[NTOK * HID];         // attention out hi/lo
__device__ __nv_bfloat16 g_attn_lo[NTOK * HID];
__device__ __nv_bfloat16 g_mid_hi[NTOK * INTER];        // GELU(MLP1) hi/lo
__device__ __nv_bfloat16 g_mid_lo[NTOK * INTER];
__device__ __nv_bfloat16 g_wqkv_hi[HID * 3 * HID];      // split weights
__device__ __nv_bfloat16 g_wqkv_lo[HID * 3 * HID];
__device__ __nv_bfloat16 g_wout_hi[HID * HID];
__device__ __nv_bfloat16 g_wout_lo[HID * HID];
__device__ __nv_bfloat16 g_w1_hi  [HID * INTER];
__device__ __nv_bfloat16 g_w1_lo  [HID * INTER];
__device__ __nv_bfloat16 g_w2_hi  [INTER * HID];
__device__ __nv_bfloat16 g_w2_lo  [INTER * HID];

// ---------------------------------------------------------------------------
// PTX helpers (sm_80-baseline features only; compile for compute_103)
// ---------------------------------------------------------------------------
__device__ __forceinline__ uint32_t smem_u32(const void* p) {
    uint32_t a;
    asm("{ .reg .u64 t; cvta.to.shared.u64 t, %1; cvt.u32.u64 %0, t; }"
        : "=r"(a) : "l"(p));
    return a;
}
__device__ __forceinline__ void ldsm4(uint32_t* r, uint32_t addr) {
    asm volatile("ldmatrix.sync.aligned.m8n8.x4.shared.b16 {%0,%1,%2,%3}, [%4];"
                 : "=r"(r[0]), "=r"(r[1]), "=r"(r[2]), "=r"(r[3]) : "r"(addr));
}
__device__ __forceinline__ void ldsm4t(uint32_t* r, uint32_t addr) {
    asm volatile("ldmatrix.sync.aligned.m8n8.x4.trans.shared.b16 {%0,%1,%2,%3}, [%4];"
                 : "=r"(r[0]), "=r"(r[1]), "=r"(r[2]), "=r"(r[3]) : "r"(addr));
}
__device__ __forceinline__ void mma16816(float* c, const uint32_t* a,
                                         uint32_t b0, uint32_t b1) {
    asm volatile(
        "mma.sync.aligned.m16n8k16.row.col.f32.bf16.bf16.f32 "
        "{%0,%1,%2,%3}, {%4,%5,%6,%7}, {%8,%9}, {%0,%1,%2,%3};"
        : "+f"(c[0]), "+f"(c[1]), "+f"(c[2]), "+f"(c[3])
        : "r"(a[0]), "r"(a[1]), "r"(a[2]), "r"(a[3]), "r"(b0), "r"(b1));
}
__device__ __forceinline__ void cpasync16(uint32_t s, const void* g) {
    asm volatile("cp.async.cg.shared.global [%0], [%1], 16;" :: "r"(s), "l"(g));
}
#define CP_COMMIT() asm volatile("cp.async.commit_group;" ::: "memory")
#define CP_WAIT1()  asm volatile("cp.async.wait_group 1;"  ::: "memory")
#define CP_WAIT0()  asm volatile("cp.async.wait_group 0;"  ::: "memory")

__device__ __forceinline__ uint32_t swA(uint32_t off) { return off ^ ((off >> 2) & 0x30); }
__device__ __forceinline__ uint32_t swB(uint32_t off) { return off ^ ((off >> 4) & 0x70); }
__device__ __forceinline__ uint32_t sw128(uint32_t off) { return off ^ ((off >> 3) & 0x70); }

// ---------------------------------------------------------------------------
// Weight fp32 -> bf16 hi/lo split
// ---------------------------------------------------------------------------
__global__ __launch_bounds__(256) void convw(
    const float* __restrict__ w, __nv_bfloat16* __restrict__ hi,
    __nv_bfloat16* __restrict__ lo, int n)
{
    const int i = (blockIdx.x * 256 + threadIdx.x) * 4;
    if (i >= n) return;
    const float4 v = *(const float4*)(w + i);
    __nv_bfloat162 h01 = __floats2bfloat162_rn(v.x, v.y);
    __nv_bfloat162 h23 = __floats2bfloat162_rn(v.z, v.w);
    __nv_bfloat162 l01 = __floats2bfloat162_rn(v.x - __bfloat162float(h01.x),
                                               v.y - __bfloat162float(h01.y));
    __nv_bfloat162 l23 = __floats2bfloat162_rn(v.z - __bfloat162float(h23.x),
                                               v.w - __bfloat162float(h23.y));
    uint2 hv, lv;
    hv.x = *(uint32_t*)&h01; hv.y = *(uint32_t*)&h23;
    lv.x = *(uint32_t*)&l01; lv.y = *(uint32_t*)&l23;
    *(uint2*)(hi + i) = hv;
    *(uint2*)(lo + i) = lv;
}

// ---------------------------------------------------------------------------
// Pure-bf16 HMMA GEMM with cp.async 3-stage pipeline (R7, + EPI=3).
// EPI: 0 = +bias -> fp32; 1 = +bias+res -> fp32;
//      2 = +bias+GELU -> bf16 hi/lo; 3 = +bias -> bf16 hi/lo
// ---------------------------------------------------------------------------
#define BM 128
#define BN 128
#define BK 32
#define ST_BYTES 32768
#define HG2_SMEM (3 * ST_BYTES)

template <int EPI>
__global__ __launch_bounds__(256, 2) void hgemm2(
    const __nv_bfloat16* __restrict__ Ahi, const __nv_bfloat16* __restrict__ Alo,
    const __nv_bfloat16* __restrict__ Bhi, const __nv_bfloat16* __restrict__ Blo,
    const float* __restrict__ bias, const float* __restrict__ res,
    float* __restrict__ Cf, __nv_bfloat16* __restrict__ Chi,
    __nv_bfloat16* __restrict__ Clo, int M, int N, int K)
{
    extern __shared__ char smem[];
    const uint32_t sb = smem_u32(smem);
    const int tid  = threadIdx.x;
    const int lane = tid & 31;
    const int wid  = tid >> 5;
    const int m0   = blockIdx.y * BM;
    const int n0   = blockIdx.x * BN;

    const int ar  = tid >> 1;
    const int ae  = (tid & 1) * 16;
    const int bkr = tid >> 3;
    const int bne = (tid & 7) * 16;
    const uint32_t sA0 = swA(ar * 64 + ae * 2);
    const uint32_t sA1 = swA(ar * 64 + ae * 2 + 16);
    const uint32_t sB0 = swB(bkr * 256 + bne * 2);
    const uint32_t sB1 = swB(bkr * 256 + bne * 2 + 16);
    const size_t aoff = (size_t)(m0 + ar) * K + ae;

    auto PRE = [&](int c, int s) {
        const uint32_t st = sb + s * ST_BYTES;
        const __nv_bfloat16* ah = Ahi + aoff + c * BK;
        const __nv_bfloat16* al = Alo + aoff + c * BK;
        const size_t boff = (size_t)(c * BK + bkr) * N + n0 + bne;
        const __nv_bfloat16* bh = Bhi + boff;
        const __nv_bfloat16* bl = Blo + boff;
        cpasync16(st + sA0, ah);
        cpasync16(st + sA1, ah + 8);
        cpasync16(st + 8192 + sA0, al);
        cpasync16(st + 8192 + sA1, al + 8);
        cpasync16(st + 16384 + sB0, bh);
        cpasync16(st + 16384 + sB1, bh + 8);
        cpasync16(st + 24576 + sB0, bl);
        cpasync16(st + 24576 + sB1, bl + 8);
    };

    const int wm  = (wid & 3) * 32;
    const int wn  = (wid >> 2) * 64;
    const int a_r = lane & 15;
    const int a_k = (lane >> 4) * 8;
    const int b_k = lane & 15;
    const int b_n = (lane >> 4) * 8;

    float acc[2][8][4];
    #pragma unroll
    for (int i = 0; i < 2; i++)
        #pragma unroll
        for (int j = 0; j < 8; j++)
            #pragma unroll
            for (int q = 0; q < 4; q++) acc[i][j][q] = 0.f;

    auto COMPUTE = [&](int s) {
        const uint32_t AhiS = sb + s * ST_BYTES;
        const uint32_t AloS = AhiS + 8192;
        const uint32_t BhiS = AhiS + 16384;
        const uint32_t BloS = AhiS + 24576;
        #pragma unroll
        for (int ks = 0; ks < 2; ks++) {
            uint32_t ah[2][4], al[2][4];
            #pragma unroll
            for (int mt = 0; mt < 2; mt++) {
                const uint32_t off = swA((wm + mt * 16 + a_r) * 64 + (ks * 16 + a_k) * 2);
                ldsm4(ah[mt], AhiS + off);
                ldsm4(al[mt], AloS + off);
            }
            #pragma unroll
            for (int ng = 0; ng < 4; ng++) {
                uint32_t bh[4], bl[4];
                const uint32_t off = swB((ks * 16 + b_k) * 256 + (wn + ng * 16 + b_n) * 2);
                ldsm4t(bh, BhiS + off);
                ldsm4t(bl, BloS + off);
                #pragma unroll
                for (int mt = 0; mt < 2; mt++) {
                    #pragma unroll
                    for (int hf = 0; hf < 2; hf++) {
                        float* cc = acc[mt][ng * 2 + hf];
                        mma16816(cc, ah[mt], bh[hf * 2], bh[hf * 2 + 1]);
                        mma16816(cc, ah[mt], bl[hf * 2], bl[hf * 2 + 1]);
                        mma16816(cc, al[mt], bh[hf * 2], bh[hf * 2 + 1]);
                    }
                }
            }
        }
    };

    PRE(0, 0); CP_COMMIT();
    PRE(1, 1); CP_COMMIT();
    const int NC = K / BK;
    #pragma unroll 1
    for (int c = 0; c < NC; c++) {
        const int s = c - (c / 3) * 3;
        CP_WAIT1();
        __syncthreads();
        COMPUTE(s);
        if (c + 2 < NC) {
            const int s2 = (c + 2) - ((c + 2) / 3) * 3;
            PRE(c + 2, s2);
        }
        CP_COMMIT();
    }

    #pragma unroll
    for (int mt = 0; mt < 2; mt++) {
        #pragma unroll
        for (int nt = 0; nt < 8; nt++) {
            const int r0 = m0 + wm + mt * 16 + (lane >> 2);
            const int cc = n0 + wn + nt * 8 + (lane & 3) * 2;
            const float bx = bias[cc], by = bias[cc + 1];
            #pragma unroll
            for (int half = 0; half < 2; half++) {
                const int r = r0 + half * 8;
                float vx = acc[mt][nt][half * 2 + 0] + bx;
                float vy = acc[mt][nt][half * 2 + 1] + by;
                if (EPI == 2) {
                    float t = tanhf(0.7978845608028654f * (vx + 0.044715f * vx * vx * vx));
                    vx = 0.5f * vx * (1.0f + t);
                    t = tanhf(0.7978845608028654f * (vy + 0.044715f * vy * vy * vy));
                    vy = 0.5f * vy * (1.0f + t);
                }
                if (EPI == 2 || EPI == 3) {
                    __nv_bfloat162 hh = __floats2bfloat162_rn(vx, vy);
                    __nv_bfloat162 ll = __floats2bfloat162_rn(
                        vx - __bfloat162float(hh.x), vy - __bfloat162float(hh.y));
                    *(__nv_bfloat162*)(Chi + (size_t)r * N + cc) = hh;
                    *(__nv_bfloat162*)(Clo + (size_t)r * N + cc) = ll;
                } else {
                    if (EPI == 1) {
                        const float2 rv = *(const float2*)(res + (size_t)r * N + cc);
                        vx += rv.x; vy += rv.y;
                    }
                    float2 w; w.x = vx; w.y = vy;
                    *(float2*)(Cf + (size_t)r * N + cc) = w;
                }
            }
        }
    }
}

// ---------------------------------------------------------------------------
// Tensor-core flash attention, cp.async edition.
// Consumes bf16 hi/lo QKV directly. One CTA = 128 q-rows x (head, batch);
// 8 warps (warp = m16 slab). KV chunks of 64, 2-stage cp.async pipeline.
// Smem: Qh 16K | Ql 16K | stage{0,1}: Kh 8K, Kl 8K, Vh 8K, Vl 8K => 96KB.
// Q fragments re-ldmatrix'd per chunk (frees regs -> 2 CTAs/SM).
// ---------------------------------------------------------------------------
#define QT 128
#define KT 64
#define ATT_SMEM (32768 + 2 * 32768)

__global__ __launch_bounds__(256, 2) void attn_mma()
{
    extern __shared__ char smem[];
    const uint32_t sb = smem_u32(smem);
    const int tid  = threadIdx.x;
    const int lane = tid & 31;
    const int wid  = tid >> 5;
    const int h    = blockIdx.y;
    const int bb   = blockIdx.z;
    const int q0   = blockIdx.x * QT;

    // ---- Q cp.async: 128 rows x 128B, hi+lo (32KB) ----
    {
        const int qr  = tid >> 1;
        const int qc0 = (tid & 1) * 32;                  // elem offset in row
        const size_t gq = (size_t)(bb * SEQ + q0 + qr) * 3072 + h * 64 + qc0;
        #pragma unroll
        for (int i = 0; i < 4; i++) {
            const uint32_t so = sw128(qr * 128 + (qc0 + i * 8) * 2);
            cpasync16(sb + so,         g_qkv_hi + gq + i * 8);
            cpasync16(sb + 16384 + so, g_qkv_lo + gq + i * 8);
        }
    }

    // ---- KV chunk prefetch (stage s): K rows then V rows, hi+lo (32KB) ----
    const int kr = tid >> 2;
    const int kc = (tid & 3) * 16;
    auto PRE = [&](int c, int s) {
        const uint32_t st = sb + 32768 + s * 32768;
        const size_t base = (size_t)(bb * SEQ + c * KT + kr) * 3072 + h * 64 + kc;
        const uint32_t so0 = sw128(kr * 128 + kc * 2);
        const uint32_t so1 = so0 ^ 16;                    // +8 elems within 32B pair
        // K (gmem col offset +1024), V (+2048)
        cpasync16(st + so0,          g_qkv_hi + base + 1024);
        cpasync16(st + so1,          g_qkv_hi + base + 1024 + 8);
        cpasync16(st + 8192 + so0,   g_qkv_lo + base + 1024);
        cpasync16(st + 8192 + so1,   g_qkv_lo + base + 1024 + 8);
        cpasync16(st + 16384 + so0,  g_qkv_hi + base + 2048);
        cpasync16(st + 16384 + so1,  g_qkv_hi + base + 2048 + 8);
        cpasync16(st + 24576 + so0,  g_qkv_lo + base + 2048);
        cpasync16(st + 24576 + so1,  g_qkv_lo + base + 2048 + 8);
    };

    PRE(0, 0); CP_COMMIT();      // group 0: Q + chunk0
    PRE(1, 1); CP_COMMIT();      // group 1: chunk1
    CP_WAIT1();                  // group 0 done
    __syncthreads();

    const int wm = wid * 16;

    float oacc[8][4];
    #pragma unroll
    for (int j = 0; j < 8; j++)
        #pragma unroll
        for (int q = 0; q < 4; q++) oacc[j][q] = 0.f;
    float m0 = -1e30f, m1 = -1e30f, l0 = 0.f, l1 = 0.f;

    const int k_rowadd = ((lane >> 4) & 1) * 8;
    const int k_koff   = ((lane >> 3) & 1) * 8;
    const int k_r8     = lane & 7;

    const int NCH = SEQ / KT;
    #pragma unroll 1
    for (int c = 0; c < NCH; c++) {
        const int s = c & 1;
        const uint32_t st  = sb + 32768 + s * 32768;
        const uint32_t Khb = st, Klb = st + 8192, Vhb = st + 16384, Vlb = st + 24576;

        // ---- S = Q @ K^T (3-term split) ----
        float sacc[8][4];
        #pragma unroll
        for (int j = 0; j < 8; j++)
            #pragma unroll
            for (int q = 0; q < 4; q++) sacc[j][q] = 0.f;

        #pragma unroll
        for (int ks = 0; ks < 4; ks++) {
            uint32_t qh[4], ql[4];
            const uint32_t qoff =
                sw128((wm + (lane & 15)) * 128 + (ks * 16 + (lane >> 4) * 8) * 2);
            ldsm4(qh, sb + qoff);
            ldsm4(ql, sb + 16384 + qoff);
            #pragma unroll
            for (int j = 0; j < 4; j++) {
                const uint32_t off = sw128((j * 16 + k_r8 + k_rowadd) * 128 +
                                           (ks * 16 + k_koff) * 2);
                uint32_t kb[4], kl[4];
                ldsm4(kb, Khb + off);
                ldsm4(kl, Klb + off);
                #pragma unroll
                for (int t2 = 0; t2 < 2; t2++) {
                    float* cc = sacc[j * 2 + t2];
                    mma16816(cc, qh, kb[t2 * 2], kb[t2 * 2 + 1]);
                    mma16816(cc, qh, kl[t2 * 2], kl[t2 * 2 + 1]);
                    mma16816(cc, ql, kb[t2 * 2], kb[t2 * 2 + 1]);
                }
            }
        }

        // ---- online softmax ----
        float vm0 = -1e30f, vm1 = -1e30f;
        #pragma unroll
        for (int j = 0; j < 8; j++) {
            vm0 = fmaxf(vm0, fmaxf(sacc[j][0], sacc[j][1]));
            vm1 = fmaxf(vm1, fmaxf(sacc[j][2], sacc[j][3]));
        }
        vm0 = fmaxf(vm0, __shfl_xor_sync(0xffffffffu, vm0, 1));
        vm0 = fmaxf(vm0, __shfl_xor_sync(0xffffffffu, vm0, 2));
        vm1 = fmaxf(vm1, __shfl_xor_sync(0xffffffffu, vm1, 1));
        vm1 = fmaxf(vm1, __shfl_xor_sync(0xffffffffu, vm1, 2));
        vm0 *= 0.125f; vm1 *= 0.125f;

        const float mn0 = fmaxf(m0, vm0), mn1 = fmaxf(m1, vm1);
        const float c0 = __expf(m0 - mn0), c1 = __expf(m1 - mn1);
        m0 = mn0; m1 = mn1;
        l0 *= c0;  l1 *= c1;
        #pragma unroll
        for (int j = 0; j < 8; j++) {
            oacc[j][0] *= c0; oacc[j][1] *= c0;
            oacc[j][2] *= c1; oacc[j][3] *= c1;
        }
        #pragma unroll
        for (int j = 0; j < 8; j++) {
            sacc[j][0] = __expf(fmaf(sacc[j][0], 0.125f, -mn0));
            sacc[j][1] = __expf(fmaf(sacc[j][1], 0.125f, -mn0));
            sacc[j][2] = __expf(fmaf(sacc[j][2], 0.125f, -mn1));
            sacc[j][3] = __expf(fmaf(sacc[j][3], 0.125f, -mn1));
            l0 += sacc[j][0] + sacc[j][1];
            l1 += sacc[j][2] + sacc[j][3];
        }

        // ---- O += P @ V (3-term split; P error term vs bf16(P)) ----
        #pragma unroll
        for (int kk = 0; kk < 4; kk++) {
            const float* p0 = sacc[kk * 2];
            const float* p1 = sacc[kk * 2 + 1];
            uint32_t pa[4], pl[4];
            {
                __nv_bfloat162 h0 = __floats2bfloat162_rn(p0[0], p0[1]);
                __nv_bfloat162 h1 = __floats2bfloat162_rn(p0[2], p0[3]);
                __nv_bfloat162 h2 = __floats2bfloat162_rn(p1[0], p1[1]);
                __nv_bfloat162 h3 = __floats2bfloat162_rn(p1[2], p1[3]);
                __nv_bfloat162 e0 = __floats2bfloat162_rn(p0[0] - __bfloat162float(h0.x),
                                                          p0[1] - __bfloat162float(h0.y));
                __nv_bfloat162 e1 = __floats2bfloat162_rn(p0[2] - __bfloat162float(h1.x),
                                                          p0[3] - __bfloat162float(h1.y));
                __nv_bfloat162 e2 = __floats2bfloat162_rn(p1[0] - __bfloat162float(h2.x),
                                                          p1[1] - __bfloat162float(h2.y));
                __nv_bfloat162 e3 = __floats2bfloat162_rn(p1[2] - __bfloat162float(h3.x),
                                                          p1[3] - __bfloat162float(h3.y));
                pa[0] = *(uint32_t*)&h0; pa[1] = *(uint32_t*)&h1;
                pa[2] = *(uint32_t*)&h2; pa[3] = *(uint32_t*)&h3;
                pl[0] = *(uint32_t*)&e0; pl[1] = *(uint32_t*)&e1;
                pl[2] = *(uint32_t*)&e2; pl[3] = *(uint32_t*)&e3;
            }
            #pragma unroll
            for (int j = 0; j < 4; j++) {
                const uint32_t off = sw128((kk * 16 + (lane & 15)) * 128 +
                                           (j * 16 + (lane >> 4) * 8) * 2);
                uint32_t vb[4], vl[4];
                ldsm4t(vb, Vhb + off);
                ldsm4t(vl, Vlb + off);
                #pragma unroll
                for (int t2 = 0; t2 < 2; t2++) {
                    float* cc = oacc[j * 2 + t2];
                    mma16816(cc, pa, vb[t2 * 2], vb[t2 * 2 + 1]);
                    mma16816(cc, pa, vl[t2 * 2], vl[t2 * 2 + 1]);
                    mma16816(cc, pl, vb[t2 * 2], vb[t2 * 2 + 1]);
                }
            }
        }

        // ---- pipeline advance ----
        if (c + 1 < NCH) {
            __syncthreads();                 // done reading stage s
            if (c + 2 < NCH) {
                PRE(c + 2, s);               // refill stage s
                CP_COMMIT();
                CP_WAIT1();                  // chunk c+1 ready
            } else {
                CP_WAIT0();                  // last chunk ready
            }
            __syncthreads();
        }
    }

    // ---- finalize ----
    l0 += __shfl_xor_sync(0xffffffffu, l0, 1);
    l0 += __shfl_xor_sync(0xffffffffu, l0, 2);
    l1 += __shfl_xor_sync(0xffffffffu, l1, 1);
    l1 += __shfl_xor_sync(0xffffffffu, l1, 2);
    const float i0 = 1.f / l0, i1 = 1.f / l1;

    const int r0g = bb * SEQ + q0 + wm + (lane >> 2);
    const int cb  = h * 64 + (lane & 3) * 2;
    #pragma unroll
    for (int j = 0; j < 8; j++) {
        const float v0x = oacc[j][0] * i0, v0y = oacc[j][1] * i0;
        const float v1x = oacc[j][2] * i1, v1y = oacc[j][3] * i1;
        __nv_bfloat162 h0 = __floats2bfloat162_rn(v0x, v0y);
        __nv_bfloat162 e0 = __floats2bfloat162_rn(v0x - __bfloat162float(h0.x),
                                                  v0y - __bfloat162float(h0.y));
        __nv_bfloat162 h1 = __floats2bfloat162_rn(v1x, v1y);
        __nv_bfloat162 e1 = __floats2bfloat162_rn(v1x - __bfloat162float(h1.x),
                                                  v1y - __bfloat162float(h1.y));
        *(__nv_bfloat162*)(g_attn_hi + (size_t)r0g * HID + cb + j * 8)       = h0;
        *(__nv_bfloat162*)(g_attn_lo + (size_t)r0g * HID + cb + j * 8)       = e0;
        *(__nv_bfloat162*)(g_attn_hi + (size_t)(r0g + 8) * HID + cb + j * 8) = h1;
        *(__nv_bfloat162*)(g_attn_lo + (size_t)(r0g + 8) * HID + cb + j * 8) = e1;
    }
}

// ---------------------------------------------------------------------------
// LayerNorm: fp32 in -> bf16 hi/lo out
// ---------------------------------------------------------------------------
__global__ __launch_bounds__(256) void ln_kernel(
    const float* __restrict__ X, const float* __restrict__ g,
    const float* __restrict__ b, __nv_bfloat16* __restrict__ Yhi,
    __nv_bfloat16* __restrict__ Ylo)
{
    __shared__ float red[16];
    const long row = blockIdx.x;
    const int  t   = threadIdx.x;

    float4 v = ((const float4*)(X + row * HID))[t];
    float s  = v.x + v.y + v.z + v.w;
    float sq = v.x*v.x + v.y*v.y + v.z*v.z + v.w*v.w;

    #pragma unroll
    for (int o = 16; o > 0; o >>= 1) {
        s  += __shfl_xor_sync(0xffffffffu, s,  o);
        sq += __shfl_xor_sync(0xffffffffu, sq, o);
    }
    const int warp = t >> 5, lane = t & 31;
    if (lane == 0) { red[warp] = s; red[warp + 8] = sq; }
    __syncthreads();
    if (t < 32) {
        float ss = (lane < 8) ? red[lane]     : 0.f;
        float qq = (lane < 8) ? red[lane + 8] : 0.f;
        #pragma unroll
        for (int o = 4; o > 0; o >>= 1) {
            ss += __shfl_xor_sync(0xffffffffu, ss, o);
            qq += __shfl_xor_sync(0xffffffffu, qq, o);
        }
        if (lane == 0) { red[0] = ss; red[1] = qq; }
    }
    __syncthreads();

    const float mu   = red[0] * (1.f / HID);
    const float var  = red[1] * (1.f / HID) - mu * mu;
    const float rstd = rsqrtf(var + LN_EPS);

    const float4 gv = ((const float4*)g)[t];
    const float4 bv = ((const float4*)b)[t];
    float4 y;
    y.x = (v.x - mu) * rstd * gv.x + bv.x;
    y.y = (v.y - mu) * rstd * gv.y + bv.y;
    y.z = (v.z - mu) * rstd * gv.z + bv.z;
    y.w = (v.w - mu) * rstd * gv.w + bv.w;

    __nv_bfloat162 h01 = __floats2bfloat162_rn(y.x, y.y);
    __nv_bfloat162 h23 = __floats2bfloat162_rn(y.z, y.w);
    __nv_bfloat162 l01 = __floats2bfloat162_rn(y.x - __bfloat162float(h01.x),
                                               y.y - __bfloat162float(h01.y));
    __nv_bfloat162 l23 = __floats2bfloat162_rn(y.z - __bfloat162float(h23.x),
                                               y.w - __bfloat162float(h23.y));
    uint2 hv, lv;
    hv.x = *(uint32_t*)&h01; hv.y = *(uint32_t*)&h23;
    lv.x = *(uint32_t*)&l01; lv.y = *(uint32_t*)&l23;
    *(uint2*)(Yhi + row * HID + t * 4) = hv;
    *(uint2*)(Ylo + row * HID + t * 4) = lv;
}

// ---------------------------------------------------------------------------
// Launch
// ---------------------------------------------------------------------------
extern "C" void kernel_launch(void* const* d_in, const int* in_sizes, int n_in,
                              void* d_out, int out_size)
{
    const float* x     = (const float*)d_in[0];
    const float* ln1_g = (const float*)d_in[1];
    const float* ln1_b = (const float*)d_in[2];
    const float* qkv_w = (const float*)d_in[3];
    const float* qkv_b = (const float*)d_in[4];
    const float* out_w = (const float*)d_in[5];
    const float* out_b = (const float*)d_in[6];
    const float* ln2_g = (const float*)d_in[7];
    const float* ln2_b = (const float*)d_in[8];
    const float* w1    = (const float*)d_in[9];
    const float* b1    = (const float*)d_in[10];
    const float* w2    = (const float*)d_in[11];
    const float* b2    = (const float*)d_in[12];
    float* out = (float*)d_out;

    float *p_x1;
    __nv_bfloat16 *p_qkv_hi, *p_qkv_lo;
    __nv_bfloat16 *p_h_hi, *p_h_lo, *p_attn_hi, *p_attn_lo, *p_mid_hi, *p_mid_lo;
    __nv_bfloat16 *p_wqkv_hi, *p_wqkv_lo, *p_wout_hi, *p_wout_lo;
    __nv_bfloat16 *p_w1_hi, *p_w1_lo, *p_w2_hi, *p_w2_lo;
    cudaGetSymbolAddress((void**)&p_x1,      g_x1);
    cudaGetSymbolAddress((void**)&p_qkv_hi,  g_qkv_hi);
    cudaGetSymbolAddress((void**)&p_qkv_lo,  g_qkv_lo);
    cudaGetSymbolAddress((void**)&p_h_hi,    g_h_hi);
    cudaGetSymbolAddress((void**)&p_h_lo,    g_h_lo);
    cudaGetSymbolAddress((void**)&p_attn_hi, g_attn_hi);
    cudaGetSymbolAddress((void**)&p_attn_lo, g_attn_lo);
    cudaGetSymbolAddress((void**)&p_mid_hi,  g_mid_hi);
    cudaGetSymbolAddress((void**)&p_mid_lo,  g_mid_lo);
    cudaGetSymbolAddress((void**)&p_wqkv_hi, g_wqkv_hi);
    cudaGetSymbolAddress((void**)&p_wqkv_lo, g_wqkv_lo);
    cudaGetSymbolAddress((void**)&p_wout_hi, g_wout_hi);
    cudaGetSymbolAddress((void**)&p_wout_lo, g_wout_lo);
    cudaGetSymbolAddress((void**)&p_w1_hi,   g_w1_hi);
    cudaGetSymbolAddress((void**)&p_w1_lo,   g_w1_lo);
    cudaGetSymbolAddress((void**)&p_w2_hi,   g_w2_hi);
    cudaGetSymbolAddress((void**)&p_w2_lo,   g_w2_lo);

    cudaFuncSetAttribute((const void*)hgemm2<0>,
                         cudaFuncAttributeMaxDynamicSharedMemorySize, HG2_SMEM);
    cudaFuncSetAttribute((const void*)hgemm2<1>,
                         cudaFuncAttributeMaxDynamicSharedMemorySize, HG2_SMEM);
    cudaFuncSetAttribute((const void*)hgemm2<2>,
                         cudaFuncAttributeMaxDynamicSharedMemorySize, HG2_SMEM);
    cudaFuncSetAttribute((const void*)hgemm2<3>,
                         cudaFuncAttributeMaxDynamicSharedMemorySize, HG2_SMEM);
    cudaFuncSetAttribute((const void*)attn_mma,
                         cudaFuncAttributeMaxDynamicSharedMemorySize, ATT_SMEM);

    // 0) weight splits
    convw<<<(HID * 3 * HID / 4 + 255) / 256, 256>>>(qkv_w, p_wqkv_hi, p_wqkv_lo, HID * 3 * HID);
    convw<<<(HID * HID / 4 + 255) / 256, 256>>>(out_w, p_wout_hi, p_wout_lo, HID * HID);
    convw<<<(HID * INTER / 4 + 255) / 256, 256>>>(w1, p_w1_hi, p_w1_lo, HID * INTER);
    convw<<<(INTER * HID / 4 + 255) / 256, 256>>>(w2, p_w2_hi, p_w2_lo, INTER * HID);

    // 1) LN1: x -> h hi/lo
    ln_kernel<<<NTOK, 256>>>(x, ln1_g, ln1_b, p_h_hi, p_h_lo);

    // 2) QKV: h @ wqkv + qkv_b -> qkv hi/lo (bf16)
    hgemm2<3><<<dim3((3 * HID) / BN, NTOK / BM), 256, HG2_SMEM>>>(
        p_h_hi, p_h_lo, p_wqkv_hi, p_wqkv_lo, qkv_b, nullptr,
        nullptr, p_qkv_hi, p_qkv_lo, NTOK, 3 * HID, HID);

    // 3) attention: qkv hi/lo -> attn hi/lo
    attn_mma<<<dim3(SEQ / QT, NHEAD, BATCH), 256, ATT_SMEM>>>();

    // 4) x1 = x + attn @ wout + out_b
    hgemm2<1><<<dim3(HID / BN, NTOK / BM), 256, HG2_SMEM>>>(
        p_attn_hi, p_attn_lo, p_wout_hi, p_wout_lo, out_b, x,
        p_x1, nullptr, nullptr, NTOK, HID, HID);

    // 5) LN2: x1 -> h hi/lo
    ln_kernel<<<NTOK, 256>>>(p_x1, ln2_g, ln2_b, p_h_hi, p_h_lo);

    // 6) mid = gelu(h @ w1 + b1) -> mid hi/lo
    hgemm2<2><<<dim3(INTER / BN, NTOK / BM), 256, HG2_SMEM>>>(
        p_h_hi, p_h_lo, p_w1_hi, p_w1_lo, b1, nullptr,
        nullptr, p_mid_hi, p_mid_lo, NTOK, INTER, HID);

    // 7) out = x1 + mid @ w2 + b2
    hgemm2<1><<<dim3(HID / BN, NTOK / BM), 256, HG2_SMEM>>>(
        p_mid_hi, p_mid_lo, p_w2_hi, p_w2_lo, b2, p_x1,
        out, nullptr, nullptr, NTOK, HID, INTER);
}

// round 9
// speedup vs baseline: 8.1199x; 1.3907x over previous
#include <cuda_runtime.h>
#include <cuda_fp16.h>
#include <math.h>
#include <stdint.h>

// ---------------------------------------------------------------------------
// Problem constants
// ---------------------------------------------------------------------------
#define HID   1024
#define NHEAD 16
#define HD    64
#define INTER 4096
#define BATCH 4
#define SEQ   2048
#define NTOK  (BATCH * SEQ)          // 8192
#define LN_EPS 1e-5f

// ---------------------------------------------------------------------------
// Scratch (static device globals; no runtime allocation)
// fp16 value format: activations single, weights + QKV hi/lo.
// ---------------------------------------------------------------------------
__device__ float  g_x1 [NTOK * HID];             // residual-1 (fp32)
__device__ __half g_qkv_hi[NTOK * 3 * HID];      // QKV hi/lo
__device__ __half g_qkv_lo[NTOK * 3 * HID];
__device__ __half g_h   [NTOK * HID];            // LN out (single fp16)
__device__ __half g_attn[NTOK * HID];            // attention out (single fp16)
__device__ __half g_mid [NTOK * INTER];          // GELU(MLP1) (single fp16)
__device__ __half g_wqkv_hi[HID * 3 * HID];      // split weights
__device__ __half g_wqkv_lo[HID * 3 * HID];
__device__ __half g_wout_hi[HID * HID];
__device__ __half g_wout_lo[HID * HID];
__device__ __half g_w1_hi  [HID * INTER];
__device__ __half g_w1_lo  [HID * INTER];
__device__ __half g_w2_hi  [INTER * HID];
__device__ __half g_w2_lo  [INTER * HID];

// ---------------------------------------------------------------------------
// PTX helpers (sm_80-baseline features only)
// ---------------------------------------------------------------------------
__device__ __forceinline__ uint32_t smem_u32(const void* p) {
    uint32_t a;
    asm("{ .reg .u64 t; cvta.to.shared.u64 t, %1; cvt.u32.u64 %0, t; }"
        : "=r"(a) : "l"(p));
    return a;
}
__device__ __forceinline__ void ldsm4(uint32_t* r, uint32_t addr) {
    asm volatile("ldmatrix.sync.aligned.m8n8.x4.shared.b16 {%0,%1,%2,%3}, [%4];"
                 : "=r"(r[0]), "=r"(r[1]), "=r"(r[2]), "=r"(r[3]) : "r"(addr));
}
__device__ __forceinline__ void ldsm4t(uint32_t* r, uint32_t addr) {
    asm volatile("ldmatrix.sync.aligned.m8n8.x4.trans.shared.b16 {%0,%1,%2,%3}, [%4];"
                 : "=r"(r[0]), "=r"(r[1]), "=r"(r[2]), "=r"(r[3]) : "r"(addr));
}
__device__ __forceinline__ void mma_f16(float* c, const uint32_t* a,
                                        uint32_t b0, uint32_t b1) {
    asm volatile(
        "mma.sync.aligned.m16n8k16.row.col.f32.f16.f16.f32 "
        "{%0,%1,%2,%3}, {%4,%5,%6,%7}, {%8,%9}, {%0,%1,%2,%3};"
        : "+f"(c[0]), "+f"(c[1]), "+f"(c[2]), "+f"(c[3])
        : "r"(a[0]), "r"(a[1]), "r"(a[2]), "r"(a[3]), "r"(b0), "r"(b1));
}
__device__ __forceinline__ void cpasync16(uint32_t s, const void* g) {
    asm volatile("cp.async.cg.shared.global [%0], [%1], 16;" :: "r"(s), "l"(g));
}
#define CP_COMMIT() asm volatile("cp.async.commit_group;" ::: "memory")
#define CP_WAIT1()  asm volatile("cp.async.wait_group 1;"  ::: "memory")
#define CP_WAIT0()  asm volatile("cp.async.wait_group 0;"  ::: "memory")

__device__ __forceinline__ uint32_t swA(uint32_t off) { return off ^ ((off >> 2) & 0x30); }
__device__ __forceinline__ uint32_t swB(uint32_t off) { return off ^ ((off >> 4) & 0x70); }
__device__ __forceinline__ uint32_t sw128(uint32_t off) { return off ^ ((off >> 3) & 0x70); }

__device__ __forceinline__ uint32_t pack_h2(float x, float y) {
    __half2 h = __floats2half2_rn(x, y);
    return *(uint32_t*)&h;
}

// ---------------------------------------------------------------------------
// Weight fp32 -> fp16 hi/lo split
// ---------------------------------------------------------------------------
__global__ __launch_bounds__(256) void convw(
    const float* __restrict__ w, __half* __restrict__ hi,
    __half* __restrict__ lo, int n)
{
    const int i = (blockIdx.x * 256 + threadIdx.x) * 4;
    if (i >= n) return;
    const float4 v = *(const float4*)(w + i);
    __half2 h01 = __floats2half2_rn(v.x, v.y);
    __half2 h23 = __floats2half2_rn(v.z, v.w);
    __half2 l01 = __floats2half2_rn(v.x - __low2float(h01), v.y - __high2float(h01));
    __half2 l23 = __floats2half2_rn(v.z - __low2float(h23), v.w - __high2float(h23));
    uint2 hv, lv;
    hv.x = *(uint32_t*)&h01; hv.y = *(uint32_t*)&h23;
    lv.x = *(uint32_t*)&l01; lv.y = *(uint32_t*)&l23;
    *(uint2*)(hi + i) = hv;
    *(uint2*)(lo + i) = lv;
}

// ---------------------------------------------------------------------------
// fp16 HMMA GEMM, 2-term split: C = A @ (Bh + Bl) + bias (+epilogue).
// A single fp16; tile 128x128, BK=32, cp.async 3-stage (24KB/stage = 72KB).
// EPI: 1 = +bias+res -> fp32; 2 = +bias+GELU -> fp16 single;
//      3 = +bias -> fp16 hi/lo
// ---------------------------------------------------------------------------
#define BM 128
#define BN 128
#define BK 32
#define ST_BYTES 24576
#define HG2_SMEM (3 * ST_BYTES)

template <int EPI>
__global__ __launch_bounds__(256, 2) void hgemm2(
    const __half* __restrict__ A,
    const __half* __restrict__ Bhi, const __half* __restrict__ Blo,
    const float* __restrict__ bias, const float* __restrict__ res,
    float* __restrict__ Cf, __half* __restrict__ Chi,
    __half* __restrict__ Clo, int M, int N, int K)
{
    extern __shared__ char smem[];
    const uint32_t sb = smem_u32(smem);
    const int tid  = threadIdx.x;
    const int lane = tid & 31;
    const int wid  = tid >> 5;
    const int m0   = blockIdx.y * BM;
    const int n0   = blockIdx.x * BN;

    const int ar  = tid >> 1;
    const int ae  = (tid & 1) * 16;
    const int bkr = tid >> 3;
    const int bne = (tid & 7) * 16;
    const uint32_t sA0 = swA(ar * 64 + ae * 2);
    const uint32_t sA1 = swA(ar * 64 + ae * 2 + 16);
    const uint32_t sB0 = swB(bkr * 256 + bne * 2);
    const uint32_t sB1 = swB(bkr * 256 + bne * 2 + 16);
    const size_t aoff = (size_t)(m0 + ar) * K + ae;

    auto PRE = [&](int c, int s) {
        const uint32_t st = sb + s * ST_BYTES;
        const __half* ap = A + aoff + c * BK;
        const size_t boff = (size_t)(c * BK + bkr) * N + n0 + bne;
        cpasync16(st + sA0, ap);
        cpasync16(st + sA1, ap + 8);
        cpasync16(st + 8192 + sB0,  Bhi + boff);
        cpasync16(st + 8192 + sB1,  Bhi + boff + 8);
        cpasync16(st + 16384 + sB0, Blo + boff);
        cpasync16(st + 16384 + sB1, Blo + boff + 8);
    };

    const int wm  = (wid & 3) * 32;
    const int wn  = (wid >> 2) * 64;
    const int a_r = lane & 15;
    const int a_k = (lane >> 4) * 8;
    const int b_k = lane & 15;
    const int b_n = (lane >> 4) * 8;

    float acc[2][8][4];
    #pragma unroll
    for (int i = 0; i < 2; i++)
        #pragma unroll
        for (int j = 0; j < 8; j++)
            #pragma unroll
            for (int q = 0; q < 4; q++) acc[i][j][q] = 0.f;

    auto COMPUTE = [&](int s) {
        const uint32_t AS  = sb + s * ST_BYTES;
        const uint32_t BhS = AS + 8192;
        const uint32_t BlS = AS + 16384;
        #pragma unroll
        for (int ks = 0; ks < 2; ks++) {
            uint32_t a_[2][4];
            #pragma unroll
            for (int mt = 0; mt < 2; mt++) {
                const uint32_t off = swA((wm + mt * 16 + a_r) * 64 + (ks * 16 + a_k) * 2);
                ldsm4(a_[mt], AS + off);
            }
            #pragma unroll
            for (int ng = 0; ng < 4; ng++) {
                uint32_t bh[4], bl[4];
                const uint32_t off = swB((ks * 16 + b_k) * 256 + (wn + ng * 16 + b_n) * 2);
                ldsm4t(bh, BhS + off);
                ldsm4t(bl, BlS + off);
                #pragma unroll
                for (int mt = 0; mt < 2; mt++) {
                    #pragma unroll
                    for (int hf = 0; hf < 2; hf++) {
                        float* cc = acc[mt][ng * 2 + hf];
                        mma_f16(cc, a_[mt], bh[hf * 2], bh[hf * 2 + 1]);
                        mma_f16(cc, a_[mt], bl[hf * 2], bl[hf * 2 + 1]);
                    }
                }
            }
        }
    };

    PRE(0, 0); CP_COMMIT();
    PRE(1, 1); CP_COMMIT();
    const int NC = K / BK;
    #pragma unroll 1
    for (int c = 0; c < NC; c++) {
        const int s = c - (c / 3) * 3;
        CP_WAIT1();
        __syncthreads();
        COMPUTE(s);
        if (c + 2 < NC) {
            const int s2 = (c + 2) - ((c + 2) / 3) * 3;
            PRE(c + 2, s2);
        }
        CP_COMMIT();
    }

    #pragma unroll
    for (int mt = 0; mt < 2; mt++) {
        #pragma unroll
        for (int nt = 0; nt < 8; nt++) {
            const int r0 = m0 + wm + mt * 16 + (lane >> 2);
            const int cc = n0 + wn + nt * 8 + (lane & 3) * 2;
            const float bx = bias[cc], by = bias[cc + 1];
            #pragma unroll
            for (int half = 0; half < 2; half++) {
                const int r = r0 + half * 8;
                float vx = acc[mt][nt][half * 2 + 0] + bx;
                float vy = acc[mt][nt][half * 2 + 1] + by;
                if (EPI == 2) {
                    float t = tanhf(0.7978845608028654f * (vx + 0.044715f * vx * vx * vx));
                    vx = 0.5f * vx * (1.0f + t);
                    t = tanhf(0.7978845608028654f * (vy + 0.044715f * vy * vy * vy));
                    vy = 0.5f * vy * (1.0f + t);
                    *(__half2*)(Chi + (size_t)r * N + cc) = __floats2half2_rn(vx, vy);
                } else if (EPI == 3) {
                    __half2 hh = __floats2half2_rn(vx, vy);
                    __half2 ll = __floats2half2_rn(vx - __low2float(hh),
                                                   vy - __high2float(hh));
                    *(__half2*)(Chi + (size_t)r * N + cc) = hh;
                    *(__half2*)(Clo + (size_t)r * N + cc) = ll;
                } else {
                    const float2 rv = *(const float2*)(res + (size_t)r * N + cc);
                    float2 w; w.x = vx + rv.x; w.y = vy + rv.y;
                    *(float2*)(Cf + (size_t)r * N + cc) = w;
                }
            }
        }
    }
}

// ---------------------------------------------------------------------------
// Tensor-core flash attention (fp16).
// QK^T: 3-term (Qh Kh + Qh Kl + Ql Kh); P@V: 2-term (P @ (Vh + Vl)).
// One CTA = 128 q-rows x (head,batch); 8 warps; KV chunks of 64,
// 2-stage cp.async. Smem: Qh 16K | Ql 16K | 2 x (Kh,Kl,Vh,Vl 32K) = 96KB.
// ---------------------------------------------------------------------------
#define QT 128
#define KT 64
#define ATT_SMEM (32768 + 2 * 32768)

__global__ __launch_bounds__(256, 2) void attn_mma()
{
    extern __shared__ char smem[];
    const uint32_t sb = smem_u32(smem);
    const int tid  = threadIdx.x;
    const int lane = tid & 31;
    const int wid  = tid >> 5;
    const int h    = blockIdx.y;
    const int bb   = blockIdx.z;
    const int q0   = blockIdx.x * QT;

    // Q cp.async (hi + lo, 32KB)
    {
        const int qr  = tid >> 1;
        const int qc0 = (tid & 1) * 32;
        const size_t gq = (size_t)(bb * SEQ + q0 + qr) * 3072 + h * 64 + qc0;
        #pragma unroll
        for (int i = 0; i < 4; i++) {
            const uint32_t so = sw128(qr * 128 + (qc0 + i * 8) * 2);
            cpasync16(sb + so,         g_qkv_hi + gq + i * 8);
            cpasync16(sb + 16384 + so, g_qkv_lo + gq + i * 8);
        }
    }

    const int kr = tid >> 2;
    const int kc = (tid & 3) * 16;
    auto PRE = [&](int c, int s) {
        const uint32_t st = sb + 32768 + s * 32768;
        const size_t base = (size_t)(bb * SEQ + c * KT + kr) * 3072 + h * 64 + kc;
        const uint32_t so0 = sw128(kr * 128 + kc * 2);
        const uint32_t so1 = so0 ^ 16;
        cpasync16(st + so0,          g_qkv_hi + base + 1024);
        cpasync16(st + so1,          g_qkv_hi + base + 1024 + 8);
        cpasync16(st + 8192 + so0,   g_qkv_lo + base + 1024);
        cpasync16(st + 8192 + so1,   g_qkv_lo + base + 1024 + 8);
        cpasync16(st + 16384 + so0,  g_qkv_hi + base + 2048);
        cpasync16(st + 16384 + so1,  g_qkv_hi + base + 2048 + 8);
        cpasync16(st + 24576 + so0,  g_qkv_lo + base + 2048);
        cpasync16(st + 24576 + so1,  g_qkv_lo + base + 2048 + 8);
    };

    PRE(0, 0); CP_COMMIT();
    PRE(1, 1); CP_COMMIT();
    CP_WAIT1();
    __syncthreads();

    const int wm = wid * 16;

    float oacc[8][4];
    #pragma unroll
    for (int j = 0; j < 8; j++)
        #pragma unroll
        for (int q = 0; q < 4; q++) oacc[j][q] = 0.f;
    float m0 = -1e30f, m1 = -1e30f, l0 = 0.f, l1 = 0.f;

    const int k_rowadd = ((lane >> 4) & 1) * 8;
    const int k_koff   = ((lane >> 3) & 1) * 8;
    const int k_r8     = lane & 7;

    const int NCH = SEQ / KT;
    #pragma unroll 1
    for (int c = 0; c < NCH; c++) {
        const int s = c & 1;
        const uint32_t st  = sb + 32768 + s * 32768;
        const uint32_t Khb = st, Klb = st + 8192, Vhb = st + 16384, Vlb = st + 24576;

        float sacc[8][4];
        #pragma unroll
        for (int j = 0; j < 8; j++)
            #pragma unroll
            for (int q = 0; q < 4; q++) sacc[j][q] = 0.f;

        #pragma unroll
        for (int ks = 0; ks < 4; ks++) {
            uint32_t qh[4], ql[4];
            const uint32_t qoff =
                sw128((wm + (lane & 15)) * 128 + (ks * 16 + (lane >> 4) * 8) * 2);
            ldsm4(qh, sb + qoff);
            ldsm4(ql, sb + 16384 + qoff);
            #pragma unroll
            for (int j = 0; j < 4; j++) {
                const uint32_t off = sw128((j * 16 + k_r8 + k_rowadd) * 128 +
                                           (ks * 16 + k_koff) * 2);
                uint32_t kb[4], kl[4];
                ldsm4(kb, Khb + off);
                ldsm4(kl, Klb + off);
                #pragma unroll
                for (int t2 = 0; t2 < 2; t2++) {
                    float* cc = sacc[j * 2 + t2];
                    mma_f16(cc, qh, kb[t2 * 2], kb[t2 * 2 + 1]);
                    mma_f16(cc, qh, kl[t2 * 2], kl[t2 * 2 + 1]);
                    mma_f16(cc, ql, kb[t2 * 2], kb[t2 * 2 + 1]);
                }
            }
        }

        // online softmax
        float vm0 = -1e30f, vm1 = -1e30f;
        #pragma unroll
        for (int j = 0; j < 8; j++) {
            vm0 = fmaxf(vm0, fmaxf(sacc[j][0], sacc[j][1]));
            vm1 = fmaxf(vm1, fmaxf(sacc[j][2], sacc[j][3]));
        }
        vm0 = fmaxf(vm0, __shfl_xor_sync(0xffffffffu, vm0, 1));
        vm0 = fmaxf(vm0, __shfl_xor_sync(0xffffffffu, vm0, 2));
        vm1 = fmaxf(vm1, __shfl_xor_sync(0xffffffffu, vm1, 1));
        vm1 = fmaxf(vm1, __shfl_xor_sync(0xffffffffu, vm1, 2));
        vm0 *= 0.125f; vm1 *= 0.125f;

        const float mn0 = fmaxf(m0, vm0), mn1 = fmaxf(m1, vm1);
        const float c0 = __expf(m0 - mn0), c1 = __expf(m1 - mn1);
        m0 = mn0; m1 = mn1;
        l0 *= c0;  l1 *= c1;
        #pragma unroll
        for (int j = 0; j < 8; j++) {
            oacc[j][0] *= c0; oacc[j][1] *= c0;
            oacc[j][2] *= c1; oacc[j][3] *= c1;
        }
        #pragma unroll
        for (int j = 0; j < 8; j++) {
            sacc[j][0] = __expf(fmaf(sacc[j][0], 0.125f, -mn0));
            sacc[j][1] = __expf(fmaf(sacc[j][1], 0.125f, -mn0));
            sacc[j][2] = __expf(fmaf(sacc[j][2], 0.125f, -mn1));
            sacc[j][3] = __expf(fmaf(sacc[j][3], 0.125f, -mn1));
            l0 += sacc[j][0] + sacc[j][1];
            l1 += sacc[j][2] + sacc[j][3];
        }

        // O += P @ (Vh + Vl); P single fp16
        #pragma unroll
        for (int kk = 0; kk < 4; kk++) {
            const float* p0 = sacc[kk * 2];
            const float* p1 = sacc[kk * 2 + 1];
            uint32_t pa[4];
            pa[0] = pack_h2(p0[0], p0[1]);
            pa[1] = pack_h2(p0[2], p0[3]);
            pa[2] = pack_h2(p1[0], p1[1]);
            pa[3] = pack_h2(p1[2], p1[3]);
            #pragma unroll
            for (int j = 0; j < 4; j++) {
                const uint32_t off = sw128((kk * 16 + (lane & 15)) * 128 +
                                           (j * 16 + (lane >> 4) * 8) * 2);
                uint32_t vb[4], vl[4];
                ldsm4t(vb, Vhb + off);
                ldsm4t(vl, Vlb + off);
                #pragma unroll
                for (int t2 = 0; t2 < 2; t2++) {
                    float* cc = oacc[j * 2 + t2];
                    mma_f16(cc, pa, vb[t2 * 2], vb[t2 * 2 + 1]);
                    mma_f16(cc, pa, vl[t2 * 2], vl[t2 * 2 + 1]);
                }
            }
        }

        if (c + 1 < NCH) {
            __syncthreads();
            if (c + 2 < NCH) {
                PRE(c + 2, s);
                CP_COMMIT();
                CP_WAIT1();
            } else {
                CP_WAIT0();
            }
            __syncthreads();
        }
    }

    l0 += __shfl_xor_sync(0xffffffffu, l0, 1);
    l0 += __shfl_xor_sync(0xffffffffu, l0, 2);
    l1 += __shfl_xor_sync(0xffffffffu, l1, 1);
    l1 += __shfl_xor_sync(0xffffffffu, l1, 2);
    const float i0 = 1.f / l0, i1 = 1.f / l1;

    const int r0g = bb * SEQ + q0 + wm + (lane >> 2);
    const int cb  = h * 64 + (lane & 3) * 2;
    #pragma unroll
    for (int j = 0; j < 8; j++) {
        *(__half2*)(g_attn + (size_t)r0g * HID + cb + j * 8) =
            __floats2half2_rn(oacc[j][0] * i0, oacc[j][1] * i0);
        *(__half2*)(g_attn + (size_t)(r0g + 8) * HID + cb + j * 8) =
            __floats2half2_rn(oacc[j][2] * i1, oacc[j][3] * i1);
    }
}

// ---------------------------------------------------------------------------
// LayerNorm: fp32 in -> fp16 single out
// ---------------------------------------------------------------------------
__global__ __launch_bounds__(256) void ln_kernel(
    const float* __restrict__ X, const float* __restrict__ g,
    const float* __restrict__ b, __half* __restrict__ Y)
{
    __shared__ float red[16];
    const long row = blockIdx.x;
    const int  t   = threadIdx.x;

    float4 v = ((const float4*)(X + row * HID))[t];
    float s  = v.x + v.y + v.z + v.w;
    float sq = v.x*v.x + v.y*v.y + v.z*v.z + v.w*v.w;

    #pragma unroll
    for (int o = 16; o > 0; o >>= 1) {
        s  += __shfl_xor_sync(0xffffffffu, s,  o);
        sq += __shfl_xor_sync(0xffffffffu, sq, o);
    }
    const int warp = t >> 5, lane = t & 31;
    if (lane == 0) { red[warp] = s; red[warp + 8] = sq; }
    __syncthreads();
    if (t < 32) {
        float ss = (lane < 8) ? red[lane]     : 0.f;
        float qq = (lane < 8) ? red[lane + 8] : 0.f;
        #pragma unroll
        for (int o = 4; o > 0; o >>= 1) {
            ss += __shfl_xor_sync(0xffffffffu, ss, o);
            qq += __shfl_xor_sync(0xffffffffu, qq, o);
        }
        if (lane == 0) { red[0] = ss; red[1] = qq; }
    }
    __syncthreads();

    const float mu   = red[0] * (1.f / HID);
    const float var  = red[1] * (1.f / HID) - mu * mu;
    const float rstd = rsqrtf(var + LN_EPS);

    const float4 gv = ((const float4*)g)[t];
    const float4 bv = ((const float4*)b)[t];
    __half2 a = __floats2half2_rn((v.x - mu) * rstd * gv.x + bv.x,
                                  (v.y - mu) * rstd * gv.y + bv.y);
    __half2 c = __floats2half2_rn((v.z - mu) * rstd * gv.z + bv.z,
                                  (v.w - mu) * rstd * gv.w + bv.w);
    uint2 u; u.x = *(uint32_t*)&a; u.y = *(uint32_t*)&c;
    *(uint2*)(Y + row * HID + t * 4) = u;
}

// ---------------------------------------------------------------------------
// Launch
// ---------------------------------------------------------------------------
extern "C" void kernel_launch(void* const* d_in, const int* in_sizes, int n_in,
                              void* d_out, int out_size)
{
    const float* x     = (const float*)d_in[0];
    const float* ln1_g = (const float*)d_in[1];
    const float* ln1_b = (const float*)d_in[2];
    const float* qkv_w = (const float*)d_in[3];
    const float* qkv_b = (const float*)d_in[4];
    const float* out_w = (const float*)d_in[5];
    const float* out_b = (const float*)d_in[6];
    const float* ln2_g = (const float*)d_in[7];
    const float* ln2_b = (const float*)d_in[8];
    const float* w1    = (const float*)d_in[9];
    const float* b1    = (const float*)d_in[10];
    const float* w2    = (const float*)d_in[11];
    const float* b2    = (const float*)d_in[12];
    float* out = (float*)d_out;

    float* p_x1;
    __half *p_qkv_hi, *p_qkv_lo, *p_h, *p_attn, *p_mid;
    __half *p_wqkv_hi, *p_wqkv_lo, *p_wout_hi, *p_wout_lo;
    __half *p_w1_hi, *p_w1_lo, *p_w2_hi, *p_w2_lo;
    cudaGetSymbolAddress((void**)&p_x1,      g_x1);
    cudaGetSymbolAddress((void**)&p_qkv_hi,  g_qkv_hi);
    cudaGetSymbolAddress((void**)&p_qkv_lo,  g_qkv_lo);
    cudaGetSymbolAddress((void**)&p_h,       g_h);
    cudaGetSymbolAddress((void**)&p_attn,    g_attn);
    cudaGetSymbolAddress((void**)&p_mid,     g_mid);
    cudaGetSymbolAddress((void**)&p_wqkv_hi, g_wqkv_hi);
    cudaGetSymbolAddress((void**)&p_wqkv_lo, g_wqkv_lo);
    cudaGetSymbolAddress((void**)&p_wout_hi, g_wout_hi);
    cudaGetSymbolAddress((void**)&p_wout_lo, g_wout_lo);
    cudaGetSymbolAddress((void**)&p_w1_hi,   g_w1_hi);
    cudaGetSymbolAddress((void**)&p_w1_lo,   g_w1_lo);
    cudaGetSymbolAddress((void**)&p_w2_hi,   g_w2_hi);
    cudaGetSymbolAddress((void**)&p_w2_lo,   g_w2_lo);

    cudaFuncSetAttribute((const void*)hgemm2<1>,
                         cudaFuncAttributeMaxDynamicSharedMemorySize, HG2_SMEM);
    cudaFuncSetAttribute((const void*)hgemm2<2>,
                         cudaFuncAttributeMaxDynamicSharedMemorySize, HG2_SMEM);
    cudaFuncSetAttribute((const void*)hgemm2<3>,
                         cudaFuncAttributeMaxDynamicSharedMemorySize, HG2_SMEM);
    cudaFuncSetAttribute((const void*)attn_mma,
                         cudaFuncAttributeMaxDynamicSharedMemorySize, ATT_SMEM);

    // 0) weight splits
    convw<<<(HID * 3 * HID / 4 + 255) / 256, 256>>>(qkv_w, p_wqkv_hi, p_wqkv_lo, HID * 3 * HID);
    convw<<<(HID * HID / 4 + 255) / 256, 256>>>(out_w, p_wout_hi, p_wout_lo, HID * HID);
    convw<<<(HID * INTER / 4 + 255) / 256, 256>>>(w1, p_w1_hi, p_w1_lo, HID * INTER);
    convw<<<(INTER * HID / 4 + 255) / 256, 256>>>(w2, p_w2_hi, p_w2_lo, INTER * HID);

    // 1) LN1: x -> h (fp16)
    ln_kernel<<<NTOK, 256>>>(x, ln1_g, ln1_b, p_h);

    // 2) QKV: h @ (wqkv hi+lo) + qkv_b -> qkv hi/lo
    hgemm2<3><<<dim3((3 * HID) / BN, NTOK / BM), 256, HG2_SMEM>>>(
        p_h, p_wqkv_hi, p_wqkv_lo, qkv_b, nullptr,
        nullptr, p_qkv_hi, p_qkv_lo, NTOK, 3 * HID, HID);

    // 3) attention: qkv hi/lo -> attn (fp16)
    attn_mma<<<dim3(SEQ / QT, NHEAD, BATCH), 256, ATT_SMEM>>>();

    // 4) x1 = x + attn @ (wout hi+lo) + out_b
    hgemm2<1><<<dim3(HID / BN, NTOK / BM), 256, HG2_SMEM>>>(
        p_attn, p_wout_hi, p_wout_lo, out_b, x,
        p_x1, nullptr, nullptr, NTOK, HID, HID);

    // 5) LN2: x1 -> h (fp16)
    ln_kernel<<<NTOK, 256>>>(p_x1, ln2_g, ln2_b, p_h);

    // 6) mid = gelu(h @ (w1 hi+lo) + b1) -> fp16
    hgemm2<2><<<dim3(INTER / BN, NTOK / BM), 256, HG2_SMEM>>>(
        p_h, p_w1_hi, p_w1_lo, b1, nullptr,
        nullptr, p_mid, nullptr, NTOK, INTER, HID);

    // 7) out = x1 + mid @ (w2 hi+lo) + b2
    hgemm2<1><<<dim3(HID / BN, NTOK / BM), 256, HG2_SMEM>>>(
        p_mid, p_w2_hi, p_w2_lo, b2, p_x1,
        out, nullptr, nullptr, NTOK, HID, INTER);
}

// round 10
// speedup vs baseline: 11.1670x; 1.3753x over previous
#include <cuda_runtime.h>
#include <cuda_fp16.h>
#include <math.h>
#include <stdint.h>

// ---------------------------------------------------------------------------
// Problem constants
// ---------------------------------------------------------------------------
#define HID   1024
#define NHEAD 16
#define HD    64
#define INTER 4096
#define BATCH 4
#define SEQ   2048
#define NTOK  (BATCH * SEQ)          // 8192
#define LN_EPS 1e-5f

// ---------------------------------------------------------------------------
// Scratch (static device globals; no runtime allocation)
// fp16 value format: weights + activations single fp16; QKV hi/lo (for
// high-precision QK^T scores and P@V).
// ---------------------------------------------------------------------------
__device__ float  g_x1 [NTOK * HID];             // residual-1 (fp32)
__device__ __half g_qkv_hi[NTOK * 3 * HID];      // QKV hi/lo
__device__ __half g_qkv_lo[NTOK * 3 * HID];
__device__ __half g_h   [NTOK * HID];            // LN out (single fp16)
__device__ __half g_attn[NTOK * HID];            // attention out (single fp16)
__device__ __half g_mid [NTOK * INTER];          // GELU(MLP1) (single fp16)
__device__ __half g_wqkv[HID * 3 * HID];         // single-fp16 weights
__device__ __half g_wout[HID * HID];
__device__ __half g_w1  [HID * INTER];
__device__ __half g_w2  [INTER * HID];

// ---------------------------------------------------------------------------
// PTX helpers (sm_80-baseline features only)
// ---------------------------------------------------------------------------
__device__ __forceinline__ uint32_t smem_u32(const void* p) {
    uint32_t a;
    asm("{ .reg .u64 t; cvta.to.shared.u64 t, %1; cvt.u32.u64 %0, t; }"
        : "=r"(a) : "l"(p));
    return a;
}
__device__ __forceinline__ void ldsm4(uint32_t* r, uint32_t addr) {
    asm volatile("ldmatrix.sync.aligned.m8n8.x4.shared.b16 {%0,%1,%2,%3}, [%4];"
                 : "=r"(r[0]), "=r"(r[1]), "=r"(r[2]), "=r"(r[3]) : "r"(addr));
}
__device__ __forceinline__ void ldsm4t(uint32_t* r, uint32_t addr) {
    asm volatile("ldmatrix.sync.aligned.m8n8.x4.trans.shared.b16 {%0,%1,%2,%3}, [%4];"
                 : "=r"(r[0]), "=r"(r[1]), "=r"(r[2]), "=r"(r[3]) : "r"(addr));
}
__device__ __forceinline__ void mma_f16(float* c, const uint32_t* a,
                                        uint32_t b0, uint32_t b1) {
    asm volatile(
        "mma.sync.aligned.m16n8k16.row.col.f32.f16.f16.f32 "
        "{%0,%1,%2,%3}, {%4,%5,%6,%7}, {%8,%9}, {%0,%1,%2,%3};"
        : "+f"(c[0]), "+f"(c[1]), "+f"(c[2]), "+f"(c[3])
        : "r"(a[0]), "r"(a[1]), "r"(a[2]), "r"(a[3]), "r"(b0), "r"(b1));
}
__device__ __forceinline__ void cpasync16(uint32_t s, const void* g) {
    asm volatile("cp.async.cg.shared.global [%0], [%1], 16;" :: "r"(s), "l"(g));
}
#define CP_COMMIT() asm volatile("cp.async.commit_group;" ::: "memory")
#define CP_WAIT1()  asm volatile("cp.async.wait_group 1;"  ::: "memory")
#define CP_WAIT0()  asm volatile("cp.async.wait_group 0;"  ::: "memory")

__device__ __forceinline__ uint32_t swA(uint32_t off) { return off ^ ((off >> 2) & 0x30); }
__device__ __forceinline__ uint32_t swB(uint32_t off) { return off ^ ((off >> 4) & 0x70); }
__device__ __forceinline__ uint32_t sw128(uint32_t off) { return off ^ ((off >> 3) & 0x70); }

__device__ __forceinline__ uint32_t pack_h2(float x, float y) {
    __half2 h = __floats2half2_rn(x, y);
    return *(uint32_t*)&h;
}

// ---------------------------------------------------------------------------
// Weight fp32 -> single fp16
// ---------------------------------------------------------------------------
__global__ __launch_bounds__(256) void convw(
    const float* __restrict__ w, __half* __restrict__ hi, int n)
{
    const int i = (blockIdx.x * 256 + threadIdx.x) * 4;
    if (i >= n) return;
    const float4 v = *(const float4*)(w + i);
    __half2 h01 = __floats2half2_rn(v.x, v.y);
    __half2 h23 = __floats2half2_rn(v.z, v.w);
    uint2 hv;
    hv.x = *(uint32_t*)&h01; hv.y = *(uint32_t*)&h23;
    *(uint2*)(hi + i) = hv;
}

// ---------------------------------------------------------------------------
// fp16 HMMA GEMM, 1-term: C = A @ B + bias (+epilogue).
// A, B single fp16; tile 128x128, BK=32, cp.async 3-stage (16KB/stage = 48KB).
// EPI: 1 = +bias+res -> fp32; 2 = +bias+GELU -> fp16 single;
//      3 = +bias -> fp16 hi/lo
// ---------------------------------------------------------------------------
#define BM 128
#define BN 128
#define BK 32
#define ST_BYTES 16384
#define HG2_SMEM (3 * ST_BYTES)

template <int EPI>
__global__ __launch_bounds__(256, 2) void hgemm2(
    const __half* __restrict__ A, const __half* __restrict__ B,
    const float* __restrict__ bias, const float* __restrict__ res,
    float* __restrict__ Cf, __half* __restrict__ Chi,
    __half* __restrict__ Clo, int M, int N, int K)
{
    extern __shared__ char smem[];
    const uint32_t sb = smem_u32(smem);
    const int tid  = threadIdx.x;
    const int lane = tid & 31;
    const int wid  = tid >> 5;
    const int m0   = blockIdx.y * BM;
    const int n0   = blockIdx.x * BN;

    const int ar  = tid >> 1;
    const int ae  = (tid & 1) * 16;
    const int bkr = tid >> 3;
    const int bne = (tid & 7) * 16;
    const uint32_t sA0 = swA(ar * 64 + ae * 2);
    const uint32_t sA1 = swA(ar * 64 + ae * 2 + 16);
    const uint32_t sB0 = swB(bkr * 256 + bne * 2);
    const uint32_t sB1 = swB(bkr * 256 + bne * 2 + 16);
    const size_t aoff = (size_t)(m0 + ar) * K + ae;

    auto PRE = [&](int c, int s) {
        const uint32_t st = sb + s * ST_BYTES;
        const __half* ap = A + aoff + c * BK;
        const size_t boff = (size_t)(c * BK + bkr) * N + n0 + bne;
        cpasync16(st + sA0, ap);
        cpasync16(st + sA1, ap + 8);
        cpasync16(st + 8192 + sB0, B + boff);
        cpasync16(st + 8192 + sB1, B + boff + 8);
    };

    const int wm  = (wid & 3) * 32;
    const int wn  = (wid >> 2) * 64;
    const int a_r = lane & 15;
    const int a_k = (lane >> 4) * 8;
    const int b_k = lane & 15;
    const int b_n = (lane >> 4) * 8;

    float acc[2][8][4];
    #pragma unroll
    for (int i = 0; i < 2; i++)
        #pragma unroll
        for (int j = 0; j < 8; j++)
            #pragma unroll
            for (int q = 0; q < 4; q++) acc[i][j][q] = 0.f;

    auto COMPUTE = [&](int s) {
        const uint32_t AS = sb + s * ST_BYTES;
        const uint32_t BS = AS + 8192;
        #pragma unroll
        for (int ks = 0; ks < 2; ks++) {
            uint32_t a_[2][4];
            #pragma unroll
            for (int mt = 0; mt < 2; mt++) {
                const uint32_t off = swA((wm + mt * 16 + a_r) * 64 + (ks * 16 + a_k) * 2);
                ldsm4(a_[mt], AS + off);
            }
            #pragma unroll
            for (int ng = 0; ng < 4; ng++) {
                uint32_t bh[4];
                const uint32_t off = swB((ks * 16 + b_k) * 256 + (wn + ng * 16 + b_n) * 2);
                ldsm4t(bh, BS + off);
                #pragma unroll
                for (int mt = 0; mt < 2; mt++) {
                    #pragma unroll
                    for (int hf = 0; hf < 2; hf++)
                        mma_f16(acc[mt][ng * 2 + hf], a_[mt],
                                bh[hf * 2], bh[hf * 2 + 1]);
                }
            }
        }
    };

    PRE(0, 0); CP_COMMIT();
    PRE(1, 1); CP_COMMIT();
    const int NC = K / BK;
    #pragma unroll 1
    for (int c = 0; c < NC; c++) {
        const int s = c - (c / 3) * 3;
        CP_WAIT1();
        __syncthreads();
        COMPUTE(s);
        if (c + 2 < NC) {
            const int s2 = (c + 2) - ((c + 2) / 3) * 3;
            PRE(c + 2, s2);
        }
        CP_COMMIT();
    }

    #pragma unroll
    for (int mt = 0; mt < 2; mt++) {
        #pragma unroll
        for (int nt = 0; nt < 8; nt++) {
            const int r0 = m0 + wm + mt * 16 + (lane >> 2);
            const int cc = n0 + wn + nt * 8 + (lane & 3) * 2;
            const float bx = bias[cc], by = bias[cc + 1];
            #pragma unroll
            for (int half = 0; half < 2; half++) {
                const int r = r0 + half * 8;
                float vx = acc[mt][nt][half * 2 + 0] + bx;
                float vy = acc[mt][nt][half * 2 + 1] + by;
                if (EPI == 2) {
                    float t = tanhf(0.7978845608028654f * (vx + 0.044715f * vx * vx * vx));
                    vx = 0.5f * vx * (1.0f + t);
                    t = tanhf(0.7978845608028654f * (vy + 0.044715f * vy * vy * vy));
                    vy = 0.5f * vy * (1.0f + t);
                    *(__half2*)(Chi + (size_t)r * N + cc) = __floats2half2_rn(vx, vy);
                } else if (EPI == 3) {
                    __half2 hh = __floats2half2_rn(vx, vy);
                    __half2 ll = __floats2half2_rn(vx - __low2float(hh),
                                                   vy - __high2float(hh));
                    *(__half2*)(Chi + (size_t)r * N + cc) = hh;
                    *(__half2*)(Clo + (size_t)r * N + cc) = ll;
                } else {
                    const float2 rv = *(const float2*)(res + (size_t)r * N + cc);
                    float2 w; w.x = vx + rv.x; w.y = vy + rv.y;
                    *(float2*)(Cf + (size_t)r * N + cc) = w;
                }
            }
        }
    }
}

// ---------------------------------------------------------------------------
// Tensor-core flash attention (fp16) — unchanged from R9.
// QK^T: 3-term (Qh Kh + Qh Kl + Ql Kh); P@V: 2-term (P @ (Vh + Vl)).
// ---------------------------------------------------------------------------
#define QT 128
#define KT 64
#define ATT_SMEM (32768 + 2 * 32768)

__global__ __launch_bounds__(256, 2) void attn_mma()
{
    extern __shared__ char smem[];
    const uint32_t sb = smem_u32(smem);
    const int tid  = threadIdx.x;
    const int lane = tid & 31;
    const int wid  = tid >> 5;
    const int h    = blockIdx.y;
    const int bb   = blockIdx.z;
    const int q0   = blockIdx.x * QT;

    {
        const int qr  = tid >> 1;
        const int qc0 = (tid & 1) * 32;
        const size_t gq = (size_t)(bb * SEQ + q0 + qr) * 3072 + h * 64 + qc0;
        #pragma unroll
        for (int i = 0; i < 4; i++) {
            const uint32_t so = sw128(qr * 128 + (qc0 + i * 8) * 2);
            cpasync16(sb + so,         g_qkv_hi + gq + i * 8);
            cpasync16(sb + 16384 + so, g_qkv_lo + gq + i * 8);
        }
    }

    const int kr = tid >> 2;
    const int kc = (tid & 3) * 16;
    auto PRE = [&](int c, int s) {
        const uint32_t st = sb + 32768 + s * 32768;
        const size_t base = (size_t)(bb * SEQ + c * KT + kr) * 3072 + h * 64 + kc;
        const uint32_t so0 = sw128(kr * 128 + kc * 2);
        const uint32_t so1 = so0 ^ 16;
        cpasync16(st + so0,          g_qkv_hi + base + 1024);
        cpasync16(st + so1,          g_qkv_hi + base + 1024 + 8);
        cpasync16(st + 8192 + so0,   g_qkv_lo + base + 1024);
        cpasync16(st + 8192 + so1,   g_qkv_lo + base + 1024 + 8);
        cpasync16(st + 16384 + so0,  g_qkv_hi + base + 2048);
        cpasync16(st + 16384 + so1,  g_qkv_hi + base + 2048 + 8);
        cpasync16(st + 24576 + so0,  g_qkv_lo + base + 2048);
        cpasync16(st + 24576 + so1,  g_qkv_lo + base + 2048 + 8);
    };

    PRE(0, 0); CP_COMMIT();
    PRE(1, 1); CP_COMMIT();
    CP_WAIT1();
    __syncthreads();

    const int wm = wid * 16;

    float oacc[8][4];
    #pragma unroll
    for (int j = 0; j < 8; j++)
        #pragma unroll
        for (int q = 0; q < 4; q++) oacc[j][q] = 0.f;
    float m0 = -1e30f, m1 = -1e30f, l0 = 0.f, l1 = 0.f;

    const int k_rowadd = ((lane >> 4) & 1) * 8;
    const int k_koff   = ((lane >> 3) & 1) * 8;
    const int k_r8     = lane & 7;

    const int NCH = SEQ / KT;
    #pragma unroll 1
    for (int c = 0; c < NCH; c++) {
        const int s = c & 1;
        const uint32_t st  = sb + 32768 + s * 32768;
        const uint32_t Khb = st, Klb = st + 8192, Vhb = st + 16384, Vlb = st + 24576;

        float sacc[8][4];
        #pragma unroll
        for (int j = 0; j < 8; j++)
            #pragma unroll
            for (int q = 0; q < 4; q++) sacc[j][q] = 0.f;

        #pragma unroll
        for (int ks = 0; ks < 4; ks++) {
            uint32_t qh[4], ql[4];
            const uint32_t qoff =
                sw128((wm + (lane & 15)) * 128 + (ks * 16 + (lane >> 4) * 8) * 2);
            ldsm4(qh, sb + qoff);
            ldsm4(ql, sb + 16384 + qoff);
            #pragma unroll
            for (int j = 0; j < 4; j++) {
                const uint32_t off = sw128((j * 16 + k_r8 + k_rowadd) * 128 +
                                           (ks * 16 + k_koff) * 2);
                uint32_t kb[4], kl[4];
                ldsm4(kb, Khb + off);
                ldsm4(kl, Klb + off);
                #pragma unroll
                for (int t2 = 0; t2 < 2; t2++) {
                    float* cc = sacc[j * 2 + t2];
                    mma_f16(cc, qh, kb[t2 * 2], kb[t2 * 2 + 1]);
                    mma_f16(cc, qh, kl[t2 * 2], kl[t2 * 2 + 1]);
                    mma_f16(cc, ql, kb[t2 * 2], kb[t2 * 2 + 1]);
                }
            }
        }

        float vm0 = -1e30f, vm1 = -1e30f;
        #pragma unroll
        for (int j = 0; j < 8; j++) {
            vm0 = fmaxf(vm0, fmaxf(sacc[j][0], sacc[j][1]));
            vm1 = fmaxf(vm1, fmaxf(sacc[j][2], sacc[j][3]));
        }
        vm0 = fmaxf(vm0, __shfl_xor_sync(0xffffffffu, vm0, 1));
        vm0 = fmaxf(vm0, __shfl_xor_sync(0xffffffffu, vm0, 2));
        vm1 = fmaxf(vm1, __shfl_xor_sync(0xffffffffu, vm1, 1));
        vm1 = fmaxf(vm1, __shfl_xor_sync(0xffffffffu, vm1, 2));
        vm0 *= 0.125f; vm1 *= 0.125f;

        const float mn0 = fmaxf(m0, vm0), mn1 = fmaxf(m1, vm1);
        const float c0 = __expf(m0 - mn0), c1 = __expf(m1 - mn1);
        m0 = mn0; m1 = mn1;
        l0 *= c0;  l1 *= c1;
        #pragma unroll
        for (int j = 0; j < 8; j++) {
            oacc[j][0] *= c0; oacc[j][1] *= c0;
            oacc[j][2] *= c1; oacc[j][3] *= c1;
        }
        #pragma unroll
        for (int j = 0; j < 8; j++) {
            sacc[j][0] = __expf(fmaf(sacc[j][0], 0.125f, -mn0));
            sacc[j][1] = __expf(fmaf(sacc[j][1], 0.125f, -mn0));
            sacc[j][2] = __expf(fmaf(sacc[j][2], 0.125f, -mn1));
            sacc[j][3] = __expf(fmaf(sacc[j][3], 0.125f, -mn1));
            l0 += sacc[j][0] + sacc[j][1];
            l1 += sacc[j][2] + sacc[j][3];
        }

        #pragma unroll
        for (int kk = 0; kk < 4; kk++) {
            const float* p0 = sacc[kk * 2];
            const float* p1 = sacc[kk * 2 + 1];
            uint32_t pa[4];
            pa[0] = pack_h2(p0[0], p0[1]);
            pa[1] = pack_h2(p0[2], p0[3]);
            pa[2] = pack_h2(p1[0], p1[1]);
            pa[3] = pack_h2(p1[2], p1[3]);
            #pragma unroll
            for (int j = 0; j < 4; j++) {
                const uint32_t off = sw128((kk * 16 + (lane & 15)) * 128 +
                                           (j * 16 + (lane >> 4) * 8) * 2);
                uint32_t vb[4], vl[4];
                ldsm4t(vb, Vhb + off);
                ldsm4t(vl, Vlb + off);
                #pragma unroll
                for (int t2 = 0; t2 < 2; t2++) {
                    float* cc = oacc[j * 2 + t2];
                    mma_f16(cc, pa, vb[t2 * 2], vb[t2 * 2 + 1]);
                    mma_f16(cc, pa, vl[t2 * 2], vl[t2 * 2 + 1]);
                }
            }
        }

        if (c + 1 < NCH) {
            __syncthreads();
            if (c + 2 < NCH) {
                PRE(c + 2, s);
                CP_COMMIT();
                CP_WAIT1();
            } else {
                CP_WAIT0();
            }
            __syncthreads();
        }
    }

    l0 += __shfl_xor_sync(0xffffffffu, l0, 1);
    l0 += __shfl_xor_sync(0xffffffffu, l0, 2);
    l1 += __shfl_xor_sync(0xffffffffu, l1, 1);
    l1 += __shfl_xor_sync(0xffffffffu, l1, 2);
    const float i0 = 1.f / l0, i1 = 1.f / l1;

    const int r0g = bb * SEQ + q0 + wm + (lane >> 2);
    const int cb  = h * 64 + (lane & 3) * 2;
    #pragma unroll
    for (int j = 0; j < 8; j++) {
        *(__half2*)(g_attn + (size_t)r0g * HID + cb + j * 8) =
            __floats2half2_rn(oacc[j][0] * i0, oacc[j][1] * i0);
        *(__half2*)(g_attn + (size_t)(r0g + 8) * HID + cb + j * 8) =
            __floats2half2_rn(oacc[j][2] * i1, oacc[j][3] * i1);
    }
}

// ---------------------------------------------------------------------------
// LayerNorm: fp32 in -> fp16 single out
// ---------------------------------------------------------------------------
__global__ __launch_bounds__(256) void ln_kernel(
    const float* __restrict__ X, const float* __restrict__ g,
    const float* __restrict__ b, __half* __restrict__ Y)
{
    __shared__ float red[16];
    const long row = blockIdx.x;
    const int  t   = threadIdx.x;

    float4 v = ((const float4*)(X + row * HID))[t];
    float s  = v.x + v.y + v.z + v.w;
    float sq = v.x*v.x + v.y*v.y + v.z*v.z + v.w*v.w;

    #pragma unroll
    for (int o = 16; o > 0; o >>= 1) {
        s  += __shfl_xor_sync(0xffffffffu, s,  o);
        sq += __shfl_xor_sync(0xffffffffu, sq, o);
    }
    const int warp = t >> 5, lane = t & 31;
    if (lane == 0) { red[warp] = s; red[warp + 8] = sq; }
    __syncthreads();
    if (t < 32) {
        float ss = (lane < 8) ? red[lane]     : 0.f;
        float qq = (lane < 8) ? red[lane + 8] : 0.f;
        #pragma unroll
        for (int o = 4; o > 0; o >>= 1) {
            ss += __shfl_xor_sync(0xffffffffu, ss, o);
            qq += __shfl_xor_sync(0xffffffffu, qq, o);
        }
        if (lane == 0) { red[0] = ss; red[1] = qq; }
    }
    __syncthreads();

    const float mu   = red[0] * (1.f / HID);
    const float var  = red[1] * (1.f / HID) - mu * mu;
    const float rstd = rsqrtf(var + LN_EPS);

    const float4 gv = ((const float4*)g)[t];
    const float4 bv = ((const float4*)b)[t];
    __half2 a = __floats2half2_rn((v.x - mu) * rstd * gv.x + bv.x,
                                  (v.y - mu) * rstd * gv.y + bv.y);
    __half2 c = __floats2half2_rn((v.z - mu) * rstd * gv.z + bv.z,
                                  (v.w - mu) * rstd * gv.w + bv.w);
    uint2 u; u.x = *(uint32_t*)&a; u.y = *(uint32_t*)&c;
    *(uint2*)(Y + row * HID + t * 4) = u;
}

// ---------------------------------------------------------------------------
// Launch
// ---------------------------------------------------------------------------
extern "C" void kernel_launch(void* const* d_in, const int* in_sizes, int n_in,
                              void* d_out, int out_size)
{
    const float* x     = (const float*)d_in[0];
    const float* ln1_g = (const float*)d_in[1];
    const float* ln1_b = (const float*)d_in[2];
    const float* qkv_w = (const float*)d_in[3];
    const float* qkv_b = (const float*)d_in[4];
    const float* out_w = (const float*)d_in[5];
    const float* out_b = (const float*)d_in[6];
    const float* ln2_g = (const float*)d_in[7];
    const float* ln2_b = (const float*)d_in[8];
    const float* w1    = (const float*)d_in[9];
    const float* b1    = (const float*)d_in[10];
    const float* w2    = (const float*)d_in[11];
    const float* b2    = (const float*)d_in[12];
    float* out = (float*)d_out;

    float* p_x1;
    __half *p_qkv_hi, *p_qkv_lo, *p_h, *p_attn, *p_mid;
    __half *p_wqkv, *p_wout, *p_w1, *p_w2;
    cudaGetSymbolAddress((void**)&p_x1,     g_x1);
    cudaGetSymbolAddress((void**)&p_qkv_hi, g_qkv_hi);
    cudaGetSymbolAddress((void**)&p_qkv_lo, g_qkv_lo);
    cudaGetSymbolAddress((void**)&p_h,      g_h);
    cudaGetSymbolAddress((void**)&p_attn,   g_attn);
    cudaGetSymbolAddress((void**)&p_mid,    g_mid);
    cudaGetSymbolAddress((void**)&p_wqkv,   g_wqkv);
    cudaGetSymbolAddress((void**)&p_wout,   g_wout);
    cudaGetSymbolAddress((void**)&p_w1,     g_w1);
    cudaGetSymbolAddress((void**)&p_w2,     g_w2);

    cudaFuncSetAttribute((const void*)hgemm2<1>,
                         cudaFuncAttributeMaxDynamicSharedMemorySize, HG2_SMEM);
    cudaFuncSetAttribute((const void*)hgemm2<2>,
                         cudaFuncAttributeMaxDynamicSharedMemorySize, HG2_SMEM);
    cudaFuncSetAttribute((const void*)hgemm2<3>,
                         cudaFuncAttributeMaxDynamicSharedMemorySize, HG2_SMEM);
    cudaFuncSetAttribute((const void*)attn_mma,
                         cudaFuncAttributeMaxDynamicSharedMemorySize, ATT_SMEM);

    // 0) weight conversions (single fp16)
    convw<<<(HID * 3 * HID / 4 + 255) / 256, 256>>>(qkv_w, p_wqkv, HID * 3 * HID);
    convw<<<(HID * HID / 4 + 255) / 256, 256>>>(out_w, p_wout, HID * HID);
    convw<<<(HID * INTER / 4 + 255) / 256, 256>>>(w1, p_w1, HID * INTER);
    convw<<<(INTER * HID / 4 + 255) / 256, 256>>>(w2, p_w2, INTER * HID);

    // 1) LN1: x -> h (fp16)
    ln_kernel<<<NTOK, 256>>>(x, ln1_g, ln1_b, p_h);

    // 2) QKV: h @ wqkv + qkv_b -> qkv hi/lo
    hgemm2<3><<<dim3((3 * HID) / BN, NTOK / BM), 256, HG2_SMEM>>>(
        p_h, p_wqkv, qkv_b, nullptr,
        nullptr, p_qkv_hi, p_qkv_lo, NTOK, 3 * HID, HID);

    // 3) attention: qkv hi/lo -> attn (fp16)
    attn_mma<<<dim3(SEQ / QT, NHEAD, BATCH), 256, ATT_SMEM>>>();

    // 4) x1 = x + attn @ wout + out_b
    hgemm2<1><<<dim3(HID / BN, NTOK / BM), 256, HG2_SMEM>>>(
        p_attn, p_wout, out_b, x,
        p_x1, nullptr, nullptr, NTOK, HID, HID);

    // 5) LN2: x1 -> h (fp16)
    ln_kernel<<<NTOK, 256>>>(p_x1, ln2_g, ln2_b, p_h);

    // 6) mid = gelu(h @ w1 + b1) -> fp16
    hgemm2<2><<<dim3(INTER / BN, NTOK / BM), 256, HG2_SMEM>>>(
        p_h, p_w1, b1, nullptr,
        nullptr, p_mid, nullptr, NTOK, INTER, HID);

    // 7) out = x1 + mid @ w2 + b2
    hgemm2<1><<<dim3(HID / BN, NTOK / BM), 256, HG2_SMEM>>>(
        p_mid, p_w2, b2, p_x1,
        out, nullptr, nullptr, NTOK, HID, INTER);
}

// round 15
// speedup vs baseline: 13.5923x; 1.2172x over previous
// Resubmission of the R11 source (two prior runs died to broker-level
// "container failed twice" with no compile/runtime diagnostics; source
// audited clean — see round theory).
#include <cuda_runtime.h>
#include <cuda_fp16.h>
#include <math.h>
#include <stdint.h>

// ---------------------------------------------------------------------------
// Problem constants
// ---------------------------------------------------------------------------
#define HID   1024
#define NHEAD 16
#define HD    64
#define INTER 4096
#define BATCH 4
#define SEQ   2048
#define NTOK  (BATCH * SEQ)          // 8192
#define LN_EPS 1e-5f

// ---------------------------------------------------------------------------
// Scratch (static device globals; no runtime allocation)
// Everything on the mma path is single fp16.
// ---------------------------------------------------------------------------
__device__ float  g_x1 [NTOK * HID];             // residual-1 (fp32)
__device__ __half g_qkv[NTOK * 3 * HID];         // QKV (single fp16)
__device__ __half g_h   [NTOK * HID];            // LN out
__device__ __half g_attn[NTOK * HID];            // attention out
__device__ __half g_mid [NTOK * INTER];          // GELU(MLP1)
__device__ __half g_wqkv[HID * 3 * HID];         // fp16 weights
__device__ __half g_wout[HID * HID];
__device__ __half g_w1  [HID * INTER];
__device__ __half g_w2  [INTER * HID];

// ---------------------------------------------------------------------------
// PTX helpers (sm_80-baseline features only)
// ---------------------------------------------------------------------------
__device__ __forceinline__ uint32_t smem_u32(const void* p) {
    uint32_t a;
    asm("{ .reg .u64 t; cvta.to.shared.u64 t, %1; cvt.u32.u64 %0, t; }"
        : "=r"(a) : "l"(p));
    return a;
}
__device__ __forceinline__ void ldsm4(uint32_t* r, uint32_t addr) {
    asm volatile("ldmatrix.sync.aligned.m8n8.x4.shared.b16 {%0,%1,%2,%3}, [%4];"
                 : "=r"(r[0]), "=r"(r[1]), "=r"(r[2]), "=r"(r[3]) : "r"(addr));
}
__device__ __forceinline__ void ldsm4t(uint32_t* r, uint32_t addr) {
    asm volatile("ldmatrix.sync.aligned.m8n8.x4.trans.shared.b16 {%0,%1,%2,%3}, [%4];"
                 : "=r"(r[0]), "=r"(r[1]), "=r"(r[2]), "=r"(r[3]) : "r"(addr));
}
__device__ __forceinline__ void mma_f16(float* c, const uint32_t* a,
                                        uint32_t b0, uint32_t b1) {
    asm volatile(
        "mma.sync.aligned.m16n8k16.row.col.f32.f16.f16.f32 "
        "{%0,%1,%2,%3}, {%4,%5,%6,%7}, {%8,%9}, {%0,%1,%2,%3};"
        : "+f"(c[0]), "+f"(c[1]), "+f"(c[2]), "+f"(c[3])
        : "r"(a[0]), "r"(a[1]), "r"(a[2]), "r"(a[3]), "r"(b0), "r"(b1));
}
__device__ __forceinline__ void cpasync16(uint32_t s, const void* g) {
    asm volatile("cp.async.cg.shared.global [%0], [%1], 16;" :: "r"(s), "l"(g));
}
#define CP_COMMIT() asm volatile("cp.async.commit_group;" ::: "memory")
#define CP_WAIT1()  asm volatile("cp.async.wait_group 1;"  ::: "memory")
#define CP_WAIT0()  asm volatile("cp.async.wait_group 0;"  ::: "memory")

__device__ __forceinline__ uint32_t swA(uint32_t off) { return off ^ ((off >> 2) & 0x30); }
__device__ __forceinline__ uint32_t swB(uint32_t off) { return off ^ ((off >> 4) & 0x70); }
__device__ __forceinline__ uint32_t sw128(uint32_t off) { return off ^ ((off >> 3) & 0x70); }

__device__ __forceinline__ uint32_t pack_h2(float x, float y) {
    __half2 h = __floats2half2_rn(x, y);
    return *(uint32_t*)&h;
}

// ---------------------------------------------------------------------------
// Weight fp32 -> fp16
// ---------------------------------------------------------------------------
__global__ __launch_bounds__(256) void convw(
    const float* __restrict__ w, __half* __restrict__ hi, int n)
{
    const int i = (blockIdx.x * 256 + threadIdx.x) * 4;
    if (i >= n) return;
    const float4 v = *(const float4*)(w + i);
    __half2 h01 = __floats2half2_rn(v.x, v.y);
    __half2 h23 = __floats2half2_rn(v.z, v.w);
    uint2 hv;
    hv.x = *(uint32_t*)&h01; hv.y = *(uint32_t*)&h23;
    *(uint2*)(hi + i) = hv;
}

// ---------------------------------------------------------------------------
// fp16 HMMA GEMM, 1-term: C = A @ B + bias (+epilogue).
// Tile 128x128, BK=32, cp.async 3-stage (16KB/stage = 48KB).
// EPI: 0 = +bias -> fp16; 1 = +bias+res -> fp32; 2 = +bias+GELU -> fp16
// ---------------------------------------------------------------------------
#define BM 128
#define BN 128
#define BK 32
#define ST_BYTES 16384
#define HG2_SMEM (3 * ST_BYTES)

template <int EPI>
__global__ __launch_bounds__(256, 2) void hgemm2(
    const __half* __restrict__ A, const __half* __restrict__ B,
    const float* __restrict__ bias, const float* __restrict__ res,
    float* __restrict__ Cf, __half* __restrict__ Ch,
    int M, int N, int K)
{
    extern __shared__ char smem[];
    const uint32_t sb = smem_u32(smem);
    const int tid  = threadIdx.x;
    const int lane = tid & 31;
    const int wid  = tid >> 5;
    const int m0   = blockIdx.y * BM;
    const int n0   = blockIdx.x * BN;

    const int ar  = tid >> 1;
    const int ae  = (tid & 1) * 16;
    const int bkr = tid >> 3;
    const int bne = (tid & 7) * 16;
    const uint32_t sA0 = swA(ar * 64 + ae * 2);
    const uint32_t sA1 = swA(ar * 64 + ae * 2 + 16);
    const uint32_t sB0 = swB(bkr * 256 + bne * 2);
    const uint32_t sB1 = swB(bkr * 256 + bne * 2 + 16);
    const size_t aoff = (size_t)(m0 + ar) * K + ae;

    auto PRE = [&](int c, int s) {
        const uint32_t st = sb + s * ST_BYTES;
        const __half* ap = A + aoff + c * BK;
        const size_t boff = (size_t)(c * BK + bkr) * N + n0 + bne;
        cpasync16(st + sA0, ap);
        cpasync16(st + sA1, ap + 8);
        cpasync16(st + 8192 + sB0, B + boff);
        cpasync16(st + 8192 + sB1, B + boff + 8);
    };

    const int wm  = (wid & 3) * 32;
    const int wn  = (wid >> 2) * 64;
    const int a_r = lane & 15;
    const int a_k = (lane >> 4) * 8;
    const int b_k = lane & 15;
    const int b_n = (lane >> 4) * 8;

    float acc[2][8][4];
    #pragma unroll
    for (int i = 0; i < 2; i++)
        #pragma unroll
        for (int j = 0; j < 8; j++)
            #pragma unroll
            for (int q = 0; q < 4; q++) acc[i][j][q] = 0.f;

    auto COMPUTE = [&](int s) {
        const uint32_t AS = sb + s * ST_BYTES;
        const uint32_t BS = AS + 8192;
        #pragma unroll
        for (int ks = 0; ks < 2; ks++) {
            uint32_t a_[2][4];
            #pragma unroll
            for (int mt = 0; mt < 2; mt++) {
                const uint32_t off = swA((wm + mt * 16 + a_r) * 64 + (ks * 16 + a_k) * 2);
                ldsm4(a_[mt], AS + off);
            }
            #pragma unroll
            for (int ng = 0; ng < 4; ng++) {
                uint32_t bh[4];
                const uint32_t off = swB((ks * 16 + b_k) * 256 + (wn + ng * 16 + b_n) * 2);
                ldsm4t(bh, BS + off);
                #pragma unroll
                for (int mt = 0; mt < 2; mt++) {
                    #pragma unroll
                    for (int hf = 0; hf < 2; hf++)
                        mma_f16(acc[mt][ng * 2 + hf], a_[mt],
                                bh[hf * 2], bh[hf * 2 + 1]);
                }
            }
        }
    };

    PRE(0, 0); CP_COMMIT();
    PRE(1, 1); CP_COMMIT();
    const int NC = K / BK;
    #pragma unroll 1
    for (int c = 0; c < NC; c++) {
        const int s = c - (c / 3) * 3;
        CP_WAIT1();
        __syncthreads();
        COMPUTE(s);
        if (c + 2 < NC) {
            const int s2 = (c + 2) - ((c + 2) / 3) * 3;
            PRE(c + 2, s2);
        }
        CP_COMMIT();
    }

    #pragma unroll
    for (int mt = 0; mt < 2; mt++) {
        #pragma unroll
        for (int nt = 0; nt < 8; nt++) {
            const int r0 = m0 + wm + mt * 16 + (lane >> 2);
            const int cc = n0 + wn + nt * 8 + (lane & 3) * 2;
            const float bx = bias[cc], by = bias[cc + 1];
            #pragma unroll
            for (int half = 0; half < 2; half++) {
                const int r = r0 + half * 8;
                float vx = acc[mt][nt][half * 2 + 0] + bx;
                float vy = acc[mt][nt][half * 2 + 1] + by;
                if (EPI == 2) {
                    float t = tanhf(0.7978845608028654f * (vx + 0.044715f * vx * vx * vx));
                    vx = 0.5f * vx * (1.0f + t);
                    t = tanhf(0.7978845608028654f * (vy + 0.044715f * vy * vy * vy));
                    vy = 0.5f * vy * (1.0f + t);
                }
                if (EPI == 0 || EPI == 2) {
                    *(__half2*)(Ch + (size_t)r * N + cc) = __floats2half2_rn(vx, vy);
                } else {
                    const float2 rv = *(const float2*)(res + (size_t)r * N + cc);
                    float2 w; w.x = vx + rv.x; w.y = vy + rv.y;
                    *(float2*)(Cf + (size_t)r * N + cc) = w;
                }
            }
        }
    }
}

// ---------------------------------------------------------------------------
// Tensor-core flash attention, single fp16 everywhere (1-term QK and PV).
// One CTA = 128 q-rows x (head,batch); 8 warps; KV chunks of 64,
// 2-stage cp.async. Smem: Q 16K | 2 x (K 8K + V 8K) = 48KB.
// ---------------------------------------------------------------------------
#define QT 128
#define KT 64
#define ATT_SMEM (16384 + 2 * 16384)

__global__ __launch_bounds__(256, 2) void attn_mma()
{
    extern __shared__ char smem[];
    const uint32_t sb = smem_u32(smem);
    const int tid  = threadIdx.x;
    const int lane = tid & 31;
    const int wid  = tid >> 5;
    const int h    = blockIdx.y;
    const int bb   = blockIdx.z;
    const int q0   = blockIdx.x * QT;

    // Q cp.async: 128 rows x 128B = 16KB
    {
        const int qr  = tid >> 1;
        const int qc0 = (tid & 1) * 32;
        const size_t gq = (size_t)(bb * SEQ + q0 + qr) * 3072 + h * 64 + qc0;
        #pragma unroll
        for (int i = 0; i < 4; i++) {
            const uint32_t so = sw128(qr * 128 + (qc0 + i * 8) * 2);
            cpasync16(sb + so, g_qkv + gq + i * 8);
        }
    }

    // KV stage prefetch: K 8KB + V 8KB
    const int kr = tid >> 2;
    const int kc = (tid & 3) * 16;
    auto PRE = [&](int c, int s) {
        const uint32_t st = sb + 16384 + s * 16384;
        const size_t base = (size_t)(bb * SEQ + c * KT + kr) * 3072 + h * 64 + kc;
        const uint32_t so0 = sw128(kr * 128 + kc * 2);
        const uint32_t so1 = so0 ^ 16;
        cpasync16(st + so0,         g_qkv + base + 1024);
        cpasync16(st + so1,         g_qkv + base + 1024 + 8);
        cpasync16(st + 8192 + so0,  g_qkv + base + 2048);
        cpasync16(st + 8192 + so1,  g_qkv + base + 2048 + 8);
    };

    PRE(0, 0); CP_COMMIT();
    PRE(1, 1); CP_COMMIT();
    CP_WAIT1();
    __syncthreads();

    const int wm = wid * 16;

    float oacc[8][4];
    #pragma unroll
    for (int j = 0; j < 8; j++)
        #pragma unroll
        for (int q = 0; q < 4; q++) oacc[j][q] = 0.f;
    float m0 = -1e30f, m1 = -1e30f, l0 = 0.f, l1 = 0.f;

    const int k_rowadd = ((lane >> 4) & 1) * 8;
    const int k_koff   = ((lane >> 3) & 1) * 8;
    const int k_r8     = lane & 7;

    const int NCH = SEQ / KT;
    #pragma unroll 1
    for (int c = 0; c < NCH; c++) {
        const int s = c & 1;
        const uint32_t st  = sb + 16384 + s * 16384;
        const uint32_t Kb = st, Vb = st + 8192;

        // S = Q @ K^T (1-term)
        float sacc[8][4];
        #pragma unroll
        for (int j = 0; j < 8; j++)
            #pragma unroll
            for (int q = 0; q < 4; q++) sacc[j][q] = 0.f;

        #pragma unroll
        for (int ks = 0; ks < 4; ks++) {
            uint32_t qf[4];
            const uint32_t qoff =
                sw128((wm + (lane & 15)) * 128 + (ks * 16 + (lane >> 4) * 8) * 2);
            ldsm4(qf, sb + qoff);
            #pragma unroll
            for (int j = 0; j < 4; j++) {
                const uint32_t off = sw128((j * 16 + k_r8 + k_rowadd) * 128 +
                                           (ks * 16 + k_koff) * 2);
                uint32_t kb[4];
                ldsm4(kb, Kb + off);
                #pragma unroll
                for (int t2 = 0; t2 < 2; t2++)
                    mma_f16(sacc[j * 2 + t2], qf, kb[t2 * 2], kb[t2 * 2 + 1]);
            }
        }

        // online softmax
        float vm0 = -1e30f, vm1 = -1e30f;
        #pragma unroll
        for (int j = 0; j < 8; j++) {
            vm0 = fmaxf(vm0, fmaxf(sacc[j][0], sacc[j][1]));
            vm1 = fmaxf(vm1, fmaxf(sacc[j][2], sacc[j][3]));
        }
        vm0 = fmaxf(vm0, __shfl_xor_sync(0xffffffffu, vm0, 1));
        vm0 = fmaxf(vm0, __shfl_xor_sync(0xffffffffu, vm0, 2));
        vm1 = fmaxf(vm1, __shfl_xor_sync(0xffffffffu, vm1, 1));
        vm1 = fmaxf(vm1, __shfl_xor_sync(0xffffffffu, vm1, 2));
        vm0 *= 0.125f; vm1 *= 0.125f;

        const float mn0 = fmaxf(m0, vm0), mn1 = fmaxf(m1, vm1);
        const float c0 = __expf(m0 - mn0), c1 = __expf(m1 - mn1);
        m0 = mn0; m1 = mn1;
        l0 *= c0;  l1 *= c1;
        #pragma unroll
        for (int j = 0; j < 8; j++) {
            oacc[j][0] *= c0; oacc[j][1] *= c0;
            oacc[j][2] *= c1; oacc[j][3] *= c1;
        }
        #pragma unroll
        for (int j = 0; j < 8; j++) {
            sacc[j][0] = __expf(fmaf(sacc[j][0], 0.125f, -mn0));
            sacc[j][1] = __expf(fmaf(sacc[j][1], 0.125f, -mn0));
            sacc[j][2] = __expf(fmaf(sacc[j][2], 0.125f, -mn1));
            sacc[j][3] = __expf(fmaf(sacc[j][3], 0.125f, -mn1));
            l0 += sacc[j][0] + sacc[j][1];
            l1 += sacc[j][2] + sacc[j][3];
        }

        // O += P @ V (1-term)
        #pragma unroll
        for (int kk = 0; kk < 4; kk++) {
            const float* p0 = sacc[kk * 2];
            const float* p1 = sacc[kk * 2 + 1];
            uint32_t pa[4];
            pa[0] = pack_h2(p0[0], p0[1]);
            pa[1] = pack_h2(p0[2], p0[3]);
            pa[2] = pack_h2(p1[0], p1[1]);
            pa[3] = pack_h2(p1[2], p1[3]);
            #pragma unroll
            for (int j = 0; j < 4; j++) {
                const uint32_t off = sw128((kk * 16 + (lane & 15)) * 128 +
                                           (j * 16 + (lane >> 4) * 8) * 2);
                uint32_t vb[4];
                ldsm4t(vb, Vb + off);
                #pragma unroll
                for (int t2 = 0; t2 < 2; t2++)
                    mma_f16(oacc[j * 2 + t2], pa, vb[t2 * 2], vb[t2 * 2 + 1]);
            }
        }

        if (c + 1 < NCH) {
            __syncthreads();
            if (c + 2 < NCH) {
                PRE(c + 2, s);
                CP_COMMIT();
                CP_WAIT1();
            } else {
                CP_WAIT0();
            }
            __syncthreads();
        }
    }

    l0 += __shfl_xor_sync(0xffffffffu, l0, 1);
    l0 += __shfl_xor_sync(0xffffffffu, l0, 2);
    l1 += __shfl_xor_sync(0xffffffffu, l1, 1);
    l1 += __shfl_xor_sync(0xffffffffu, l1, 2);
    const float i0 = 1.f / l0, i1 = 1.f / l1;

    const int r0g = bb * SEQ + q0 + wm + (lane >> 2);
    const int cb  = h * 64 + (lane & 3) * 2;
    #pragma unroll
    for (int j = 0; j < 8; j++) {
        *(__half2*)(g_attn + (size_t)r0g * HID + cb + j * 8) =
            __floats2half2_rn(oacc[j][0] * i0, oacc[j][1] * i0);
        *(__half2*)(g_attn + (size_t)(r0g + 8) * HID + cb + j * 8) =
            __floats2half2_rn(oacc[j][2] * i1, oacc[j][3] * i1);
    }
}

// ---------------------------------------------------------------------------
// LayerNorm: fp32 in -> fp16 out
// ---------------------------------------------------------------------------
__global__ __launch_bounds__(256) void ln_kernel(
    const float* __restrict__ X, const float* __restrict__ g,
    const float* __restrict__ b, __half* __restrict__ Y)
{
    __shared__ float red[16];
    const long row = blockIdx.x;
    const int  t   = threadIdx.x;

    float4 v = ((const float4*)(X + row * HID))[t];
    float s  = v.x + v.y + v.z + v.w;
    float sq = v.x*v.x + v.y*v.y + v.z*v.z + v.w*v.w;

    #pragma unroll
    for (int o = 16; o > 0; o >>= 1) {
        s  += __shfl_xor_sync(0xffffffffu, s,  o);
        sq += __shfl_xor_sync(0xffffffffu, sq, o);
    }
    const int warp = t >> 5, lane = t & 31;
    if (lane == 0) { red[warp] = s; red[warp + 8] = sq; }
    __syncthreads();
    if (t < 32) {
        float ss = (lane < 8) ? red[lane]     : 0.f;
        float qq = (lane < 8) ? red[lane + 8] : 0.f;
        #pragma unroll
        for (int o = 4; o > 0; o >>= 1) {
            ss += __shfl_xor_sync(0xffffffffu, ss, o);
            qq += __shfl_xor_sync(0xffffffffu, qq, o);
        }
        if (lane == 0) { red[0] = ss; red[1] = qq; }
    }
    __syncthreads();

    const float mu   = red[0] * (1.f / HID);
    const float var  = red[1] * (1.f / HID) - mu * mu;
    const float rstd = rsqrtf(var + LN_EPS);

    const float4 gv = ((const float4*)g)[t];
    const float4 bv = ((const float4*)b)[t];
    __half2 a = __floats2half2_rn((v.x - mu) * rstd * gv.x + bv.x,
                                  (v.y - mu) * rstd * gv.y + bv.y);
    __half2 c = __floats2half2_rn((v.z - mu) * rstd * gv.z + bv.z,
                                  (v.w - mu) * rstd * gv.w + bv.w);
    uint2 u; u.x = *(uint32_t*)&a; u.y = *(uint32_t*)&c;
    *(uint2*)(Y + row * HID + t * 4) = u;
}

// ---------------------------------------------------------------------------
// Launch
// ---------------------------------------------------------------------------
extern "C" void kernel_launch(void* const* d_in, const int* in_sizes, int n_in,
                              void* d_out, int out_size)
{
    const float* x     = (const float*)d_in[0];
    const float* ln1_g = (const float*)d_in[1];
    const float* ln1_b = (const float*)d_in[2];
    const float* qkv_w = (const float*)d_in[3];
    const float* qkv_b = (const float*)d_in[4];
    const float* out_w = (const float*)d_in[5];
    const float* out_b = (const float*)d_in[6];
    const float* ln2_g = (const float*)d_in[7];
    const float* ln2_b = (const float*)d_in[8];
    const float* w1    = (const float*)d_in[9];
    const float* b1    = (const float*)d_in[10];
    const float* w2    = (const float*)d_in[11];
    const float* b2    = (const float*)d_in[12];
    float* out = (float*)d_out;

    float* p_x1;
    __half *p_qkv, *p_h, *p_attn, *p_mid;
    __half *p_wqkv, *p_wout, *p_w1, *p_w2;
    cudaGetSymbolAddress((void**)&p_x1,   g_x1);
    cudaGetSymbolAddress((void**)&p_qkv,  g_qkv);
    cudaGetSymbolAddress((void**)&p_h,    g_h);
    cudaGetSymbolAddress((void**)&p_attn, g_attn);
    cudaGetSymbolAddress((void**)&p_mid,  g_mid);
    cudaGetSymbolAddress((void**)&p_wqkv, g_wqkv);
    cudaGetSymbolAddress((void**)&p_wout, g_wout);
    cudaGetSymbolAddress((void**)&p_w1,   g_w1);
    cudaGetSymbolAddress((void**)&p_w2,   g_w2);

    cudaFuncSetAttribute((const void*)hgemm2<0>,
                         cudaFuncAttributeMaxDynamicSharedMemorySize, HG2_SMEM);
    cudaFuncSetAttribute((const void*)hgemm2<1>,
                         cudaFuncAttributeMaxDynamicSharedMemorySize, HG2_SMEM);
    cudaFuncSetAttribute((const void*)hgemm2<2>,
                         cudaFuncAttributeMaxDynamicSharedMemorySize, HG2_SMEM);
    cudaFuncSetAttribute((const void*)attn_mma,
                         cudaFuncAttributeMaxDynamicSharedMemorySize, ATT_SMEM);

    // 0) weight conversions
    convw<<<(HID * 3 * HID / 4 + 255) / 256, 256>>>(qkv_w, p_wqkv, HID * 3 * HID);
    convw<<<(HID * HID / 4 + 255) / 256, 256>>>(out_w, p_wout, HID * HID);
    convw<<<(HID * INTER / 4 + 255) / 256, 256>>>(w1, p_w1, HID * INTER);
    convw<<<(INTER * HID / 4 + 255) / 256, 256>>>(w2, p_w2, INTER * HID);

    // 1) LN1: x -> h
    ln_kernel<<<NTOK, 256>>>(x, ln1_g, ln1_b, p_h);

    // 2) QKV: h @ wqkv + qkv_b -> qkv (fp16)
    hgemm2<0><<<dim3((3 * HID) / BN, NTOK / BM), 256, HG2_SMEM>>>(
        p_h, p_wqkv, qkv_b, nullptr,
        nullptr, p_qkv, NTOK, 3 * HID, HID);

    // 3) attention: qkv -> attn
    attn_mma<<<dim3(SEQ / QT, NHEAD, BATCH), 256, ATT_SMEM>>>();

    // 4) x1 = x + attn @ wout + out_b
    hgemm2<1><<<dim3(HID / BN, NTOK / BM), 256, HG2_SMEM>>>(
        p_attn, p_wout, out_b, x,
        p_x1, nullptr, NTOK, HID, HID);

    // 5) LN2: x1 -> h
    ln_kernel<<<NTOK, 256>>>(p_x1, ln2_g, ln2_b, p_h);

    // 6) mid = gelu(h @ w1 + b1)
    hgemm2<2><<<dim3(INTER / BN, NTOK / BM), 256, HG2_SMEM>>>(
        p_h, p_w1, b1, nullptr,
        nullptr, p_mid, NTOK, INTER, HID);

    // 7) out = x1 + mid @ w2 + b2
    hgemm2<1><<<dim3(HID / BN, NTOK / BM), 256, HG2_SMEM>>>(
        p_mid, p_w2, b2, p_x1,
        out, nullptr, NTOK, HID, INTER);
}